// round 5
// baseline (speedup 1.0000x reference)
#include <cuda_runtime.h>
#include <math.h>
#include <stdint.h>

#define QLEN   1024
#define BSZ    4
#define DMODEL 1024
#define NHEAD  16
#define DHEAD  64
#define DINNER 4096
#define MEMLEN 1024
#define KLEN   2048
#define H3     (3 * DMODEL)   // 3072
#define QK     ((long long)QLEN * KLEN)

// ---- static device scratch (no cudaMalloc allowed) ----
__device__ float g_heads[(size_t)KLEN * BSZ * H3];          // 8192 x 3072
__device__ float g_rk[(size_t)KLEN * DMODEL];               // 2048 x 1024
__device__ float g_BD[(size_t)BSZ * NHEAD * QLEN * KLEN];
__device__ float g_av[(size_t)QLEN * BSZ * DMODEL];
__device__ float g_tmp[(size_t)QLEN * BSZ * DMODEL];
__device__ float g_out1[(size_t)QLEN * BSZ * DMODEL];
__device__ float g_ffh[(size_t)QLEN * BSZ * DINNER];        // 4096 x 4096

__device__ __forceinline__ uint32_t f2tf32(float x) {
    uint32_t u;
    asm("cvt.rna.tf32.f32 %0, %1;" : "=r"(u) : "f"(x));
    return u;
}

__device__ __forceinline__ void cpa16(uint32_t s, const float* g) {
    asm volatile("cp.async.cg.shared.global [%0], [%1], 16;" :: "r"(s), "l"(g));
}
#define CP_COMMIT() asm volatile("cp.async.commit_group;")
#define CP_WAIT(N)  asm volatile("cp.async.wait_group %0;" :: "n"(N))

#define MMA_TF32(acc, av, bv)                                               \
    asm volatile(                                                           \
        "mma.sync.aligned.m16n8k8.row.col.f32.tf32.tf32.f32 "               \
        "{%0,%1,%2,%3}, {%4,%5,%6,%7}, {%8,%9}, {%0,%1,%2,%3};"             \
        : "+f"(acc[0]), "+f"(acc[1]), "+f"(acc[2]), "+f"(acc[3])            \
        : "r"(av[0]), "r"(av[1]), "r"(av[2]), "r"(av[3]),                   \
          "r"(bv[0]), "r"(bv[1]))

// ----------------------------------------------------------------------------
// Generic batched strided tf32 tensor-core GEMM (unchanged, proven).
// ----------------------------------------------------------------------------
template <int BT>
__global__ __launch_bounds__(256) void mma_gemm(
    const float* __restrict__ A, const float* __restrict__ A2, int splitRow,
    long long aRow, long long aHi, long long aLo,
    const float* __restrict__ abias, int abLo,
    const float* __restrict__ B, long long bRow, long long bHi, long long bLo,
    const float* __restrict__ cbias, const float* __restrict__ resid, int doRelu,
    float* __restrict__ C, long long cRow, long long cHi, long long cLo,
    int M, int N, int Kd)
{
    __shared__ uint32_t As[2][2560];   // [m][20] (16 k + 4 pad)
    __shared__ uint32_t Bs[2][2560];   // BT: [n][20]; !BT: [k][136]

    const int tid  = threadIdx.x;
    const int warp = tid >> 5, lane = tid & 31;
    const int lr = lane >> 2, lc = lane & 3;
    const int bm = blockIdx.y * 128, bn = blockIdx.x * 128;
    const int bh = blockIdx.z >> 4, bl = blockIdx.z & 15;
    const long long aOff = (long long)bh * aHi + (long long)bl * aLo;
    const long long bOff = (long long)bh * bHi + (long long)bl * bLo;
    const long long cOff = (long long)bh * cHi + (long long)bl * cLo;
    const int wm = (warp & 1) * 64;
    const int wn = (warp >> 1) * 32;

    float acc[4][4][4];
#pragma unroll
    for (int mt = 0; mt < 4; mt++)
#pragma unroll
        for (int nt = 0; nt < 4; nt++)
#pragma unroll
            for (int q = 0; q < 4; q++) acc[mt][nt][q] = 0.f;

    const int ar  = tid >> 2;
    const int akc = (tid & 3) << 2;
    const int bkr = tid >> 5;
    const int bc  = (tid & 31) << 2;

    float4 aS[2], bS[2];

    auto gload = [&](int kt) {
        const int k0 = kt * 16;
#pragma unroll
        for (int h = 0; h < 2; h++) {
            const int row = bm + ar + h * 64;
            const float* ap = (row < splitRow)
                ? (A  + aOff + (long long)row * aRow)
                : (A2 + aOff + (long long)(row - splitRow) * aRow);
            float4 v = *(const float4*)(ap + k0 + akc);
            if (abias) {
                const float4 bb = *(const float4*)(abias + bl * abLo + k0 + akc);
                v.x += bb.x; v.y += bb.y; v.z += bb.z; v.w += bb.w;
            }
            aS[h] = v;
        }
        if (BT) {
#pragma unroll
            for (int h = 0; h < 2; h++) {
                const int nrow = bn + ar + h * 64;
                float4 v = make_float4(0.f, 0.f, 0.f, 0.f);
                if (nrow < N)
                    v = *(const float4*)(B + bOff + (long long)nrow * bRow + k0 + akc);
                bS[h] = v;
            }
        } else {
            const int col = bn + bc;
#pragma unroll
            for (int h = 0; h < 2; h++) {
                float4 v = make_float4(0.f, 0.f, 0.f, 0.f);
                if (col < N)
                    v = *(const float4*)(B + bOff + (long long)(k0 + bkr + h * 8) * bRow + col);
                bS[h] = v;
            }
        }
    };

    auto sstore = [&](int buf) {
#pragma unroll
        for (int h = 0; h < 2; h++) {
            uint32_t* p = &As[buf][(ar + h * 64) * 20 + akc];
            *(uint4*)p = make_uint4(f2tf32(aS[h].x), f2tf32(aS[h].y),
                                    f2tf32(aS[h].z), f2tf32(aS[h].w));
        }
        if (BT) {
#pragma unroll
            for (int h = 0; h < 2; h++) {
                uint32_t* p = &Bs[buf][(ar + h * 64) * 20 + akc];
                *(uint4*)p = make_uint4(f2tf32(bS[h].x), f2tf32(bS[h].y),
                                        f2tf32(bS[h].z), f2tf32(bS[h].w));
            }
        } else {
#pragma unroll
            for (int h = 0; h < 2; h++) {
                uint32_t* p = &Bs[buf][(bkr + h * 8) * 136 + bc];
                *(uint4*)p = make_uint4(f2tf32(bS[h].x), f2tf32(bS[h].y),
                                        f2tf32(bS[h].z), f2tf32(bS[h].w));
            }
        }
    };

    auto compute = [&](int buf) {
#pragma unroll
        for (int kk = 0; kk < 16; kk += 8) {
            uint32_t af[4][4], bf[4][2];
#pragma unroll
            for (int mt = 0; mt < 4; mt++) {
                const int m0 = wm + mt * 16 + lr;
                af[mt][0] = As[buf][m0 * 20 + kk + lc];
                af[mt][1] = As[buf][(m0 + 8) * 20 + kk + lc];
                af[mt][2] = As[buf][m0 * 20 + kk + 4 + lc];
                af[mt][3] = As[buf][(m0 + 8) * 20 + kk + 4 + lc];
            }
#pragma unroll
            for (int nt = 0; nt < 4; nt++) {
                const int n0 = wn + nt * 8 + lr;
                if (BT) {
                    bf[nt][0] = Bs[buf][n0 * 20 + kk + lc];
                    bf[nt][1] = Bs[buf][n0 * 20 + kk + 4 + lc];
                } else {
                    bf[nt][0] = Bs[buf][(kk + lc) * 136 + n0];
                    bf[nt][1] = Bs[buf][(kk + 4 + lc) * 136 + n0];
                }
            }
#pragma unroll
            for (int mt = 0; mt < 4; mt++)
#pragma unroll
                for (int nt = 0; nt < 4; nt++)
                    MMA_TF32(acc[mt][nt], af[mt], bf[nt]);
        }
    };

    const int nk = Kd >> 4;
    gload(0);
    sstore(0);
    __syncthreads();
    for (int kt = 0; kt < nk; kt++) {
        const int buf = kt & 1;
        if (kt + 1 < nk) gload(kt + 1);
        compute(buf);
        if (kt + 1 < nk) sstore(buf ^ 1);
        __syncthreads();
    }

#pragma unroll
    for (int mt = 0; mt < 4; mt++) {
#pragma unroll
        for (int nt = 0; nt < 4; nt++) {
            const int col = bn + wn + nt * 8 + lc * 2;
            if (col >= N) continue;
#pragma unroll
            for (int half = 0; half < 2; half++) {
                const int row = bm + wm + mt * 16 + lr + half * 8;
                float v0 = acc[mt][nt][half * 2 + 0];
                float v1 = acc[mt][nt][half * 2 + 1];
                if (cbias) { v0 += cbias[col]; v1 += cbias[col + 1]; }
                if (resid) {
                    const float* rp = resid + cOff + (long long)row * cRow + col;
                    v0 += rp[0]; v1 += rp[1];
                }
                if (doRelu) { v0 = fmaxf(v0, 0.f); v1 = fmaxf(v1, 0.f); }
                float* cp = C + cOff + (long long)row * cRow + col;
                cp[0] = v0; cp[1] = v1;
            }
        }
    }
}

// ----------------------------------------------------------------------------
// Flash attention v2: cp.async-pipelined K (double-buffered) + V (intra-iter),
// warp-per-row softmax with coalesced BD reads, raw-fp32 tf32 MMA operands.
// One block per (128-query tile, b*16+n). 8 warps (2x4).
// ----------------------------------------------------------------------------
#define QSS 68
#define SSS 132
#define FLASH_SMEM ((128 * QSS + 2 * 128 * QSS + 128 * QSS + 128 * SSS + 3 * 128) * 4)

__global__ __launch_bounds__(256, 1) void flash_k(
    const float* __restrict__ heads, const float* __restrict__ BD,
    const float* __restrict__ rwb, float* __restrict__ av)
{
    extern __shared__ float sm[];
    float* Qs  = sm;                        // 128*68 (tf32 rna)
    float* Ks  = Qs + 128 * QSS;            // 2*128*68 (raw fp32, cp.async)
    float* Vs  = Ks + 2 * 128 * QSS;        // 128*68 (raw fp32, cp.async)
    float* Ss  = Vs + 128 * QSS;            // 128*132 (fp32 S, then trunc-tf32 P)
    float* m_s = Ss + 128 * SSS;            // 128
    float* l_s = m_s + 128;                 // 128
    float* sc_s = l_s + 128;                // 128
    uint32_t* Qsu = (uint32_t*)Qs;
    uint32_t* Ksu = (uint32_t*)Ks;
    uint32_t* Vsu = (uint32_t*)Vs;
    uint32_t* Ssu = (uint32_t*)Ss;
    const uint32_t ks_base = (uint32_t)__cvta_generic_to_shared(Ks);
    const uint32_t vs_base = (uint32_t)__cvta_generic_to_shared(Vs);

    const int tid = threadIdx.x;
    const int warp = tid >> 5, lane = tid & 31;
    const int lr = lane >> 2, lc = lane & 3;
    const int qt = (int)gridDim.x - 1 - (int)blockIdx.x;   // longest-first
    const int i0 = qt * 128;
    const int bn = blockIdx.y;
    const int b = bn >> 4, n = bn & 15;
    const int wm = (warp & 1) * 64;          // row half
    const int wn = (warp >> 1) * 32;         // S col quarter
    const int wn2 = (warp >> 1) * 16;        // O col quarter
    const int njt = qt + 9;                  // causal+mem tile bound

    auto loadK = [&](int jt, int buf) {
        const int j0 = jt * 128;
#pragma unroll
        for (int it = 0; it < 8; it++) {
            const int c = tid + it * 256;
            const int row = c >> 4, seg = (c & 15) << 2;
            const float* g = heads + ((size_t)(j0 + row) * BSZ + b) * H3 + DMODEL + n * DHEAD + seg;
            cpa16(ks_base + (uint32_t)((((buf << 7) + row) * QSS + seg) << 2), g);
        }
        CP_COMMIT();
    };
    auto loadV = [&](int jt) {
        const int j0 = jt * 128;
#pragma unroll
        for (int it = 0; it < 8; it++) {
            const int c = tid + it * 256;
            const int row = c >> 4, seg = (c & 15) << 2;
            const float* g = heads + ((size_t)(j0 + row) * BSZ + b) * H3 + 2 * DMODEL + n * DHEAD + seg;
            cpa16(vs_base + (uint32_t)((row * QSS + seg) << 2), g);
        }
        CP_COMMIT();
    };

    // ---- prologue: issue K(0), load Q (+bias, rna), init stats ----
    loadK(0, 0);
    const float* qbase = heads + (size_t)MEMLEN * BSZ * H3;
#pragma unroll
    for (int it = 0; it < 8; it++) {
        const int idx = tid + it * 256;
        const int row = idx >> 4, c4 = (idx & 15) * 4;
        float4 v = *(const float4*)(qbase + ((size_t)(i0 + row) * BSZ + b) * H3 + n * DHEAD + c4);
        const float4 bb = *(const float4*)(rwb + n * DHEAD + c4);
        uint32_t* d = &Qsu[row * QSS + c4];
        d[0] = f2tf32(v.x + bb.x); d[1] = f2tf32(v.y + bb.y);
        d[2] = f2tf32(v.z + bb.z); d[3] = f2tf32(v.w + bb.w);
    }
    if (tid < 128) { m_s[tid] = -1e30f; l_s[tid] = 0.f; }

    float accO[4][2][4];
#pragma unroll
    for (int mt = 0; mt < 4; mt++)
#pragma unroll
        for (int nt = 0; nt < 2; nt++)
#pragma unroll
            for (int q = 0; q < 4; q++) accO[mt][nt][q] = 0.f;

    CP_WAIT(0);
    __syncthreads();   // Q staged, K(0) resident+visible

    for (int jt = 0; jt < njt; jt++) {
        const int j0 = jt * 128;
        const int cur = jt & 1;
        const bool more = (jt + 1 < njt);

        // ---- issue V(jt), then K(jt+1) prefetch ----
        loadV(jt);
        if (more) loadK(jt + 1, cur ^ 1);

        // ---- S = Qw . K[cur]^T  (128x128, K=64) ----
        float accS[4][4][4];
#pragma unroll
        for (int mt = 0; mt < 4; mt++)
#pragma unroll
            for (int nt = 0; nt < 4; nt++)
#pragma unroll
                for (int q = 0; q < 4; q++) accS[mt][nt][q] = 0.f;

#pragma unroll
        for (int kk = 0; kk < 64; kk += 8) {
            uint32_t af[4][4], bf[4][2];
#pragma unroll
            for (int mt = 0; mt < 4; mt++) {
                const int m0 = wm + mt * 16 + lr;
                af[mt][0] = Qsu[m0 * QSS + kk + lc];
                af[mt][1] = Qsu[(m0 + 8) * QSS + kk + lc];
                af[mt][2] = Qsu[m0 * QSS + kk + 4 + lc];
                af[mt][3] = Qsu[(m0 + 8) * QSS + kk + 4 + lc];
            }
#pragma unroll
            for (int nt = 0; nt < 4; nt++) {
                const int n0 = (cur << 7) + wn + nt * 8 + lr;
                bf[nt][0] = Ksu[n0 * QSS + kk + lc];
                bf[nt][1] = Ksu[n0 * QSS + kk + 4 + lc];
            }
#pragma unroll
            for (int mt = 0; mt < 4; mt++)
#pragma unroll
                for (int nt = 0; nt < 4; nt++)
                    MMA_TF32(accS[mt][nt], af[mt], bf[nt]);
        }

        // ---- stage raw AC scores to smem ----
#pragma unroll
        for (int mt = 0; mt < 4; mt++) {
            const int r0 = wm + mt * 16 + lr;
#pragma unroll
            for (int nt = 0; nt < 4; nt++) {
                const int col = wn + nt * 8 + 2 * lc;
                *(float2*)&Ss[r0 * SSS + col] =
                    make_float2(accS[mt][nt][0], accS[mt][nt][1]);
                *(float2*)&Ss[(r0 + 8) * SSS + col] =
                    make_float2(accS[mt][nt][2], accS[mt][nt][3]);
            }
        }
        __syncthreads();

        // ---- softmax: one warp per row, coalesced BD reads ----
#pragma unroll 1
        for (int rr = 0; rr < 16; rr++) {
            const int row = warp * 16 + rr;
            const int i = i0 + row;
            const float* bdp = BD + ((size_t)bn * QLEN + i) * KLEN + (j0 - i + QLEN - 1);
            const int vmax = i + MEMLEN - j0;   // valid col c <= vmax
            float sv[4];
            float mloc = -1e30f;
#pragma unroll
            for (int k2 = 0; k2 < 4; k2++) {
                const int c = lane + 32 * k2;
                float s = -1e30f;
                if (c <= vmax) s = (Ss[row * SSS + c] + __ldg(bdp + c)) * 0.125f;
                sv[k2] = s;
                mloc = fmaxf(mloc, s);
            }
#pragma unroll
            for (int o = 16; o; o >>= 1)
                mloc = fmaxf(mloc, __shfl_xor_sync(0xffffffffu, mloc, o));
            const float mo = m_s[row];
            const float nm = fmaxf(mo, mloc);
            float lsum = 0.f;
#pragma unroll
            for (int k2 = 0; k2 < 4; k2++) {
                const int c = lane + 32 * k2;
                float p = __expf(sv[k2] - nm);
                const uint32_t pb = __float_as_uint(p) & 0xFFFFE000u;  // trunc to tf32
                const float pt = __uint_as_float(pb);
                lsum += pt;
                Ssu[row * SSS + c] = pb;
            }
#pragma unroll
            for (int o = 16; o; o >>= 1)
                lsum += __shfl_xor_sync(0xffffffffu, lsum, o);
            if (lane == 0) {
                const float alpha = __expf(mo - nm);
                m_s[row] = nm;
                l_s[row] = l_s[row] * alpha + lsum;
                sc_s[row] = alpha;
            }
        }
        __syncthreads();

        // ---- wait V(jt) (older group than K(jt+1)) ----
        if (more) { CP_WAIT(1); } else { CP_WAIT(0); }
        __syncthreads();

        // ---- rescale O, then O += P . V  (128x64, K=128) ----
#pragma unroll
        for (int mt = 0; mt < 4; mt++) {
            const int r = wm + mt * 16 + lr;
            const float s0 = sc_s[r], s1 = sc_s[r + 8];
#pragma unroll
            for (int nt = 0; nt < 2; nt++) {
                accO[mt][nt][0] *= s0; accO[mt][nt][1] *= s0;
                accO[mt][nt][2] *= s1; accO[mt][nt][3] *= s1;
            }
        }
#pragma unroll
        for (int jj = 0; jj < 128; jj += 8) {
            uint32_t af[4][4], bf[2][2];
#pragma unroll
            for (int mt = 0; mt < 4; mt++) {
                const int m0 = wm + mt * 16 + lr;
                af[mt][0] = Ssu[m0 * SSS + jj + lc];
                af[mt][1] = Ssu[(m0 + 8) * SSS + jj + lc];
                af[mt][2] = Ssu[m0 * SSS + jj + 4 + lc];
                af[mt][3] = Ssu[(m0 + 8) * SSS + jj + 4 + lc];
            }
#pragma unroll
            for (int nt = 0; nt < 2; nt++) {
                const int n0 = wn2 + nt * 8 + lr;
                bf[nt][0] = Vsu[(jj + lc) * QSS + n0];
                bf[nt][1] = Vsu[(jj + 4 + lc) * QSS + n0];
            }
#pragma unroll
            for (int mt = 0; mt < 4; mt++)
#pragma unroll
                for (int nt = 0; nt < 2; nt++)
                    MMA_TF32(accO[mt][nt], af[mt], bf[nt]);
        }

        // K(jt+1) resident + all PV reads of Vs/Ss done before next iter writes
        if (more) CP_WAIT(0);
        __syncthreads();
    }

    // ---- finalize: O /= l, write av[(i*B + b)*D + n*64 + d] ----
#pragma unroll
    for (int mt = 0; mt < 4; mt++) {
        const int r = wm + mt * 16 + lr;
        const float inv0 = 1.f / l_s[r];
        const float inv1 = 1.f / l_s[r + 8];
#pragma unroll
        for (int nt = 0; nt < 2; nt++) {
            const int col = wn2 + nt * 8 + 2 * lc;
            float* p0 = av + ((size_t)(i0 + r) * BSZ + b) * DMODEL + n * DHEAD + col;
            *(float2*)p0 = make_float2(accO[mt][nt][0] * inv0, accO[mt][nt][1] * inv0);
            float* p1 = av + ((size_t)(i0 + r + 8) * BSZ + b) * DMODEL + n * DHEAD + col;
            *(float2*)p1 = make_float2(accO[mt][nt][2] * inv1, accO[mt][nt][3] * inv1);
        }
    }
}

// ----------------------------------------------------------------------------
// Row LayerNorm over D=1024 (one block per row, 4 elems/thread).
// ----------------------------------------------------------------------------
__device__ __forceinline__ float warpSum(float v) {
#pragma unroll
    for (int o = 16; o; o >>= 1) v += __shfl_xor_sync(0xffffffffu, v, o);
    return v;
}

__global__ __launch_bounds__(256) void ln_k(
    const float* __restrict__ X, const float* __restrict__ gam,
    const float* __restrict__ bet, float* __restrict__ Y)
{
    __shared__ float red[8];
    const size_t row = blockIdx.x;
    const int tid = threadIdx.x;
    const float4 v = *(const float4*)(X + row * DMODEL + tid * 4);
    float s = v.x + v.y + v.z + v.w;
    float q = v.x * v.x + v.y * v.y + v.z * v.z + v.w * v.w;

    float ws = warpSum(s);
    if ((tid & 31) == 0) red[tid >> 5] = ws;
    __syncthreads();
    if (tid < 32) {
        float t = (tid < 8) ? red[tid] : 0.f;
        t = warpSum(t);
        if (tid == 0) red[0] = t;
    }
    __syncthreads();
    const float mu = red[0] * (1.f / DMODEL);
    __syncthreads();

    float wq = warpSum(q);
    if ((tid & 31) == 0) red[tid >> 5] = wq;
    __syncthreads();
    if (tid < 32) {
        float t = (tid < 8) ? red[tid] : 0.f;
        t = warpSum(t);
        if (tid == 0) red[0] = t;
    }
    __syncthreads();
    const float var = red[0] * (1.f / DMODEL) - mu * mu;
    const float rs = rsqrtf(var + 1e-5f);

    const float4 gv = *(const float4*)(gam + tid * 4);
    const float4 bv = *(const float4*)(bet + tid * 4);
    float4 o;
    o.x = (v.x - mu) * rs * gv.x + bv.x;
    o.y = (v.y - mu) * rs * gv.y + bv.y;
    o.z = (v.z - mu) * rs * gv.z + bv.z;
    o.w = (v.w - mu) * rs * gv.w + bv.w;
    *(float4*)(Y + row * DMODEL + tid * 4) = o;
}

// ----------------------------------------------------------------------------
extern "C" void kernel_launch(void* const* d_in, const int* in_sizes, int n_in,
                              void* d_out, int out_size)
{
    (void)in_sizes; (void)n_in; (void)out_size;
    const float* w       = (const float*)d_in[0];
    const float* r       = (const float*)d_in[1];
    const float* mems    = (const float*)d_in[2];
    const float* qkv_w   = (const float*)d_in[3];
    const float* r_net_w = (const float*)d_in[4];
    const float* o_w     = (const float*)d_in[5];
    const float* rwb     = (const float*)d_in[6];
    const float* rrb     = (const float*)d_in[7];
    const float* ln1g    = (const float*)d_in[8];
    const float* ln1b    = (const float*)d_in[9];
    const float* ffw1    = (const float*)d_in[10];
    const float* ffb1    = (const float*)d_in[11];
    const float* ffw2    = (const float*)d_in[12];
    const float* ffb2    = (const float*)d_in[13];
    const float* ln2g    = (const float*)d_in[14];
    const float* ln2b    = (const float*)d_in[15];
    float* out = (float*)d_out;

    float *heads, *rk, *BD, *av, *tmp, *out1, *ffh;
    cudaGetSymbolAddress((void**)&heads, g_heads);
    cudaGetSymbolAddress((void**)&rk,    g_rk);
    cudaGetSymbolAddress((void**)&BD,    g_BD);
    cudaGetSymbolAddress((void**)&av,    g_av);
    cudaGetSymbolAddress((void**)&tmp,   g_tmp);
    cudaGetSymbolAddress((void**)&out1,  g_out1);
    cudaGetSymbolAddress((void**)&ffh,   g_ffh);

    static int s_attr_done = 0;
    if (!s_attr_done) {
        cudaFuncSetAttribute(flash_k, cudaFuncAttributeMaxDynamicSharedMemorySize,
                             FLASH_SMEM);
        s_attr_done = 1;
    }

    const dim3 blk(256);
    const int BIG = 1 << 30;
    const float* qbase = heads + (size_t)MEMLEN * BSZ * H3;  // query rows

    // 1) heads = concat(mems, w) @ qkv_w          [8192 x 3072 x 1024]
    mma_gemm<0><<<dim3(H3 / 128, (KLEN * BSZ) / 128, 1), blk>>>(
        mems, w, MEMLEN * BSZ, DMODEL, 0, 0, nullptr, 0,
        qkv_w, H3, 0, 0, nullptr, nullptr, 0,
        heads, H3, 0, 0, KLEN * BSZ, H3, DMODEL);

    // 2) rk = r @ r_net_w                          [2048 x 1024 x 1024]
    mma_gemm<0><<<dim3(DMODEL / 128, KLEN / 128, 1), blk>>>(
        r, r, BIG, DMODEL, 0, 0, nullptr, 0,
        r_net_w, DMODEL, 0, 0, nullptr, nullptr, 0,
        rk, DMODEL, 0, 0, KLEN, DMODEL, DMODEL);

    // 3) BD_pre[bn][i][c] = (q_i + rrb_n) . rk_c   batched, K=64
    mma_gemm<1><<<dim3(KLEN / 128, QLEN / 128, BSZ * NHEAD), blk>>>(
        qbase, qbase, BIG, BSZ * H3, H3, DHEAD, rrb, DHEAD,
        rk, DMODEL, 0, DHEAD, nullptr, nullptr, 0,
        BD, KLEN, 16 * QK, QK, QLEN, KLEN, DHEAD);

    // 4) flash: AC + shifted-BD + mask + softmax + PV -> av
    flash_k<<<dim3(QLEN / 128, BSZ * NHEAD), blk, FLASH_SMEM>>>(heads, BD, rwb, av);

    // 5) attn_out = av @ o_w + w (residual)        [4096 x 1024 x 1024]
    mma_gemm<0><<<dim3(DMODEL / 128, (QLEN * BSZ) / 128, 1), blk>>>(
        av, av, BIG, DMODEL, 0, 0, nullptr, 0,
        o_w, DMODEL, 0, 0, nullptr, w, 0,
        tmp, DMODEL, 0, 0, QLEN * BSZ, DMODEL, DMODEL);

    // 6) LN1
    ln_k<<<QLEN * BSZ, blk>>>(tmp, ln1g, ln1b, out1);

    // 7) ffh = relu(out1 @ ff_w1 + b1)             [4096 x 4096 x 1024]
    mma_gemm<0><<<dim3(DINNER / 128, (QLEN * BSZ) / 128, 1), blk>>>(
        out1, out1, BIG, DMODEL, 0, 0, nullptr, 0,
        ffw1, DINNER, 0, 0, ffb1, nullptr, 1,
        ffh, DINNER, 0, 0, QLEN * BSZ, DINNER, DMODEL);

    // 8) tmp = ffh @ ff_w2 + b2 + out1             [4096 x 1024 x 4096]
    mma_gemm<0><<<dim3(DMODEL / 128, (QLEN * BSZ) / 128, 1), blk>>>(
        ffh, ffh, BIG, DINNER, 0, 0, nullptr, 0,
        ffw2, DMODEL, 0, 0, ffb2, out1, 0,
        tmp, DMODEL, 0, 0, QLEN * BSZ, DMODEL, DINNER);

    // 9) LN2 -> output
    ln_k<<<QLEN * BSZ, blk>>>(tmp, ln2g, ln2b, out);
}

// round 6
// speedup vs baseline: 1.1185x; 1.1185x over previous
#include <cuda_runtime.h>
#include <math.h>
#include <stdint.h>

#define QLEN   1024
#define BSZ    4
#define DMODEL 1024
#define NHEAD  16
#define DHEAD  64
#define DINNER 4096
#define MEMLEN 1024
#define KLEN   2048
#define H3     (3 * DMODEL)   // 3072
#define QK     ((long long)QLEN * KLEN)

// ---- static device scratch (no cudaMalloc allowed) ----
__device__ float g_heads[(size_t)KLEN * BSZ * H3];          // 8192 x 3072
__device__ float g_rk[(size_t)KLEN * DMODEL];               // 2048 x 1024
__device__ float g_BD[(size_t)BSZ * NHEAD * QLEN * KLEN];
__device__ float g_av[(size_t)QLEN * BSZ * DMODEL];
__device__ float g_tmp[(size_t)QLEN * BSZ * DMODEL];
__device__ float g_out1[(size_t)QLEN * BSZ * DMODEL];
__device__ float g_ffh[(size_t)QLEN * BSZ * DINNER];        // 4096 x 4096

__device__ __forceinline__ uint32_t f2tf32(float x) {
    uint32_t u;
    asm("cvt.rna.tf32.f32 %0, %1;" : "=r"(u) : "f"(x));
    return u;
}

__device__ __forceinline__ void cpa16(uint32_t s, const float* g) {
    asm volatile("cp.async.cg.shared.global [%0], [%1], 16;" :: "r"(s), "l"(g));
}
#define CP_COMMIT() asm volatile("cp.async.commit_group;")
#define CP_WAIT(N)  asm volatile("cp.async.wait_group %0;" :: "n"(N))

#define MMA_TF32(acc, av, bv)                                               \
    asm volatile(                                                           \
        "mma.sync.aligned.m16n8k8.row.col.f32.tf32.tf32.f32 "               \
        "{%0,%1,%2,%3}, {%4,%5,%6,%7}, {%8,%9}, {%0,%1,%2,%3};"             \
        : "+f"(acc[0]), "+f"(acc[1]), "+f"(acc[2]), "+f"(acc[3])            \
        : "r"(av[0]), "r"(av[1]), "r"(av[2]), "r"(av[3]),                   \
          "r"(bv[0]), "r"(bv[1]))

// ----------------------------------------------------------------------------
// Generic batched strided tf32 tensor-core GEMM (unchanged, proven).
// ----------------------------------------------------------------------------
template <int BT>
__global__ __launch_bounds__(256) void mma_gemm(
    const float* __restrict__ A, const float* __restrict__ A2, int splitRow,
    long long aRow, long long aHi, long long aLo,
    const float* __restrict__ abias, int abLo,
    const float* __restrict__ B, long long bRow, long long bHi, long long bLo,
    const float* __restrict__ cbias, const float* __restrict__ resid, int doRelu,
    float* __restrict__ C, long long cRow, long long cHi, long long cLo,
    int M, int N, int Kd)
{
    __shared__ uint32_t As[2][2560];   // [m][20] (16 k + 4 pad)
    __shared__ uint32_t Bs[2][2560];   // BT: [n][20]; !BT: [k][136]

    const int tid  = threadIdx.x;
    const int warp = tid >> 5, lane = tid & 31;
    const int lr = lane >> 2, lc = lane & 3;
    const int bm = blockIdx.y * 128, bn = blockIdx.x * 128;
    const int bh = blockIdx.z >> 4, bl = blockIdx.z & 15;
    const long long aOff = (long long)bh * aHi + (long long)bl * aLo;
    const long long bOff = (long long)bh * bHi + (long long)bl * bLo;
    const long long cOff = (long long)bh * cHi + (long long)bl * cLo;
    const int wm = (warp & 1) * 64;
    const int wn = (warp >> 1) * 32;

    float acc[4][4][4];
#pragma unroll
    for (int mt = 0; mt < 4; mt++)
#pragma unroll
        for (int nt = 0; nt < 4; nt++)
#pragma unroll
            for (int q = 0; q < 4; q++) acc[mt][nt][q] = 0.f;

    const int ar  = tid >> 2;
    const int akc = (tid & 3) << 2;
    const int bkr = tid >> 5;
    const int bc  = (tid & 31) << 2;

    float4 aS[2], bS[2];

    auto gload = [&](int kt) {
        const int k0 = kt * 16;
#pragma unroll
        for (int h = 0; h < 2; h++) {
            const int row = bm + ar + h * 64;
            const float* ap = (row < splitRow)
                ? (A  + aOff + (long long)row * aRow)
                : (A2 + aOff + (long long)(row - splitRow) * aRow);
            float4 v = *(const float4*)(ap + k0 + akc);
            if (abias) {
                const float4 bb = *(const float4*)(abias + bl * abLo + k0 + akc);
                v.x += bb.x; v.y += bb.y; v.z += bb.z; v.w += bb.w;
            }
            aS[h] = v;
        }
        if (BT) {
#pragma unroll
            for (int h = 0; h < 2; h++) {
                const int nrow = bn + ar + h * 64;
                float4 v = make_float4(0.f, 0.f, 0.f, 0.f);
                if (nrow < N)
                    v = *(const float4*)(B + bOff + (long long)nrow * bRow + k0 + akc);
                bS[h] = v;
            }
        } else {
            const int col = bn + bc;
#pragma unroll
            for (int h = 0; h < 2; h++) {
                float4 v = make_float4(0.f, 0.f, 0.f, 0.f);
                if (col < N)
                    v = *(const float4*)(B + bOff + (long long)(k0 + bkr + h * 8) * bRow + col);
                bS[h] = v;
            }
        }
    };

    auto sstore = [&](int buf) {
#pragma unroll
        for (int h = 0; h < 2; h++) {
            uint32_t* p = &As[buf][(ar + h * 64) * 20 + akc];
            *(uint4*)p = make_uint4(f2tf32(aS[h].x), f2tf32(aS[h].y),
                                    f2tf32(aS[h].z), f2tf32(aS[h].w));
        }
        if (BT) {
#pragma unroll
            for (int h = 0; h < 2; h++) {
                uint32_t* p = &Bs[buf][(ar + h * 64) * 20 + akc];
                *(uint4*)p = make_uint4(f2tf32(bS[h].x), f2tf32(bS[h].y),
                                        f2tf32(bS[h].z), f2tf32(bS[h].w));
            }
        } else {
#pragma unroll
            for (int h = 0; h < 2; h++) {
                uint32_t* p = &Bs[buf][(bkr + h * 8) * 136 + bc];
                *(uint4*)p = make_uint4(f2tf32(bS[h].x), f2tf32(bS[h].y),
                                        f2tf32(bS[h].z), f2tf32(bS[h].w));
            }
        }
    };

    auto compute = [&](int buf) {
#pragma unroll
        for (int kk = 0; kk < 16; kk += 8) {
            uint32_t af[4][4], bf[4][2];
#pragma unroll
            for (int mt = 0; mt < 4; mt++) {
                const int m0 = wm + mt * 16 + lr;
                af[mt][0] = As[buf][m0 * 20 + kk + lc];
                af[mt][1] = As[buf][(m0 + 8) * 20 + kk + lc];
                af[mt][2] = As[buf][m0 * 20 + kk + 4 + lc];
                af[mt][3] = As[buf][(m0 + 8) * 20 + kk + 4 + lc];
            }
#pragma unroll
            for (int nt = 0; nt < 4; nt++) {
                const int n0 = wn + nt * 8 + lr;
                if (BT) {
                    bf[nt][0] = Bs[buf][n0 * 20 + kk + lc];
                    bf[nt][1] = Bs[buf][n0 * 20 + kk + 4 + lc];
                } else {
                    bf[nt][0] = Bs[buf][(kk + lc) * 136 + n0];
                    bf[nt][1] = Bs[buf][(kk + 4 + lc) * 136 + n0];
                }
            }
#pragma unroll
            for (int mt = 0; mt < 4; mt++)
#pragma unroll
                for (int nt = 0; nt < 4; nt++)
                    MMA_TF32(acc[mt][nt], af[mt], bf[nt]);
        }
    };

    const int nk = Kd >> 4;
    gload(0);
    sstore(0);
    __syncthreads();
    for (int kt = 0; kt < nk; kt++) {
        const int buf = kt & 1;
        if (kt + 1 < nk) gload(kt + 1);
        compute(buf);
        if (kt + 1 < nk) sstore(buf ^ 1);
        __syncthreads();
    }

#pragma unroll
    for (int mt = 0; mt < 4; mt++) {
#pragma unroll
        for (int nt = 0; nt < 4; nt++) {
            const int col = bn + wn + nt * 8 + lc * 2;
            if (col >= N) continue;
#pragma unroll
            for (int half = 0; half < 2; half++) {
                const int row = bm + wm + mt * 16 + lr + half * 8;
                float v0 = acc[mt][nt][half * 2 + 0];
                float v1 = acc[mt][nt][half * 2 + 1];
                if (cbias) { v0 += cbias[col]; v1 += cbias[col + 1]; }
                if (resid) {
                    const float* rp = resid + cOff + (long long)row * cRow + col;
                    v0 += rp[0]; v1 += rp[1];
                }
                if (doRelu) { v0 = fmaxf(v0, 0.f); v1 = fmaxf(v1, 0.f); }
                float* cp = C + cOff + (long long)row * cRow + col;
                cp[0] = v0; cp[1] = v1;
            }
        }
    }
}

// ----------------------------------------------------------------------------
// Flash attention v3: 512 threads / 16 warps (latency hiding), cp.async
// pipelined K (double-buffered) + V (intra-iter), warp-per-row softmax.
// One block per (128-query tile, b*16+n). Warp tile: 32x32 of S, 32x16 of O.
// ----------------------------------------------------------------------------
#define QSS 68
#define SSS 132
#define FLASH_SMEM ((128 * QSS + 2 * 128 * QSS + 128 * QSS + 128 * SSS + 3 * 128) * 4)

__global__ __launch_bounds__(512, 1) void flash_k(
    const float* __restrict__ heads, const float* __restrict__ BD,
    const float* __restrict__ rwb, float* __restrict__ av)
{
    extern __shared__ float sm[];
    float* Qs  = sm;                        // 128*68 (tf32 rna)
    float* Ks  = Qs + 128 * QSS;            // 2*128*68 (raw fp32, cp.async)
    float* Vs  = Ks + 2 * 128 * QSS;        // 128*68 (raw fp32, cp.async)
    float* Ss  = Vs + 128 * QSS;            // 128*132 (fp32 S, then trunc-tf32 P)
    float* m_s = Ss + 128 * SSS;            // 128
    float* l_s = m_s + 128;                 // 128
    float* sc_s = l_s + 128;                // 128
    uint32_t* Qsu = (uint32_t*)Qs;
    uint32_t* Ksu = (uint32_t*)Ks;
    uint32_t* Vsu = (uint32_t*)Vs;
    uint32_t* Ssu = (uint32_t*)Ss;
    const uint32_t ks_base = (uint32_t)__cvta_generic_to_shared(Ks);
    const uint32_t vs_base = (uint32_t)__cvta_generic_to_shared(Vs);

    const int tid = threadIdx.x;
    const int warp = tid >> 5, lane = tid & 31;
    const int lr = lane >> 2, lc = lane & 3;
    const int qt = (int)gridDim.x - 1 - (int)blockIdx.x;   // longest-first
    const int i0 = qt * 128;
    const int bn = blockIdx.y;
    const int b = bn >> 4, n = bn & 15;
    const int wm  = (warp & 3) * 32;         // 32-row group
    const int wn  = (warp >> 2) * 32;        // S col group (32 wide)
    const int wn2 = (warp >> 2) * 16;        // O col group (16 wide)
    const int njt = qt + 9;                  // causal+mem tile bound

    auto loadK = [&](int jt, int buf) {
        const int j0 = jt * 128;
#pragma unroll
        for (int it = 0; it < 4; it++) {
            const int c = tid + it * 512;
            const int row = c >> 4, seg = (c & 15) << 2;
            const float* g = heads + ((size_t)(j0 + row) * BSZ + b) * H3 + DMODEL + n * DHEAD + seg;
            cpa16(ks_base + (uint32_t)((((buf << 7) + row) * QSS + seg) << 2), g);
        }
        CP_COMMIT();
    };
    auto loadV = [&](int jt) {
        const int j0 = jt * 128;
#pragma unroll
        for (int it = 0; it < 4; it++) {
            const int c = tid + it * 512;
            const int row = c >> 4, seg = (c & 15) << 2;
            const float* g = heads + ((size_t)(j0 + row) * BSZ + b) * H3 + 2 * DMODEL + n * DHEAD + seg;
            cpa16(vs_base + (uint32_t)((row * QSS + seg) << 2), g);
        }
        CP_COMMIT();
    };

    // ---- prologue: issue K(0), load Q (+bias, rna), init stats ----
    loadK(0, 0);
    const float* qbase = heads + (size_t)MEMLEN * BSZ * H3;
#pragma unroll
    for (int it = 0; it < 4; it++) {
        const int idx = tid + it * 512;
        const int row = idx >> 4, c4 = (idx & 15) * 4;
        float4 v = *(const float4*)(qbase + ((size_t)(i0 + row) * BSZ + b) * H3 + n * DHEAD + c4);
        const float4 bb = *(const float4*)(rwb + n * DHEAD + c4);
        uint32_t* d = &Qsu[row * QSS + c4];
        d[0] = f2tf32(v.x + bb.x); d[1] = f2tf32(v.y + bb.y);
        d[2] = f2tf32(v.z + bb.z); d[3] = f2tf32(v.w + bb.w);
    }
    if (tid < 128) { m_s[tid] = -1e30f; l_s[tid] = 0.f; }

    float accO[2][2][4];
#pragma unroll
    for (int mt = 0; mt < 2; mt++)
#pragma unroll
        for (int nt = 0; nt < 2; nt++)
#pragma unroll
            for (int q = 0; q < 4; q++) accO[mt][nt][q] = 0.f;

    CP_WAIT(0);
    __syncthreads();   // Q staged, K(0) resident+visible

    for (int jt = 0; jt < njt; jt++) {
        const int j0 = jt * 128;
        const int cur = jt & 1;
        const bool more = (jt + 1 < njt);

        // ---- issue V(jt), then K(jt+1) prefetch ----
        loadV(jt);
        if (more) loadK(jt + 1, cur ^ 1);

        // ---- S = Qw . K[cur]^T  (128x128, K=64); warp tile 32x32 ----
        float accS[2][4][4];
#pragma unroll
        for (int mt = 0; mt < 2; mt++)
#pragma unroll
            for (int nt = 0; nt < 4; nt++)
#pragma unroll
                for (int q = 0; q < 4; q++) accS[mt][nt][q] = 0.f;

#pragma unroll
        for (int kk = 0; kk < 64; kk += 8) {
            uint32_t af[2][4], bf[4][2];
#pragma unroll
            for (int mt = 0; mt < 2; mt++) {
                const int m0 = wm + mt * 16 + lr;
                af[mt][0] = Qsu[m0 * QSS + kk + lc];
                af[mt][1] = Qsu[(m0 + 8) * QSS + kk + lc];
                af[mt][2] = Qsu[m0 * QSS + kk + 4 + lc];
                af[mt][3] = Qsu[(m0 + 8) * QSS + kk + 4 + lc];
            }
#pragma unroll
            for (int nt = 0; nt < 4; nt++) {
                const int n0 = (cur << 7) + wn + nt * 8 + lr;
                bf[nt][0] = Ksu[n0 * QSS + kk + lc];
                bf[nt][1] = Ksu[n0 * QSS + kk + 4 + lc];
            }
#pragma unroll
            for (int mt = 0; mt < 2; mt++)
#pragma unroll
                for (int nt = 0; nt < 4; nt++)
                    MMA_TF32(accS[mt][nt], af[mt], bf[nt]);
        }

        // ---- stage raw AC scores to smem ----
#pragma unroll
        for (int mt = 0; mt < 2; mt++) {
            const int r0 = wm + mt * 16 + lr;
#pragma unroll
            for (int nt = 0; nt < 4; nt++) {
                const int col = wn + nt * 8 + 2 * lc;
                *(float2*)&Ss[r0 * SSS + col] =
                    make_float2(accS[mt][nt][0], accS[mt][nt][1]);
                *(float2*)&Ss[(r0 + 8) * SSS + col] =
                    make_float2(accS[mt][nt][2], accS[mt][nt][3]);
            }
        }
        __syncthreads();

        // ---- softmax: one warp per row (8 rows/warp), coalesced BD reads ----
#pragma unroll 1
        for (int rr = 0; rr < 8; rr++) {
            const int row = warp * 8 + rr;
            const int i = i0 + row;
            const float* bdp = BD + ((size_t)bn * QLEN + i) * KLEN + (j0 - i + QLEN - 1);
            const int vmax = i + MEMLEN - j0;   // valid col c <= vmax
            float sv[4];
            float mloc = -1e30f;
#pragma unroll
            for (int k2 = 0; k2 < 4; k2++) {
                const int c = lane + 32 * k2;
                float s = -1e30f;
                if (c <= vmax) s = (Ss[row * SSS + c] + __ldg(bdp + c)) * 0.125f;
                sv[k2] = s;
                mloc = fmaxf(mloc, s);
            }
#pragma unroll
            for (int o = 16; o; o >>= 1)
                mloc = fmaxf(mloc, __shfl_xor_sync(0xffffffffu, mloc, o));
            const float mo = m_s[row];
            const float nm = fmaxf(mo, mloc);
            float lsum = 0.f;
#pragma unroll
            for (int k2 = 0; k2 < 4; k2++) {
                const int c = lane + 32 * k2;
                float p = __expf(sv[k2] - nm);
                const uint32_t pb = __float_as_uint(p) & 0xFFFFE000u;  // trunc to tf32
                const float pt = __uint_as_float(pb);
                lsum += pt;
                Ssu[row * SSS + c] = pb;
            }
#pragma unroll
            for (int o = 16; o; o >>= 1)
                lsum += __shfl_xor_sync(0xffffffffu, lsum, o);
            if (lane == 0) {
                const float alpha = __expf(mo - nm);
                m_s[row] = nm;
                l_s[row] = l_s[row] * alpha + lsum;
                sc_s[row] = alpha;
            }
        }
        __syncthreads();

        // ---- wait V(jt) (older group than K(jt+1)) ----
        if (more) { CP_WAIT(1); } else { CP_WAIT(0); }
        __syncthreads();

        // ---- rescale O, then O += P . V  (128x64, K=128); warp tile 32x16 ----
#pragma unroll
        for (int mt = 0; mt < 2; mt++) {
            const int r = wm + mt * 16 + lr;
            const float s0 = sc_s[r], s1 = sc_s[r + 8];
#pragma unroll
            for (int nt = 0; nt < 2; nt++) {
                accO[mt][nt][0] *= s0; accO[mt][nt][1] *= s0;
                accO[mt][nt][2] *= s1; accO[mt][nt][3] *= s1;
            }
        }
#pragma unroll
        for (int jj = 0; jj < 128; jj += 8) {
            uint32_t af[2][4], bf[2][2];
#pragma unroll
            for (int mt = 0; mt < 2; mt++) {
                const int m0 = wm + mt * 16 + lr;
                af[mt][0] = Ssu[m0 * SSS + jj + lc];
                af[mt][1] = Ssu[(m0 + 8) * SSS + jj + lc];
                af[mt][2] = Ssu[m0 * SSS + jj + 4 + lc];
                af[mt][3] = Ssu[(m0 + 8) * SSS + jj + 4 + lc];
            }
#pragma unroll
            for (int nt = 0; nt < 2; nt++) {
                const int n0 = wn2 + nt * 8 + lr;
                bf[nt][0] = Vsu[(jj + lc) * QSS + n0];
                bf[nt][1] = Vsu[(jj + 4 + lc) * QSS + n0];
            }
#pragma unroll
            for (int mt = 0; mt < 2; mt++)
#pragma unroll
                for (int nt = 0; nt < 2; nt++)
                    MMA_TF32(accO[mt][nt], af[mt], bf[nt]);
        }

        // K(jt+1) resident + all PV reads of Vs/Ss done before next iter writes
        if (more) CP_WAIT(0);
        __syncthreads();
    }

    // ---- finalize: O /= l, write av[(i*B + b)*D + n*64 + d] ----
#pragma unroll
    for (int mt = 0; mt < 2; mt++) {
        const int r = wm + mt * 16 + lr;
        const float inv0 = 1.f / l_s[r];
        const float inv1 = 1.f / l_s[r + 8];
#pragma unroll
        for (int nt = 0; nt < 2; nt++) {
            const int col = wn2 + nt * 8 + 2 * lc;
            float* p0 = av + ((size_t)(i0 + r) * BSZ + b) * DMODEL + n * DHEAD + col;
            *(float2*)p0 = make_float2(accO[mt][nt][0] * inv0, accO[mt][nt][1] * inv0);
            float* p1 = av + ((size_t)(i0 + r + 8) * BSZ + b) * DMODEL + n * DHEAD + col;
            *(float2*)p1 = make_float2(accO[mt][nt][2] * inv1, accO[mt][nt][3] * inv1);
        }
    }
}

// ----------------------------------------------------------------------------
// Row LayerNorm over D=1024 (one block per row, 4 elems/thread).
// ----------------------------------------------------------------------------
__device__ __forceinline__ float warpSum(float v) {
#pragma unroll
    for (int o = 16; o; o >>= 1) v += __shfl_xor_sync(0xffffffffu, v, o);
    return v;
}

__global__ __launch_bounds__(256) void ln_k(
    const float* __restrict__ X, const float* __restrict__ gam,
    const float* __restrict__ bet, float* __restrict__ Y)
{
    __shared__ float red[8];
    const size_t row = blockIdx.x;
    const int tid = threadIdx.x;
    const float4 v = *(const float4*)(X + row * DMODEL + tid * 4);
    float s = v.x + v.y + v.z + v.w;
    float q = v.x * v.x + v.y * v.y + v.z * v.z + v.w * v.w;

    float ws = warpSum(s);
    if ((tid & 31) == 0) red[tid >> 5] = ws;
    __syncthreads();
    if (tid < 32) {
        float t = (tid < 8) ? red[tid] : 0.f;
        t = warpSum(t);
        if (tid == 0) red[0] = t;
    }
    __syncthreads();
    const float mu = red[0] * (1.f / DMODEL);
    __syncthreads();

    float wq = warpSum(q);
    if ((tid & 31) == 0) red[tid >> 5] = wq;
    __syncthreads();
    if (tid < 32) {
        float t = (tid < 8) ? red[tid] : 0.f;
        t = warpSum(t);
        if (tid == 0) red[0] = t;
    }
    __syncthreads();
    const float var = red[0] * (1.f / DMODEL) - mu * mu;
    const float rs = rsqrtf(var + 1e-5f);

    const float4 gv = *(const float4*)(gam + tid * 4);
    const float4 bv = *(const float4*)(bet + tid * 4);
    float4 o;
    o.x = (v.x - mu) * rs * gv.x + bv.x;
    o.y = (v.y - mu) * rs * gv.y + bv.y;
    o.z = (v.z - mu) * rs * gv.z + bv.z;
    o.w = (v.w - mu) * rs * gv.w + bv.w;
    *(float4*)(Y + row * DMODEL + tid * 4) = o;
}

// ----------------------------------------------------------------------------
extern "C" void kernel_launch(void* const* d_in, const int* in_sizes, int n_in,
                              void* d_out, int out_size)
{
    (void)in_sizes; (void)n_in; (void)out_size;
    const float* w       = (const float*)d_in[0];
    const float* r       = (const float*)d_in[1];
    const float* mems    = (const float*)d_in[2];
    const float* qkv_w   = (const float*)d_in[3];
    const float* r_net_w = (const float*)d_in[4];
    const float* o_w     = (const float*)d_in[5];
    const float* rwb     = (const float*)d_in[6];
    const float* rrb     = (const float*)d_in[7];
    const float* ln1g    = (const float*)d_in[8];
    const float* ln1b    = (const float*)d_in[9];
    const float* ffw1    = (const float*)d_in[10];
    const float* ffb1    = (const float*)d_in[11];
    const float* ffw2    = (const float*)d_in[12];
    const float* ffb2    = (const float*)d_in[13];
    const float* ln2g    = (const float*)d_in[14];
    const float* ln2b    = (const float*)d_in[15];
    float* out = (float*)d_out;

    float *heads, *rk, *BD, *av, *tmp, *out1, *ffh;
    cudaGetSymbolAddress((void**)&heads, g_heads);
    cudaGetSymbolAddress((void**)&rk,    g_rk);
    cudaGetSymbolAddress((void**)&BD,    g_BD);
    cudaGetSymbolAddress((void**)&av,    g_av);
    cudaGetSymbolAddress((void**)&tmp,   g_tmp);
    cudaGetSymbolAddress((void**)&out1,  g_out1);
    cudaGetSymbolAddress((void**)&ffh,   g_ffh);

    static int s_attr_done = 0;
    if (!s_attr_done) {
        cudaFuncSetAttribute(flash_k, cudaFuncAttributeMaxDynamicSharedMemorySize,
                             FLASH_SMEM);
        s_attr_done = 1;
    }

    const dim3 blk(256);
    const int BIG = 1 << 30;
    const float* qbase = heads + (size_t)MEMLEN * BSZ * H3;  // query rows

    // 1) heads = concat(mems, w) @ qkv_w          [8192 x 3072 x 1024]
    mma_gemm<0><<<dim3(H3 / 128, (KLEN * BSZ) / 128, 1), blk>>>(
        mems, w, MEMLEN * BSZ, DMODEL, 0, 0, nullptr, 0,
        qkv_w, H3, 0, 0, nullptr, nullptr, 0,
        heads, H3, 0, 0, KLEN * BSZ, H3, DMODEL);

    // 2) rk = r @ r_net_w                          [2048 x 1024 x 1024]
    mma_gemm<0><<<dim3(DMODEL / 128, KLEN / 128, 1), blk>>>(
        r, r, BIG, DMODEL, 0, 0, nullptr, 0,
        r_net_w, DMODEL, 0, 0, nullptr, nullptr, 0,
        rk, DMODEL, 0, 0, KLEN, DMODEL, DMODEL);

    // 3) BD_pre[bn][i][c] = (q_i + rrb_n) . rk_c   batched, K=64
    mma_gemm<1><<<dim3(KLEN / 128, QLEN / 128, BSZ * NHEAD), blk>>>(
        qbase, qbase, BIG, BSZ * H3, H3, DHEAD, rrb, DHEAD,
        rk, DMODEL, 0, DHEAD, nullptr, nullptr, 0,
        BD, KLEN, 16 * QK, QK, QLEN, KLEN, DHEAD);

    // 4) flash: AC + shifted-BD + mask + softmax + PV -> av
    flash_k<<<dim3(QLEN / 128, BSZ * NHEAD), dim3(512), FLASH_SMEM>>>(heads, BD, rwb, av);

    // 5) attn_out = av @ o_w + w (residual)        [4096 x 1024 x 1024]
    mma_gemm<0><<<dim3(DMODEL / 128, (QLEN * BSZ) / 128, 1), blk>>>(
        av, av, BIG, DMODEL, 0, 0, nullptr, 0,
        o_w, DMODEL, 0, 0, nullptr, w, 0,
        tmp, DMODEL, 0, 0, QLEN * BSZ, DMODEL, DMODEL);

    // 6) LN1
    ln_k<<<QLEN * BSZ, blk>>>(tmp, ln1g, ln1b, out1);

    // 7) ffh = relu(out1 @ ff_w1 + b1)             [4096 x 4096 x 1024]
    mma_gemm<0><<<dim3(DINNER / 128, (QLEN * BSZ) / 128, 1), blk>>>(
        out1, out1, BIG, DMODEL, 0, 0, nullptr, 0,
        ffw1, DINNER, 0, 0, ffb1, nullptr, 1,
        ffh, DINNER, 0, 0, QLEN * BSZ, DINNER, DMODEL);

    // 8) tmp = ffh @ ff_w2 + b2 + out1             [4096 x 1024 x 4096]
    mma_gemm<0><<<dim3(DMODEL / 128, (QLEN * BSZ) / 128, 1), blk>>>(
        ffh, ffh, BIG, DINNER, 0, 0, nullptr, 0,
        ffw2, DMODEL, 0, 0, ffb2, out1, 0,
        tmp, DMODEL, 0, 0, QLEN * BSZ, DMODEL, DINNER);

    // 9) LN2 -> output
    ln_k<<<QLEN * BSZ, blk>>>(tmp, ln2g, ln2b, out);
}

// round 7
// speedup vs baseline: 1.2539x; 1.1211x over previous
#include <cuda_runtime.h>
#include <cuda_fp16.h>
#include <math.h>
#include <stdint.h>

#define QLEN   1024
#define BSZ    4
#define DMODEL 1024
#define NHEAD  16
#define DHEAD  64
#define DINNER 4096
#define MEMLEN 1024
#define KLEN   2048
#define H3     (3 * DMODEL)   // 3072
#define QK     ((long long)QLEN * KLEN)

// ---- static device scratch (no cudaMalloc allowed) ----
__device__ float g_heads[(size_t)KLEN * BSZ * H3];          // 8192 x 3072
__device__ float g_rk[(size_t)KLEN * DMODEL];               // 2048 x 1024
__device__ __half g_BD[(size_t)BSZ * NHEAD * QLEN * KLEN];  // fp16 BD_pre
__device__ float g_av[(size_t)QLEN * BSZ * DMODEL];
__device__ float g_tmp[(size_t)QLEN * BSZ * DMODEL];
__device__ float g_out1[(size_t)QLEN * BSZ * DMODEL];
__device__ float g_ffh[(size_t)QLEN * BSZ * DINNER];        // 4096 x 4096

__device__ __forceinline__ uint32_t f2tf32(float x) {
    uint32_t u;
    asm("cvt.rna.tf32.f32 %0, %1;" : "=r"(u) : "f"(x));
    return u;
}

__device__ __forceinline__ void cpa16(uint32_t s, const float* g) {
    asm volatile("cp.async.cg.shared.global [%0], [%1], 16;" :: "r"(s), "l"(g));
}
#define CP_COMMIT() asm volatile("cp.async.commit_group;")
#define CP_WAIT(N)  asm volatile("cp.async.wait_group %0;" :: "n"(N))

#define MMA_TF32(acc, av, bv)                                               \
    asm volatile(                                                           \
        "mma.sync.aligned.m16n8k8.row.col.f32.tf32.tf32.f32 "               \
        "{%0,%1,%2,%3}, {%4,%5,%6,%7}, {%8,%9}, {%0,%1,%2,%3};"             \
        : "+f"(acc[0]), "+f"(acc[1]), "+f"(acc[2]), "+f"(acc[3])            \
        : "r"(av[0]), "r"(av[1]), "r"(av[2]), "r"(av[3]),                   \
          "r"(bv[0]), "r"(bv[1]))

// ----------------------------------------------------------------------------
// Fast dense tf32 GEMM: C[M,N] = Arows @ B (+bias)(+resid)(relu).
// 3-stage cp.async pipeline, raw fp32 bits into tf32 MMA.
// 128x128 tile, 256 threads, 8 warps (2x4) of 64x32.
// ----------------------------------------------------------------------------
__global__ __launch_bounds__(256) void gemm_f(
    const float* __restrict__ A, const float* __restrict__ A2, int splitRow,
    int lda,
    const float* __restrict__ B,
    const float* __restrict__ bias, const float* __restrict__ resid, int doRelu,
    float* __restrict__ C, int M, int N, int Kd)
{
    __shared__ uint32_t As[3][2560];   // [m][20]  (16k + 4 pad)
    __shared__ uint32_t Bs[3][2176];   // [k][136] (128n + 8 pad)

    const int tid  = threadIdx.x;
    const int warp = tid >> 5, lane = tid & 31;
    const int lr = lane >> 2, lc = lane & 3;
    const int bm = blockIdx.y * 128, bn = blockIdx.x * 128;
    const int wm = (warp & 1) * 64;
    const int wn = (warp >> 1) * 32;

    float acc[4][4][4];
#pragma unroll
    for (int mt = 0; mt < 4; mt++)
#pragma unroll
        for (int nt = 0; nt < 4; nt++)
#pragma unroll
            for (int q = 0; q < 4; q++) acc[mt][nt][q] = 0.f;

    // per-thread loader geometry (2 chunks of 16B each for A and B)
    const float* aPtr[2];
    uint32_t aDst[2], bDst[2];
    const float* bPtr[2];
#pragma unroll
    for (int h = 0; h < 2; h++) {
        const int ch = tid + h * 256;
        const int arow = ch >> 2, akc = (ch & 3) * 4;
        const int gr = bm + arow;
        aPtr[h] = ((gr < splitRow) ? (A + (long long)gr * lda)
                                   : (A2 + (long long)(gr - splitRow) * lda)) + akc;
        aDst[h] = (uint32_t)__cvta_generic_to_shared(&As[0][arow * 20 + akc]);
        const int bkr = ch >> 5, bnc = (ch & 31) * 4;
        bPtr[h] = B + (long long)bkr * N + bn + bnc;
        bDst[h] = (uint32_t)__cvta_generic_to_shared(&Bs[0][bkr * 136 + bnc]);
    }
    const long long bStep = (long long)16 * N;

    auto load = [&](int kt, int s) {
#pragma unroll
        for (int h = 0; h < 2; h++)
            cpa16(aDst[h] + s * 2560 * 4, aPtr[h] + kt * 16);
#pragma unroll
        for (int h = 0; h < 2; h++)
            cpa16(bDst[h] + s * 2176 * 4, bPtr[h] + kt * bStep);
    };

    const int nk = Kd >> 4;
    load(0, 0); CP_COMMIT();
    load(1, 1); CP_COMMIT();

    for (int kt = 0; kt < nk; kt++) {
        const int s = kt % 3;
        CP_WAIT(1);
        __syncthreads();
        if (kt + 2 < nk) load(kt + 2, (kt + 2) % 3);
        CP_COMMIT();

#pragma unroll
        for (int kk = 0; kk < 16; kk += 8) {
            uint32_t af[4][4], bf[4][2];
#pragma unroll
            for (int mt = 0; mt < 4; mt++) {
                const int m0 = wm + mt * 16 + lr;
                af[mt][0] = As[s][m0 * 20 + kk + lc];
                af[mt][1] = As[s][(m0 + 8) * 20 + kk + lc];
                af[mt][2] = As[s][m0 * 20 + kk + 4 + lc];
                af[mt][3] = As[s][(m0 + 8) * 20 + kk + 4 + lc];
            }
#pragma unroll
            for (int nt = 0; nt < 4; nt++) {
                const int n0 = wn + nt * 8 + lr;
                bf[nt][0] = Bs[s][(kk + lc) * 136 + n0];
                bf[nt][1] = Bs[s][(kk + 4 + lc) * 136 + n0];
            }
#pragma unroll
            for (int mt = 0; mt < 4; mt++)
#pragma unroll
                for (int nt = 0; nt < 4; nt++)
                    MMA_TF32(acc[mt][nt], af[mt], bf[nt]);
        }
        __syncthreads();
    }

    // epilogue
#pragma unroll
    for (int mt = 0; mt < 4; mt++) {
#pragma unroll
        for (int nt = 0; nt < 4; nt++) {
            const int col = bn + wn + nt * 8 + lc * 2;
#pragma unroll
            for (int half = 0; half < 2; half++) {
                const int row = bm + wm + mt * 16 + lr + half * 8;
                float v0 = acc[mt][nt][half * 2 + 0];
                float v1 = acc[mt][nt][half * 2 + 1];
                if (bias) { v0 += bias[col]; v1 += bias[col + 1]; }
                if (resid) {
                    const float* rp = resid + (long long)row * N + col;
                    v0 += rp[0]; v1 += rp[1];
                }
                if (doRelu) { v0 = fmaxf(v0, 0.f); v1 = fmaxf(v1, 0.f); }
                float* cp = C + (long long)row * N + col;
                cp[0] = v0; cp[1] = v1;
            }
        }
    }
}

// ----------------------------------------------------------------------------
// Batched strided tf32 GEMM (BD only now): half output + causal tile skip.
// ----------------------------------------------------------------------------
template <int BT, int HOUT>
__global__ __launch_bounds__(256) void mma_gemm(
    const float* __restrict__ A, const float* __restrict__ A2, int splitRow,
    long long aRow, long long aHi, long long aLo,
    const float* __restrict__ abias, int abLo,
    const float* __restrict__ B, long long bRow, long long bHi, long long bLo,
    const float* __restrict__ cbias, const float* __restrict__ resid, int doRelu,
    void* __restrict__ Cv, long long cRow, long long cHi, long long cLo,
    int M, int N, int Kd, int diagSkip)
{
    __shared__ uint32_t As[2][2560];   // [m][20] (16 k + 4 pad)
    __shared__ uint32_t Bs[2][2560];   // BT: [n][20]; !BT: [k][136]

    const int tid  = threadIdx.x;
    const int warp = tid >> 5, lane = tid & 31;
    const int lr = lane >> 2, lc = lane & 3;
    const int bm = blockIdx.y * 128, bn = blockIdx.x * 128;
    if (diagSkip && bm + bn < 769) return;   // fully masked tile, never read
    const int bh = blockIdx.z >> 4, bl = blockIdx.z & 15;
    const long long aOff = (long long)bh * aHi + (long long)bl * aLo;
    const long long bOff = (long long)bh * bHi + (long long)bl * bLo;
    const long long cOff = (long long)bh * cHi + (long long)bl * cLo;
    const int wm = (warp & 1) * 64;
    const int wn = (warp >> 1) * 32;

    float acc[4][4][4];
#pragma unroll
    for (int mt = 0; mt < 4; mt++)
#pragma unroll
        for (int nt = 0; nt < 4; nt++)
#pragma unroll
            for (int q = 0; q < 4; q++) acc[mt][nt][q] = 0.f;

    const int ar  = tid >> 2;
    const int akc = (tid & 3) << 2;
    const int bkr = tid >> 5;
    const int bc  = (tid & 31) << 2;

    float4 aS[2], bS[2];

    auto gload = [&](int kt) {
        const int k0 = kt * 16;
#pragma unroll
        for (int h = 0; h < 2; h++) {
            const int row = bm + ar + h * 64;
            const float* ap = (row < splitRow)
                ? (A  + aOff + (long long)row * aRow)
                : (A2 + aOff + (long long)(row - splitRow) * aRow);
            float4 v = *(const float4*)(ap + k0 + akc);
            if (abias) {
                const float4 bb = *(const float4*)(abias + bl * abLo + k0 + akc);
                v.x += bb.x; v.y += bb.y; v.z += bb.z; v.w += bb.w;
            }
            aS[h] = v;
        }
        if (BT) {
#pragma unroll
            for (int h = 0; h < 2; h++) {
                const int nrow = bn + ar + h * 64;
                float4 v = make_float4(0.f, 0.f, 0.f, 0.f);
                if (nrow < N)
                    v = *(const float4*)(B + bOff + (long long)nrow * bRow + k0 + akc);
                bS[h] = v;
            }
        } else {
            const int col = bn + bc;
#pragma unroll
            for (int h = 0; h < 2; h++) {
                float4 v = make_float4(0.f, 0.f, 0.f, 0.f);
                if (col < N)
                    v = *(const float4*)(B + bOff + (long long)(k0 + bkr + h * 8) * bRow + col);
                bS[h] = v;
            }
        }
    };

    auto sstore = [&](int buf) {
#pragma unroll
        for (int h = 0; h < 2; h++) {
            uint32_t* p = &As[buf][(ar + h * 64) * 20 + akc];
            *(uint4*)p = make_uint4(f2tf32(aS[h].x), f2tf32(aS[h].y),
                                    f2tf32(aS[h].z), f2tf32(aS[h].w));
        }
        if (BT) {
#pragma unroll
            for (int h = 0; h < 2; h++) {
                uint32_t* p = &Bs[buf][(ar + h * 64) * 20 + akc];
                *(uint4*)p = make_uint4(f2tf32(bS[h].x), f2tf32(bS[h].y),
                                        f2tf32(bS[h].z), f2tf32(bS[h].w));
            }
        } else {
#pragma unroll
            for (int h = 0; h < 2; h++) {
                uint32_t* p = &Bs[buf][(bkr + h * 8) * 136 + bc];
                *(uint4*)p = make_uint4(f2tf32(bS[h].x), f2tf32(bS[h].y),
                                        f2tf32(bS[h].z), f2tf32(bS[h].w));
            }
        }
    };

    auto compute = [&](int buf) {
#pragma unroll
        for (int kk = 0; kk < 16; kk += 8) {
            uint32_t af[4][4], bf[4][2];
#pragma unroll
            for (int mt = 0; mt < 4; mt++) {
                const int m0 = wm + mt * 16 + lr;
                af[mt][0] = As[buf][m0 * 20 + kk + lc];
                af[mt][1] = As[buf][(m0 + 8) * 20 + kk + lc];
                af[mt][2] = As[buf][m0 * 20 + kk + 4 + lc];
                af[mt][3] = As[buf][(m0 + 8) * 20 + kk + 4 + lc];
            }
#pragma unroll
            for (int nt = 0; nt < 4; nt++) {
                const int n0 = wn + nt * 8 + lr;
                if (BT) {
                    bf[nt][0] = Bs[buf][n0 * 20 + kk + lc];
                    bf[nt][1] = Bs[buf][n0 * 20 + kk + 4 + lc];
                } else {
                    bf[nt][0] = Bs[buf][(kk + lc) * 136 + n0];
                    bf[nt][1] = Bs[buf][(kk + 4 + lc) * 136 + n0];
                }
            }
#pragma unroll
            for (int mt = 0; mt < 4; mt++)
#pragma unroll
                for (int nt = 0; nt < 4; nt++)
                    MMA_TF32(acc[mt][nt], af[mt], bf[nt]);
        }
    };

    const int nk = Kd >> 4;
    gload(0);
    sstore(0);
    __syncthreads();
    for (int kt = 0; kt < nk; kt++) {
        const int buf = kt & 1;
        if (kt + 1 < nk) gload(kt + 1);
        compute(buf);
        if (kt + 1 < nk) sstore(buf ^ 1);
        __syncthreads();
    }

#pragma unroll
    for (int mt = 0; mt < 4; mt++) {
#pragma unroll
        for (int nt = 0; nt < 4; nt++) {
            const int col = bn + wn + nt * 8 + lc * 2;
            if (col >= N) continue;
#pragma unroll
            for (int half = 0; half < 2; half++) {
                const int row = bm + wm + mt * 16 + lr + half * 8;
                float v0 = acc[mt][nt][half * 2 + 0];
                float v1 = acc[mt][nt][half * 2 + 1];
                if (cbias) { v0 += cbias[col]; v1 += cbias[col + 1]; }
                if (resid) {
                    const float* rp = resid + cOff + (long long)row * cRow + col;
                    v0 += rp[0]; v1 += rp[1];
                }
                if (doRelu) { v0 = fmaxf(v0, 0.f); v1 = fmaxf(v1, 0.f); }
                if (HOUT) {
                    __half* cp = (__half*)Cv + cOff + (long long)row * cRow + col;
                    cp[0] = __float2half(v0); cp[1] = __float2half(v1);
                } else {
                    float* cp = (float*)Cv + cOff + (long long)row * cRow + col;
                    cp[0] = v0; cp[1] = v1;
                }
            }
        }
    }
}

// ----------------------------------------------------------------------------
// Flash attention v3: 512 threads / 16 warps, cp.async pipelined K + V,
// warp-per-row softmax, fp16 BD reads.
// ----------------------------------------------------------------------------
#define QSS 68
#define SSS 132
#define FLASH_SMEM ((128 * QSS + 2 * 128 * QSS + 128 * QSS + 128 * SSS + 3 * 128) * 4)

__global__ __launch_bounds__(512, 1) void flash_k(
    const float* __restrict__ heads, const __half* __restrict__ BD,
    const float* __restrict__ rwb, float* __restrict__ av)
{
    extern __shared__ float sm[];
    float* Qs  = sm;                        // 128*68 (tf32 rna)
    float* Ks  = Qs + 128 * QSS;            // 2*128*68 (raw fp32, cp.async)
    float* Vs  = Ks + 2 * 128 * QSS;        // 128*68 (raw fp32, cp.async)
    float* Ss  = Vs + 128 * QSS;            // 128*132 (fp32 S, then trunc-tf32 P)
    float* m_s = Ss + 128 * SSS;            // 128
    float* l_s = m_s + 128;                 // 128
    float* sc_s = l_s + 128;                // 128
    uint32_t* Qsu = (uint32_t*)Qs;
    uint32_t* Ksu = (uint32_t*)Ks;
    uint32_t* Vsu = (uint32_t*)Vs;
    uint32_t* Ssu = (uint32_t*)Ss;
    const uint32_t ks_base = (uint32_t)__cvta_generic_to_shared(Ks);
    const uint32_t vs_base = (uint32_t)__cvta_generic_to_shared(Vs);

    const int tid = threadIdx.x;
    const int warp = tid >> 5, lane = tid & 31;
    const int lr = lane >> 2, lc = lane & 3;
    const int qt = (int)gridDim.x - 1 - (int)blockIdx.x;   // longest-first
    const int i0 = qt * 128;
    const int bn = blockIdx.y;
    const int b = bn >> 4, n = bn & 15;
    const int wm  = (warp & 3) * 32;         // 32-row group
    const int wn  = (warp >> 2) * 32;        // S col group (32 wide)
    const int wn2 = (warp >> 2) * 16;        // O col group (16 wide)
    const int njt = qt + 9;                  // causal+mem tile bound

    auto loadK = [&](int jt, int buf) {
        const int j0 = jt * 128;
#pragma unroll
        for (int it = 0; it < 4; it++) {
            const int c = tid + it * 512;
            const int row = c >> 4, seg = (c & 15) << 2;
            const float* g = heads + ((size_t)(j0 + row) * BSZ + b) * H3 + DMODEL + n * DHEAD + seg;
            cpa16(ks_base + (uint32_t)((((buf << 7) + row) * QSS + seg) << 2), g);
        }
        CP_COMMIT();
    };
    auto loadV = [&](int jt) {
        const int j0 = jt * 128;
#pragma unroll
        for (int it = 0; it < 4; it++) {
            const int c = tid + it * 512;
            const int row = c >> 4, seg = (c & 15) << 2;
            const float* g = heads + ((size_t)(j0 + row) * BSZ + b) * H3 + 2 * DMODEL + n * DHEAD + seg;
            cpa16(vs_base + (uint32_t)((row * QSS + seg) << 2), g);
        }
        CP_COMMIT();
    };

    // ---- prologue: issue K(0), load Q (+bias, rna), init stats ----
    loadK(0, 0);
    const float* qbase = heads + (size_t)MEMLEN * BSZ * H3;
#pragma unroll
    for (int it = 0; it < 4; it++) {
        const int idx = tid + it * 512;
        const int row = idx >> 4, c4 = (idx & 15) * 4;
        float4 v = *(const float4*)(qbase + ((size_t)(i0 + row) * BSZ + b) * H3 + n * DHEAD + c4);
        const float4 bb = *(const float4*)(rwb + n * DHEAD + c4);
        uint32_t* d = &Qsu[row * QSS + c4];
        d[0] = f2tf32(v.x + bb.x); d[1] = f2tf32(v.y + bb.y);
        d[2] = f2tf32(v.z + bb.z); d[3] = f2tf32(v.w + bb.w);
    }
    if (tid < 128) { m_s[tid] = -1e30f; l_s[tid] = 0.f; }

    float accO[2][2][4];
#pragma unroll
    for (int mt = 0; mt < 2; mt++)
#pragma unroll
        for (int nt = 0; nt < 2; nt++)
#pragma unroll
            for (int q = 0; q < 4; q++) accO[mt][nt][q] = 0.f;

    CP_WAIT(0);
    __syncthreads();   // Q staged, K(0) resident+visible

    for (int jt = 0; jt < njt; jt++) {
        const int j0 = jt * 128;
        const int cur = jt & 1;
        const bool more = (jt + 1 < njt);

        // ---- issue V(jt), then K(jt+1) prefetch ----
        loadV(jt);
        if (more) loadK(jt + 1, cur ^ 1);

        // ---- S = Qw . K[cur]^T  (128x128, K=64); warp tile 32x32 ----
        float accS[2][4][4];
#pragma unroll
        for (int mt = 0; mt < 2; mt++)
#pragma unroll
            for (int nt = 0; nt < 4; nt++)
#pragma unroll
                for (int q = 0; q < 4; q++) accS[mt][nt][q] = 0.f;

#pragma unroll
        for (int kk = 0; kk < 64; kk += 8) {
            uint32_t af[2][4], bf[4][2];
#pragma unroll
            for (int mt = 0; mt < 2; mt++) {
                const int m0 = wm + mt * 16 + lr;
                af[mt][0] = Qsu[m0 * QSS + kk + lc];
                af[mt][1] = Qsu[(m0 + 8) * QSS + kk + lc];
                af[mt][2] = Qsu[m0 * QSS + kk + 4 + lc];
                af[mt][3] = Qsu[(m0 + 8) * QSS + kk + 4 + lc];
            }
#pragma unroll
            for (int nt = 0; nt < 4; nt++) {
                const int n0 = (cur << 7) + wn + nt * 8 + lr;
                bf[nt][0] = Ksu[n0 * QSS + kk + lc];
                bf[nt][1] = Ksu[n0 * QSS + kk + 4 + lc];
            }
#pragma unroll
            for (int mt = 0; mt < 2; mt++)
#pragma unroll
                for (int nt = 0; nt < 4; nt++)
                    MMA_TF32(accS[mt][nt], af[mt], bf[nt]);
        }

        // ---- stage raw AC scores to smem ----
#pragma unroll
        for (int mt = 0; mt < 2; mt++) {
            const int r0 = wm + mt * 16 + lr;
#pragma unroll
            for (int nt = 0; nt < 4; nt++) {
                const int col = wn + nt * 8 + 2 * lc;
                *(float2*)&Ss[r0 * SSS + col] =
                    make_float2(accS[mt][nt][0], accS[mt][nt][1]);
                *(float2*)&Ss[(r0 + 8) * SSS + col] =
                    make_float2(accS[mt][nt][2], accS[mt][nt][3]);
            }
        }
        __syncthreads();

        // ---- softmax: one warp per row (8 rows/warp), fp16 BD reads ----
#pragma unroll 1
        for (int rr = 0; rr < 8; rr++) {
            const int row = warp * 8 + rr;
            const int i = i0 + row;
            const __half* bdp = BD + ((size_t)bn * QLEN + i) * KLEN + (j0 - i + QLEN - 1);
            const int vmax = i + MEMLEN - j0;   // valid col c <= vmax
            float sv[4];
            float mloc = -1e30f;
#pragma unroll
            for (int k2 = 0; k2 < 4; k2++) {
                const int c = lane + 32 * k2;
                float s = -1e30f;
                if (c <= vmax) s = (Ss[row * SSS + c] + __half2float(__ldg(bdp + c))) * 0.125f;
                sv[k2] = s;
                mloc = fmaxf(mloc, s);
            }
#pragma unroll
            for (int o = 16; o; o >>= 1)
                mloc = fmaxf(mloc, __shfl_xor_sync(0xffffffffu, mloc, o));
            const float mo = m_s[row];
            const float nm = fmaxf(mo, mloc);
            float lsum = 0.f;
#pragma unroll
            for (int k2 = 0; k2 < 4; k2++) {
                const int c = lane + 32 * k2;
                float p = __expf(sv[k2] - nm);
                const uint32_t pb = __float_as_uint(p) & 0xFFFFE000u;  // trunc to tf32
                const float pt = __uint_as_float(pb);
                lsum += pt;
                Ssu[row * SSS + c] = pb;
            }
#pragma unroll
            for (int o = 16; o; o >>= 1)
                lsum += __shfl_xor_sync(0xffffffffu, lsum, o);
            if (lane == 0) {
                const float alpha = __expf(mo - nm);
                m_s[row] = nm;
                l_s[row] = l_s[row] * alpha + lsum;
                sc_s[row] = alpha;
            }
        }
        __syncthreads();

        // ---- wait V(jt) (older group than K(jt+1)) ----
        if (more) { CP_WAIT(1); } else { CP_WAIT(0); }
        __syncthreads();

        // ---- rescale O, then O += P . V  (128x64, K=128); warp tile 32x16 ----
#pragma unroll
        for (int mt = 0; mt < 2; mt++) {
            const int r = wm + mt * 16 + lr;
            const float s0 = sc_s[r], s1 = sc_s[r + 8];
#pragma unroll
            for (int nt = 0; nt < 2; nt++) {
                accO[mt][nt][0] *= s0; accO[mt][nt][1] *= s0;
                accO[mt][nt][2] *= s1; accO[mt][nt][3] *= s1;
            }
        }
#pragma unroll
        for (int jj = 0; jj < 128; jj += 8) {
            uint32_t af[2][4], bf[2][2];
#pragma unroll
            for (int mt = 0; mt < 2; mt++) {
                const int m0 = wm + mt * 16 + lr;
                af[mt][0] = Ssu[m0 * SSS + jj + lc];
                af[mt][1] = Ssu[(m0 + 8) * SSS + jj + lc];
                af[mt][2] = Ssu[m0 * SSS + jj + 4 + lc];
                af[mt][3] = Ssu[(m0 + 8) * SSS + jj + 4 + lc];
            }
#pragma unroll
            for (int nt = 0; nt < 2; nt++) {
                const int n0 = wn2 + nt * 8 + lr;
                bf[nt][0] = Vsu[(jj + lc) * QSS + n0];
                bf[nt][1] = Vsu[(jj + 4 + lc) * QSS + n0];
            }
#pragma unroll
            for (int mt = 0; mt < 2; mt++)
#pragma unroll
                for (int nt = 0; nt < 2; nt++)
                    MMA_TF32(accO[mt][nt], af[mt], bf[nt]);
        }

        // K(jt+1) resident + all PV reads of Vs/Ss done before next iter writes
        if (more) CP_WAIT(0);
        __syncthreads();
    }

    // ---- finalize: O /= l, write av[(i*B + b)*D + n*64 + d] ----
#pragma unroll
    for (int mt = 0; mt < 2; mt++) {
        const int r = wm + mt * 16 + lr;
        const float inv0 = 1.f / l_s[r];
        const float inv1 = 1.f / l_s[r + 8];
#pragma unroll
        for (int nt = 0; nt < 2; nt++) {
            const int col = wn2 + nt * 8 + 2 * lc;
            float* p0 = av + ((size_t)(i0 + r) * BSZ + b) * DMODEL + n * DHEAD + col;
            *(float2*)p0 = make_float2(accO[mt][nt][0] * inv0, accO[mt][nt][1] * inv0);
            float* p1 = av + ((size_t)(i0 + r + 8) * BSZ + b) * DMODEL + n * DHEAD + col;
            *(float2*)p1 = make_float2(accO[mt][nt][2] * inv1, accO[mt][nt][3] * inv1);
        }
    }
}

// ----------------------------------------------------------------------------
// Row LayerNorm over D=1024 (one block per row, 4 elems/thread).
// ----------------------------------------------------------------------------
__device__ __forceinline__ float warpSum(float v) {
#pragma unroll
    for (int o = 16; o; o >>= 1) v += __shfl_xor_sync(0xffffffffu, v, o);
    return v;
}

__global__ __launch_bounds__(256) void ln_k(
    const float* __restrict__ X, const float* __restrict__ gam,
    const float* __restrict__ bet, float* __restrict__ Y)
{
    __shared__ float red[8];
    const size_t row = blockIdx.x;
    const int tid = threadIdx.x;
    const float4 v = *(const float4*)(X + row * DMODEL + tid * 4);
    float s = v.x + v.y + v.z + v.w;
    float q = v.x * v.x + v.y * v.y + v.z * v.z + v.w * v.w;

    float ws = warpSum(s);
    if ((tid & 31) == 0) red[tid >> 5] = ws;
    __syncthreads();
    if (tid < 32) {
        float t = (tid < 8) ? red[tid] : 0.f;
        t = warpSum(t);
        if (tid == 0) red[0] = t;
    }
    __syncthreads();
    const float mu = red[0] * (1.f / DMODEL);
    __syncthreads();

    float wq = warpSum(q);
    if ((tid & 31) == 0) red[tid >> 5] = wq;
    __syncthreads();
    if (tid < 32) {
        float t = (tid < 8) ? red[tid] : 0.f;
        t = warpSum(t);
        if (tid == 0) red[0] = t;
    }
    __syncthreads();
    const float var = red[0] * (1.f / DMODEL) - mu * mu;
    const float rs = rsqrtf(var + 1e-5f);

    const float4 gv = *(const float4*)(gam + tid * 4);
    const float4 bv = *(const float4*)(bet + tid * 4);
    float4 o;
    o.x = (v.x - mu) * rs * gv.x + bv.x;
    o.y = (v.y - mu) * rs * gv.y + bv.y;
    o.z = (v.z - mu) * rs * gv.z + bv.z;
    o.w = (v.w - mu) * rs * gv.w + bv.w;
    *(float4*)(Y + row * DMODEL + tid * 4) = o;
}

// ----------------------------------------------------------------------------
extern "C" void kernel_launch(void* const* d_in, const int* in_sizes, int n_in,
                              void* d_out, int out_size)
{
    (void)in_sizes; (void)n_in; (void)out_size;
    const float* w       = (const float*)d_in[0];
    const float* r       = (const float*)d_in[1];
    const float* mems    = (const float*)d_in[2];
    const float* qkv_w   = (const float*)d_in[3];
    const float* r_net_w = (const float*)d_in[4];
    const float* o_w     = (const float*)d_in[5];
    const float* rwb     = (const float*)d_in[6];
    const float* rrb     = (const float*)d_in[7];
    const float* ln1g    = (const float*)d_in[8];
    const float* ln1b    = (const float*)d_in[9];
    const float* ffw1    = (const float*)d_in[10];
    const float* ffb1    = (const float*)d_in[11];
    const float* ffw2    = (const float*)d_in[12];
    const float* ffb2    = (const float*)d_in[13];
    const float* ln2g    = (const float*)d_in[14];
    const float* ln2b    = (const float*)d_in[15];
    float* out = (float*)d_out;

    float *heads, *rk, *av, *tmp, *out1, *ffh;
    __half* BD;
    cudaGetSymbolAddress((void**)&heads, g_heads);
    cudaGetSymbolAddress((void**)&rk,    g_rk);
    cudaGetSymbolAddress((void**)&BD,    g_BD);
    cudaGetSymbolAddress((void**)&av,    g_av);
    cudaGetSymbolAddress((void**)&tmp,   g_tmp);
    cudaGetSymbolAddress((void**)&out1,  g_out1);
    cudaGetSymbolAddress((void**)&ffh,   g_ffh);

    static int s_attr_done = 0;
    if (!s_attr_done) {
        cudaFuncSetAttribute(flash_k, cudaFuncAttributeMaxDynamicSharedMemorySize,
                             FLASH_SMEM);
        s_attr_done = 1;
    }

    const dim3 blk(256);
    const int BIG = 1 << 30;
    const float* qbase = heads + (size_t)MEMLEN * BSZ * H3;  // query rows

    // 1) heads = concat(mems, w) @ qkv_w          [8192 x 3072 x 1024]
    gemm_f<<<dim3(H3 / 128, (KLEN * BSZ) / 128), blk>>>(
        mems, w, MEMLEN * BSZ, DMODEL, qkv_w, nullptr, nullptr, 0,
        heads, KLEN * BSZ, H3, DMODEL);

    // 2) rk = r @ r_net_w                          [2048 x 1024 x 1024]
    gemm_f<<<dim3(DMODEL / 128, KLEN / 128), blk>>>(
        r, r, BIG, DMODEL, r_net_w, nullptr, nullptr, 0,
        rk, KLEN, DMODEL, DMODEL);

    // 3) BD_pre[bn][i][c] = (q_i + rrb_n) . rk_c   batched, K=64, fp16 out
    mma_gemm<1, 1><<<dim3(KLEN / 128, QLEN / 128, BSZ * NHEAD), blk>>>(
        qbase, qbase, BIG, BSZ * H3, H3, DHEAD, rrb, DHEAD,
        rk, DMODEL, 0, DHEAD, nullptr, nullptr, 0,
        (void*)BD, KLEN, 16 * QK, QK, QLEN, KLEN, DHEAD, 1);

    // 4) flash: AC + shifted-BD + mask + softmax + PV -> av
    flash_k<<<dim3(QLEN / 128, BSZ * NHEAD), dim3(512), FLASH_SMEM>>>(heads, BD, rwb, av);

    // 5) attn_out = av @ o_w + w (residual)        [4096 x 1024 x 1024]
    gemm_f<<<dim3(DMODEL / 128, (QLEN * BSZ) / 128), blk>>>(
        av, av, BIG, DMODEL, o_w, nullptr, w, 0,
        tmp, QLEN * BSZ, DMODEL, DMODEL);

    // 6) LN1
    ln_k<<<QLEN * BSZ, blk>>>(tmp, ln1g, ln1b, out1);

    // 7) ffh = relu(out1 @ ff_w1 + b1)             [4096 x 4096 x 1024]
    gemm_f<<<dim3(DINNER / 128, (QLEN * BSZ) / 128), blk>>>(
        out1, out1, BIG, DMODEL, ffw1, ffb1, nullptr, 1,
        ffh, QLEN * BSZ, DINNER, DMODEL);

    // 8) tmp = ffh @ ff_w2 + b2 + out1             [4096 x 1024 x 4096]
    gemm_f<<<dim3(DMODEL / 128, (QLEN * BSZ) / 128), blk>>>(
        ffh, ffh, BIG, DINNER, ffw2, ffb2, out1, 0,
        tmp, QLEN * BSZ, DMODEL, DINNER);

    // 9) LN2 -> output
    ln_k<<<QLEN * BSZ, blk>>>(tmp, ln2g, ln2b, out);
}

// round 8
// speedup vs baseline: 1.4412x; 1.1493x over previous
#include <cuda_runtime.h>
#include <cuda_fp16.h>
#include <math.h>
#include <stdint.h>

#define QLEN   1024
#define BSZ    4
#define DMODEL 1024
#define NHEAD  16
#define DHEAD  64
#define DINNER 4096
#define MEMLEN 1024
#define KLEN   2048
#define H3     (3 * DMODEL)   // 3072
#define QK     ((long long)QLEN * KLEN)

// ---- static device scratch (no cudaMalloc allowed) ----
__device__ float g_heads[(size_t)KLEN * BSZ * H3];          // 8192 x 3072
__device__ float g_rk[(size_t)KLEN * DMODEL];               // 2048 x 1024
__device__ float g_rbias[(size_t)NHEAD * KLEN];             // rrb . rk
__device__ __half g_BD[(size_t)BSZ * NHEAD * QLEN * KLEN];  // fp16 BD_pre
__device__ float g_av[(size_t)QLEN * BSZ * DMODEL];
__device__ float g_tmp[(size_t)QLEN * BSZ * DMODEL];
__device__ float g_out1[(size_t)QLEN * BSZ * DMODEL];
__device__ float g_ffh[(size_t)QLEN * BSZ * DINNER];        // 4096 x 4096

__device__ __forceinline__ uint32_t f2tf32(float x) {
    uint32_t u;
    asm("cvt.rna.tf32.f32 %0, %1;" : "=r"(u) : "f"(x));
    return u;
}

__device__ __forceinline__ void cpa16(uint32_t s, const float* g) {
    asm volatile("cp.async.cg.shared.global [%0], [%1], 16;" :: "r"(s), "l"(g));
}
#define CP_COMMIT() asm volatile("cp.async.commit_group;")
#define CP_WAIT(N)  asm volatile("cp.async.wait_group %0;" :: "n"(N))

// +half-ULP of tf32: raw-bits round-to-nearest before HW truncation
#define RN(x) ((x) + 0x1000u)

#define MMA_TF32(acc, av, bv)                                               \
    asm volatile(                                                           \
        "mma.sync.aligned.m16n8k8.row.col.f32.tf32.tf32.f32 "               \
        "{%0,%1,%2,%3}, {%4,%5,%6,%7}, {%8,%9}, {%0,%1,%2,%3};"             \
        : "+f"(acc[0]), "+f"(acc[1]), "+f"(acc[2]), "+f"(acc[3])            \
        : "r"(av[0]), "r"(av[1]), "r"(av[2]), "r"(av[3]),                   \
          "r"(bv[0]), "r"(bv[1]))

// ----------------------------------------------------------------------------
// Fast dense tf32 GEMM: C[M,N] = Arows @ B (+bias)(+resid)(relu).
// 3-stage cp.async pipeline, RN-rounded fp32 bits into tf32 MMA.
// 128x128 tile, 256 threads, 8 warps (2x4) of 64x32.
// ----------------------------------------------------------------------------
__global__ __launch_bounds__(256, 2) void gemm_f(
    const float* __restrict__ A, const float* __restrict__ A2, int splitRow,
    int lda,
    const float* __restrict__ B,
    const float* __restrict__ bias, const float* __restrict__ resid, int doRelu,
    float* __restrict__ C, int M, int N, int Kd)
{
    __shared__ uint32_t As[3][2560];   // [m][20]  (16k + 4 pad)
    __shared__ uint32_t Bs[3][2176];   // [k][136] (128n + 8 pad)

    const int tid  = threadIdx.x;
    const int warp = tid >> 5, lane = tid & 31;
    const int lr = lane >> 2, lc = lane & 3;
    const int bm = blockIdx.y * 128, bn = blockIdx.x * 128;
    const int wm = (warp & 1) * 64;
    const int wn = (warp >> 1) * 32;

    float acc[4][4][4];
#pragma unroll
    for (int mt = 0; mt < 4; mt++)
#pragma unroll
        for (int nt = 0; nt < 4; nt++)
#pragma unroll
            for (int q = 0; q < 4; q++) acc[mt][nt][q] = 0.f;

    const float* aPtr[2];
    uint32_t aDst[2], bDst[2];
    const float* bPtr[2];
#pragma unroll
    for (int h = 0; h < 2; h++) {
        const int ch = tid + h * 256;
        const int arow = ch >> 2, akc = (ch & 3) * 4;
        const int gr = bm + arow;
        aPtr[h] = ((gr < splitRow) ? (A + (long long)gr * lda)
                                   : (A2 + (long long)(gr - splitRow) * lda)) + akc;
        aDst[h] = (uint32_t)__cvta_generic_to_shared(&As[0][arow * 20 + akc]);
        const int bkr = ch >> 5, bnc = (ch & 31) * 4;
        bPtr[h] = B + (long long)bkr * N + bn + bnc;
        bDst[h] = (uint32_t)__cvta_generic_to_shared(&Bs[0][bkr * 136 + bnc]);
    }
    const long long bStep = (long long)16 * N;

    auto load = [&](int kt, int s) {
#pragma unroll
        for (int h = 0; h < 2; h++)
            cpa16(aDst[h] + s * 2560 * 4, aPtr[h] + kt * 16);
#pragma unroll
        for (int h = 0; h < 2; h++)
            cpa16(bDst[h] + s * 2176 * 4, bPtr[h] + kt * bStep);
    };

    const int nk = Kd >> 4;
    load(0, 0); CP_COMMIT();
    load(1, 1); CP_COMMIT();

    for (int kt = 0; kt < nk; kt++) {
        const int s = kt % 3;
        CP_WAIT(1);
        __syncthreads();   // stage s ready; also protects stage reuse (see note)
        if (kt + 2 < nk) load(kt + 2, (kt + 2) % 3);
        CP_COMMIT();

#pragma unroll
        for (int kk = 0; kk < 16; kk += 8) {
            uint32_t af[4][4], bf[4][2];
#pragma unroll
            for (int mt = 0; mt < 4; mt++) {
                const int m0 = wm + mt * 16 + lr;
                af[mt][0] = RN(As[s][m0 * 20 + kk + lc]);
                af[mt][1] = RN(As[s][(m0 + 8) * 20 + kk + lc]);
                af[mt][2] = RN(As[s][m0 * 20 + kk + 4 + lc]);
                af[mt][3] = RN(As[s][(m0 + 8) * 20 + kk + 4 + lc]);
            }
#pragma unroll
            for (int nt = 0; nt < 4; nt++) {
                const int n0 = wn + nt * 8 + lr;
                bf[nt][0] = RN(Bs[s][(kk + lc) * 136 + n0]);
                bf[nt][1] = RN(Bs[s][(kk + 4 + lc) * 136 + n0]);
            }
#pragma unroll
            for (int mt = 0; mt < 4; mt++)
#pragma unroll
                for (int nt = 0; nt < 4; nt++)
                    MMA_TF32(acc[mt][nt], af[mt], bf[nt]);
        }
        // no bottom barrier needed: next iteration's loads target stage
        // (kt+3)%3 and are issued only after the next top barrier, which
        // all threads reach only after finishing this iteration's reads.
    }

    // epilogue
#pragma unroll
    for (int mt = 0; mt < 4; mt++) {
#pragma unroll
        for (int nt = 0; nt < 4; nt++) {
            const int col = bn + wn + nt * 8 + lc * 2;
#pragma unroll
            for (int half = 0; half < 2; half++) {
                const int row = bm + wm + mt * 16 + lr + half * 8;
                float v0 = acc[mt][nt][half * 2 + 0];
                float v1 = acc[mt][nt][half * 2 + 1];
                if (bias) { v0 += bias[col]; v1 += bias[col + 1]; }
                if (resid) {
                    const float* rp = resid + (long long)row * N + col;
                    v0 += rp[0]; v1 += rp[1];
                }
                if (doRelu) { v0 = fmaxf(v0, 0.f); v1 = fmaxf(v1, 0.f); }
                float* cp = C + (long long)row * N + col;
                cp[0] = v0; cp[1] = v1;
            }
        }
    }
}

// ----------------------------------------------------------------------------
// rbias[n][c] = rrb_n . rk_c   (tiny; enables bias-free async BD GEMM)
// ----------------------------------------------------------------------------
__global__ __launch_bounds__(256) void rbias_k(
    const float* __restrict__ rrb, const float* __restrict__ rk,
    float* __restrict__ rbias)
{
    const int idx = blockIdx.x * 256 + threadIdx.x;   // 32768 = 2048c x 16n
    const int c = idx >> 4, n = idx & 15;
    const float* rp = rk + (size_t)c * DMODEL + n * DHEAD;
    const float* bp = rrb + n * DHEAD;
    float s = 0.f;
#pragma unroll
    for (int d = 0; d < DHEAD; d++) s += rp[d] * bp[d];
    rbias[n * KLEN + c] = s;
}

// ----------------------------------------------------------------------------
// BD GEMM: BD[bn][i][c] = q_i . rk_c (+rbias[n][c]), fp16 out, diag skip.
// cp.async 3-stage, batched over (b,n). 128x128 tile, K=64.
// ----------------------------------------------------------------------------
__global__ __launch_bounds__(256, 2) void bd_gemm(
    const float* __restrict__ Q,      // qbase (query rows of g_heads)
    const float* __restrict__ RK,     // g_rk
    const float* __restrict__ rbias,  // [16][2048]
    __half* __restrict__ BD)
{
    __shared__ uint32_t As[3][2560];   // [m][20]
    __shared__ uint32_t Bs[3][2560];   // [n][20]  (BT: rows are rk rows)

    const int tid = threadIdx.x;
    const int warp = tid >> 5, lane = tid & 31;
    const int lr = lane >> 2, lc = lane & 3;
    const int bm = blockIdx.y * 128, bn = blockIdx.x * 128;
    if (bm + bn < 769) return;   // fully masked tile, never read by flash
    const int bnidx = blockIdx.z;
    const int b = bnidx >> 4, n = bnidx & 15;
    const int wm = (warp & 1) * 64;
    const int wn = (warp >> 1) * 32;

    float acc[4][4][4];
#pragma unroll
    for (int mt = 0; mt < 4; mt++)
#pragma unroll
        for (int nt = 0; nt < 4; nt++)
#pragma unroll
            for (int q = 0; q < 4; q++) acc[mt][nt][q] = 0.f;

    const float* aPtr[2];
    const float* bPtr[2];
    uint32_t aDst[2], bDst[2];
#pragma unroll
    for (int h = 0; h < 2; h++) {
        const int ch = tid + h * 256;
        const int row = ch >> 2, kc = (ch & 3) * 4;
        aPtr[h] = Q + (size_t)(bm + row) * (BSZ * H3) + (size_t)b * H3 + n * DHEAD + kc;
        aDst[h] = (uint32_t)__cvta_generic_to_shared(&As[0][row * 20 + kc]);
        bPtr[h] = RK + (size_t)(bn + row) * DMODEL + n * DHEAD + kc;
        bDst[h] = (uint32_t)__cvta_generic_to_shared(&Bs[0][row * 20 + kc]);
    }

    auto load = [&](int kt, int s) {
#pragma unroll
        for (int h = 0; h < 2; h++)
            cpa16(aDst[h] + s * 2560 * 4, aPtr[h] + kt * 16);
#pragma unroll
        for (int h = 0; h < 2; h++)
            cpa16(bDst[h] + s * 2560 * 4, bPtr[h] + kt * 16);
    };

    const int nk = 4;   // K = 64
    load(0, 0); CP_COMMIT();
    load(1, 1); CP_COMMIT();

    for (int kt = 0; kt < nk; kt++) {
        const int s = kt % 3;
        CP_WAIT(1);
        __syncthreads();
        if (kt + 2 < nk) load(kt + 2, (kt + 2) % 3);
        CP_COMMIT();

#pragma unroll
        for (int kk = 0; kk < 16; kk += 8) {
            uint32_t af[4][4], bf[4][2];
#pragma unroll
            for (int mt = 0; mt < 4; mt++) {
                const int m0 = wm + mt * 16 + lr;
                af[mt][0] = RN(As[s][m0 * 20 + kk + lc]);
                af[mt][1] = RN(As[s][(m0 + 8) * 20 + kk + lc]);
                af[mt][2] = RN(As[s][m0 * 20 + kk + 4 + lc]);
                af[mt][3] = RN(As[s][(m0 + 8) * 20 + kk + 4 + lc]);
            }
#pragma unroll
            for (int nt = 0; nt < 4; nt++) {
                const int n0 = wn + nt * 8 + lr;
                bf[nt][0] = RN(Bs[s][n0 * 20 + kk + lc]);
                bf[nt][1] = RN(Bs[s][n0 * 20 + kk + 4 + lc]);
            }
#pragma unroll
            for (int mt = 0; mt < 4; mt++)
#pragma unroll
                for (int nt = 0; nt < 4; nt++)
                    MMA_TF32(acc[mt][nt], af[mt], bf[nt]);
        }
    }

    // epilogue: + rbias, fp16 store
#pragma unroll
    for (int mt = 0; mt < 4; mt++) {
#pragma unroll
        for (int nt = 0; nt < 4; nt++) {
            const int col = bn + wn + nt * 8 + lc * 2;
            const float rb0 = rbias[n * KLEN + col];
            const float rb1 = rbias[n * KLEN + col + 1];
#pragma unroll
            for (int half = 0; half < 2; half++) {
                const int row = bm + wm + mt * 16 + lr + half * 8;
                const float v0 = acc[mt][nt][half * 2 + 0] + rb0;
                const float v1 = acc[mt][nt][half * 2 + 1] + rb1;
                __half2* cp = (__half2*)(BD + ((size_t)bnidx * QLEN + row) * KLEN + col);
                *cp = __floats2half2_rn(v0, v1);
            }
        }
    }
}

// ----------------------------------------------------------------------------
// Flash attention: 512 threads / 16 warps, cp.async pipelined K + V,
// warp-per-row softmax (fp16 BD), RN-rounded K/V fragments, merged barriers.
// ----------------------------------------------------------------------------
#define QSS 68
#define SSS 132
#define FLASH_SMEM ((128 * QSS + 2 * 128 * QSS + 128 * QSS + 128 * SSS + 3 * 128) * 4)

__global__ __launch_bounds__(512, 1) void flash_k(
    const float* __restrict__ heads, const __half* __restrict__ BD,
    const float* __restrict__ rwb, float* __restrict__ av)
{
    extern __shared__ float sm[];
    float* Qs  = sm;                        // 128*68 (tf32 rna)
    float* Ks  = Qs + 128 * QSS;            // 2*128*68 (raw fp32, cp.async)
    float* Vs  = Ks + 2 * 128 * QSS;        // 128*68 (raw fp32, cp.async)
    float* Ss  = Vs + 128 * QSS;            // 128*132 (fp32 S, then trunc-tf32 P)
    float* m_s = Ss + 128 * SSS;            // 128
    float* l_s = m_s + 128;                 // 128
    float* sc_s = l_s + 128;                // 128
    uint32_t* Qsu = (uint32_t*)Qs;
    uint32_t* Ksu = (uint32_t*)Ks;
    uint32_t* Vsu = (uint32_t*)Vs;
    uint32_t* Ssu = (uint32_t*)Ss;
    const uint32_t ks_base = (uint32_t)__cvta_generic_to_shared(Ks);
    const uint32_t vs_base = (uint32_t)__cvta_generic_to_shared(Vs);

    const int tid = threadIdx.x;
    const int warp = tid >> 5, lane = tid & 31;
    const int lr = lane >> 2, lc = lane & 3;
    const int qt = (int)gridDim.x - 1 - (int)blockIdx.x;   // longest-first
    const int i0 = qt * 128;
    const int bn = blockIdx.y;
    const int b = bn >> 4, n = bn & 15;
    const int wm  = (warp & 3) * 32;         // 32-row group
    const int wn  = (warp >> 2) * 32;        // S col group (32 wide)
    const int wn2 = (warp >> 2) * 16;        // O col group (16 wide)
    const int njt = qt + 9;                  // causal+mem tile bound

    auto loadK = [&](int jt, int buf) {
        const int j0 = jt * 128;
#pragma unroll
        for (int it = 0; it < 4; it++) {
            const int c = tid + it * 512;
            const int row = c >> 4, seg = (c & 15) << 2;
            const float* g = heads + ((size_t)(j0 + row) * BSZ + b) * H3 + DMODEL + n * DHEAD + seg;
            cpa16(ks_base + (uint32_t)((((buf << 7) + row) * QSS + seg) << 2), g);
        }
        CP_COMMIT();
    };
    auto loadV = [&](int jt) {
        const int j0 = jt * 128;
#pragma unroll
        for (int it = 0; it < 4; it++) {
            const int c = tid + it * 512;
            const int row = c >> 4, seg = (c & 15) << 2;
            const float* g = heads + ((size_t)(j0 + row) * BSZ + b) * H3 + 2 * DMODEL + n * DHEAD + seg;
            cpa16(vs_base + (uint32_t)((row * QSS + seg) << 2), g);
        }
        CP_COMMIT();
    };

    // ---- prologue: issue K(0), load Q (+bias, rna), init stats ----
    loadK(0, 0);
    const float* qbase = heads + (size_t)MEMLEN * BSZ * H3;
#pragma unroll
    for (int it = 0; it < 4; it++) {
        const int idx = tid + it * 512;
        const int row = idx >> 4, c4 = (idx & 15) * 4;
        float4 v = *(const float4*)(qbase + ((size_t)(i0 + row) * BSZ + b) * H3 + n * DHEAD + c4);
        const float4 bb = *(const float4*)(rwb + n * DHEAD + c4);
        uint32_t* d = &Qsu[row * QSS + c4];
        d[0] = f2tf32(v.x + bb.x); d[1] = f2tf32(v.y + bb.y);
        d[2] = f2tf32(v.z + bb.z); d[3] = f2tf32(v.w + bb.w);
    }
    if (tid < 128) { m_s[tid] = -1e30f; l_s[tid] = 0.f; }

    float accO[2][2][4];
#pragma unroll
    for (int mt = 0; mt < 2; mt++)
#pragma unroll
        for (int nt = 0; nt < 2; nt++)
#pragma unroll
            for (int q = 0; q < 4; q++) accO[mt][nt][q] = 0.f;

    CP_WAIT(0);
    __syncthreads();   // Q staged, K(0) resident+visible

    for (int jt = 0; jt < njt; jt++) {
        const int j0 = jt * 128;
        const int cur = jt & 1;
        const bool more = (jt + 1 < njt);

        // ---- issue V(jt), then K(jt+1) prefetch ----
        loadV(jt);
        if (more) loadK(jt + 1, cur ^ 1);

        // ---- S = Qw . K[cur]^T  (128x128, K=64); warp tile 32x32 ----
        float accS[2][4][4];
#pragma unroll
        for (int mt = 0; mt < 2; mt++)
#pragma unroll
            for (int nt = 0; nt < 4; nt++)
#pragma unroll
                for (int q = 0; q < 4; q++) accS[mt][nt][q] = 0.f;

#pragma unroll
        for (int kk = 0; kk < 64; kk += 8) {
            uint32_t af[2][4], bf[4][2];
#pragma unroll
            for (int mt = 0; mt < 2; mt++) {
                const int m0 = wm + mt * 16 + lr;
                af[mt][0] = Qsu[m0 * QSS + kk + lc];
                af[mt][1] = Qsu[(m0 + 8) * QSS + kk + lc];
                af[mt][2] = Qsu[m0 * QSS + kk + 4 + lc];
                af[mt][3] = Qsu[(m0 + 8) * QSS + kk + 4 + lc];
            }
#pragma unroll
            for (int nt = 0; nt < 4; nt++) {
                const int n0 = (cur << 7) + wn + nt * 8 + lr;
                bf[nt][0] = RN(Ksu[n0 * QSS + kk + lc]);
                bf[nt][1] = RN(Ksu[n0 * QSS + kk + 4 + lc]);
            }
#pragma unroll
            for (int mt = 0; mt < 2; mt++)
#pragma unroll
                for (int nt = 0; nt < 4; nt++)
                    MMA_TF32(accS[mt][nt], af[mt], bf[nt]);
        }

        // ---- stage raw AC scores to smem ----
#pragma unroll
        for (int mt = 0; mt < 2; mt++) {
            const int r0 = wm + mt * 16 + lr;
#pragma unroll
            for (int nt = 0; nt < 4; nt++) {
                const int col = wn + nt * 8 + 2 * lc;
                *(float2*)&Ss[r0 * SSS + col] =
                    make_float2(accS[mt][nt][0], accS[mt][nt][1]);
                *(float2*)&Ss[(r0 + 8) * SSS + col] =
                    make_float2(accS[mt][nt][2], accS[mt][nt][3]);
            }
        }
        __syncthreads();

        // ---- softmax: one warp per row (8 rows/warp), fp16 BD reads ----
#pragma unroll 2
        for (int rr = 0; rr < 8; rr++) {
            const int row = warp * 8 + rr;
            const int i = i0 + row;
            const __half* bdp = BD + ((size_t)bn * QLEN + i) * KLEN + (j0 - i + QLEN - 1);
            const int vmax = i + MEMLEN - j0;   // valid col c <= vmax
            float sv[4];
            float mloc = -1e30f;
#pragma unroll
            for (int k2 = 0; k2 < 4; k2++) {
                const int c = lane + 32 * k2;
                float s = -1e30f;
                if (c <= vmax) s = (Ss[row * SSS + c] + __half2float(__ldg(bdp + c))) * 0.125f;
                sv[k2] = s;
                mloc = fmaxf(mloc, s);
            }
#pragma unroll
            for (int o = 16; o; o >>= 1)
                mloc = fmaxf(mloc, __shfl_xor_sync(0xffffffffu, mloc, o));
            const float mo = m_s[row];
            const float nm = fmaxf(mo, mloc);
            float lsum = 0.f;
#pragma unroll
            for (int k2 = 0; k2 < 4; k2++) {
                const int c = lane + 32 * k2;
                float p = __expf(sv[k2] - nm);
                const uint32_t pb = __float_as_uint(p) & 0xFFFFE000u;  // trunc to tf32
                const float pt = __uint_as_float(pb);
                lsum += pt;
                Ssu[row * SSS + c] = pb;
            }
#pragma unroll
            for (int o = 16; o; o >>= 1)
                lsum += __shfl_xor_sync(0xffffffffu, lsum, o);
            if (lane == 0) {
                const float alpha = __expf(mo - nm);
                m_s[row] = nm;
                l_s[row] = l_s[row] * alpha + lsum;
                sc_s[row] = alpha;
            }
        }

        // ---- single barrier covers: P/stat visibility AND V(jt) residency ----
        if (more) { CP_WAIT(1); } else { CP_WAIT(0); }
        __syncthreads();

        // ---- rescale O, then O += P . V  (128x64, K=128); warp tile 32x16 ----
#pragma unroll
        for (int mt = 0; mt < 2; mt++) {
            const int r = wm + mt * 16 + lr;
            const float s0 = sc_s[r], s1 = sc_s[r + 8];
#pragma unroll
            for (int nt = 0; nt < 2; nt++) {
                accO[mt][nt][0] *= s0; accO[mt][nt][1] *= s0;
                accO[mt][nt][2] *= s1; accO[mt][nt][3] *= s1;
            }
        }
#pragma unroll
        for (int jj = 0; jj < 128; jj += 8) {
            uint32_t af[2][4], bf[2][2];
#pragma unroll
            for (int mt = 0; mt < 2; mt++) {
                const int m0 = wm + mt * 16 + lr;
                af[mt][0] = Ssu[m0 * SSS + jj + lc];
                af[mt][1] = Ssu[(m0 + 8) * SSS + jj + lc];
                af[mt][2] = Ssu[m0 * SSS + jj + 4 + lc];
                af[mt][3] = Ssu[(m0 + 8) * SSS + jj + 4 + lc];
            }
#pragma unroll
            for (int nt = 0; nt < 2; nt++) {
                const int n0 = wn2 + nt * 8 + lr;
                bf[nt][0] = RN(Vsu[(jj + lc) * QSS + n0]);
                bf[nt][1] = RN(Vsu[(jj + 4 + lc) * QSS + n0]);
            }
#pragma unroll
            for (int mt = 0; mt < 2; mt++)
#pragma unroll
                for (int nt = 0; nt < 2; nt++)
                    MMA_TF32(accO[mt][nt], af[mt], bf[nt]);
        }

        // K(jt+1) resident + all PV reads of Vs/Ss done before next iter writes
        if (more) CP_WAIT(0);
        __syncthreads();
    }

    // ---- finalize: O /= l, write av[(i*B + b)*D + n*64 + d] ----
#pragma unroll
    for (int mt = 0; mt < 2; mt++) {
        const int r = wm + mt * 16 + lr;
        const float inv0 = 1.f / l_s[r];
        const float inv1 = 1.f / l_s[r + 8];
#pragma unroll
        for (int nt = 0; nt < 2; nt++) {
            const int col = wn2 + nt * 8 + 2 * lc;
            float* p0 = av + ((size_t)(i0 + r) * BSZ + b) * DMODEL + n * DHEAD + col;
            *(float2*)p0 = make_float2(accO[mt][nt][0] * inv0, accO[mt][nt][1] * inv0);
            float* p1 = av + ((size_t)(i0 + r + 8) * BSZ + b) * DMODEL + n * DHEAD + col;
            *(float2*)p1 = make_float2(accO[mt][nt][2] * inv1, accO[mt][nt][3] * inv1);
        }
    }
}

// ----------------------------------------------------------------------------
// Row LayerNorm over D=1024 (one block per row, 4 elems/thread).
// ----------------------------------------------------------------------------
__device__ __forceinline__ float warpSum(float v) {
#pragma unroll
    for (int o = 16; o; o >>= 1) v += __shfl_xor_sync(0xffffffffu, v, o);
    return v;
}

__global__ __launch_bounds__(256) void ln_k(
    const float* __restrict__ X, const float* __restrict__ gam,
    const float* __restrict__ bet, float* __restrict__ Y)
{
    __shared__ float red[8];
    const size_t row = blockIdx.x;
    const int tid = threadIdx.x;
    const float4 v = *(const float4*)(X + row * DMODEL + tid * 4);
    float s = v.x + v.y + v.z + v.w;
    float q = v.x * v.x + v.y * v.y + v.z * v.z + v.w * v.w;

    float ws = warpSum(s);
    if ((tid & 31) == 0) red[tid >> 5] = ws;
    __syncthreads();
    if (tid < 32) {
        float t = (tid < 8) ? red[tid] : 0.f;
        t = warpSum(t);
        if (tid == 0) red[0] = t;
    }
    __syncthreads();
    const float mu = red[0] * (1.f / DMODEL);
    __syncthreads();

    float wq = warpSum(q);
    if ((tid & 31) == 0) red[tid >> 5] = wq;
    __syncthreads();
    if (tid < 32) {
        float t = (tid < 8) ? red[tid] : 0.f;
        t = warpSum(t);
        if (tid == 0) red[0] = t;
    }
    __syncthreads();
    const float var = red[0] * (1.f / DMODEL) - mu * mu;
    const float rs = rsqrtf(var + 1e-5f);

    const float4 gv = *(const float4*)(gam + tid * 4);
    const float4 bv = *(const float4*)(bet + tid * 4);
    float4 o;
    o.x = (v.x - mu) * rs * gv.x + bv.x;
    o.y = (v.y - mu) * rs * gv.y + bv.y;
    o.z = (v.z - mu) * rs * gv.z + bv.z;
    o.w = (v.w - mu) * rs * gv.w + bv.w;
    *(float4*)(Y + row * DMODEL + tid * 4) = o;
}

// ----------------------------------------------------------------------------
extern "C" void kernel_launch(void* const* d_in, const int* in_sizes, int n_in,
                              void* d_out, int out_size)
{
    (void)in_sizes; (void)n_in; (void)out_size;
    const float* w       = (const float*)d_in[0];
    const float* r       = (const float*)d_in[1];
    const float* mems    = (const float*)d_in[2];
    const float* qkv_w   = (const float*)d_in[3];
    const float* r_net_w = (const float*)d_in[4];
    const float* o_w     = (const float*)d_in[5];
    const float* rwb     = (const float*)d_in[6];
    const float* rrb     = (const float*)d_in[7];
    const float* ln1g    = (const float*)d_in[8];
    const float* ln1b    = (const float*)d_in[9];
    const float* ffw1    = (const float*)d_in[10];
    const float* ffb1    = (const float*)d_in[11];
    const float* ffw2    = (const float*)d_in[12];
    const float* ffb2    = (const float*)d_in[13];
    const float* ln2g    = (const float*)d_in[14];
    const float* ln2b    = (const float*)d_in[15];
    float* out = (float*)d_out;

    float *heads, *rk, *rbias, *av, *tmp, *out1, *ffh;
    __half* BD;
    cudaGetSymbolAddress((void**)&heads, g_heads);
    cudaGetSymbolAddress((void**)&rk,    g_rk);
    cudaGetSymbolAddress((void**)&rbias, g_rbias);
    cudaGetSymbolAddress((void**)&BD,    g_BD);
    cudaGetSymbolAddress((void**)&av,    g_av);
    cudaGetSymbolAddress((void**)&tmp,   g_tmp);
    cudaGetSymbolAddress((void**)&out1,  g_out1);
    cudaGetSymbolAddress((void**)&ffh,   g_ffh);

    static int s_attr_done = 0;
    if (!s_attr_done) {
        cudaFuncSetAttribute(flash_k, cudaFuncAttributeMaxDynamicSharedMemorySize,
                             FLASH_SMEM);
        s_attr_done = 1;
    }

    const dim3 blk(256);
    const int BIG = 1 << 30;
    const float* qbase = heads + (size_t)MEMLEN * BSZ * H3;  // query rows

    // 1) heads = concat(mems, w) @ qkv_w          [8192 x 3072 x 1024]
    gemm_f<<<dim3(H3 / 128, (KLEN * BSZ) / 128), blk>>>(
        mems, w, MEMLEN * BSZ, DMODEL, qkv_w, nullptr, nullptr, 0,
        heads, KLEN * BSZ, H3, DMODEL);

    // 2) rk = r @ r_net_w                          [2048 x 1024 x 1024]
    gemm_f<<<dim3(DMODEL / 128, KLEN / 128), blk>>>(
        r, r, BIG, DMODEL, r_net_w, nullptr, nullptr, 0,
        rk, KLEN, DMODEL, DMODEL);

    // 3) rbias[n][c] = rrb_n . rk_c
    rbias_k<<<(NHEAD * KLEN) / 256, blk>>>(rrb, rk, rbias);

    // 4) BD[bn][i][c] = q_i . rk_c + rbias         batched, fp16 out
    bd_gemm<<<dim3(KLEN / 128, QLEN / 128, BSZ * NHEAD), blk>>>(
        qbase, rk, rbias, BD);

    // 5) flash: AC + shifted-BD + mask + softmax + PV -> av
    flash_k<<<dim3(QLEN / 128, BSZ * NHEAD), dim3(512), FLASH_SMEM>>>(heads, BD, rwb, av);

    // 6) attn_out = av @ o_w + w (residual)        [4096 x 1024 x 1024]
    gemm_f<<<dim3(DMODEL / 128, (QLEN * BSZ) / 128), blk>>>(
        av, av, BIG, DMODEL, o_w, nullptr, w, 0,
        tmp, QLEN * BSZ, DMODEL, DMODEL);

    // 7) LN1
    ln_k<<<QLEN * BSZ, blk>>>(tmp, ln1g, ln1b, out1);

    // 8) ffh = relu(out1 @ ff_w1 + b1)             [4096 x 4096 x 1024]
    gemm_f<<<dim3(DINNER / 128, (QLEN * BSZ) / 128), blk>>>(
        out1, out1, BIG, DMODEL, ffw1, ffb1, nullptr, 1,
        ffh, QLEN * BSZ, DINNER, DMODEL);

    // 9) tmp = ffh @ ff_w2 + b2 + out1             [4096 x 1024 x 4096]
    gemm_f<<<dim3(DMODEL / 128, (QLEN * BSZ) / 128), blk>>>(
        ffh, ffh, BIG, DINNER, ffw2, ffb2, out1, 0,
        tmp, QLEN * BSZ, DMODEL, DINNER);

    // 10) LN2 -> output
    ln_k<<<QLEN * BSZ, blk>>>(tmp, ln2g, ln2b, out);
}

// round 9
// speedup vs baseline: 1.9114x; 1.3263x over previous
#include <cuda_runtime.h>
#include <cuda_fp16.h>
#include <math.h>
#include <stdint.h>

#define QLEN   1024
#define BSZ    4
#define DMODEL 1024
#define NHEAD  16
#define DHEAD  64
#define DINNER 4096
#define MEMLEN 1024
#define KLEN   2048
#define H3     (3 * DMODEL)   // 3072
#define QK     ((long long)QLEN * KLEN)

// ---- static device scratch (no cudaMalloc allowed) ----
__device__ float  g_heads[(size_t)KLEN * BSZ * H3];          // 8192 x 3072 (fp32)
__device__ float  g_rk[(size_t)KLEN * DMODEL];               // 2048 x 1024
__device__ float  g_rbias[(size_t)NHEAD * KLEN];             // rrb . rk
__device__ __half g_BD[(size_t)BSZ * NHEAD * QLEN * KLEN];   // fp16 BD_pre
__device__ __half g_av16[(size_t)QLEN * BSZ * DMODEL];       // flash out (fp16)
__device__ float  g_tmp[(size_t)QLEN * BSZ * DMODEL];
__device__ float  g_out1[(size_t)QLEN * BSZ * DMODEL];
__device__ __half g_out116[(size_t)QLEN * BSZ * DMODEL];
__device__ __half g_ffh16[(size_t)QLEN * BSZ * DINNER];      // 4096 x 4096 fp16
// fp16 inputs/weights (converted per launch)
__device__ __half g_cat16[(size_t)KLEN * BSZ * DMODEL];      // concat(mems,w)
__device__ __half g_r16[(size_t)KLEN * DMODEL];
__device__ __half g_qkvw16[(size_t)DMODEL * H3];
__device__ __half g_rnw16[(size_t)DMODEL * DMODEL];
__device__ __half g_ow16[(size_t)DMODEL * DMODEL];
__device__ __half g_ffw116[(size_t)DMODEL * DINNER];
__device__ __half g_ffw216[(size_t)DINNER * DMODEL];

__device__ __forceinline__ uint32_t f2tf32(float x) {
    uint32_t u;
    asm("cvt.rna.tf32.f32 %0, %1;" : "=r"(u) : "f"(x));
    return u;
}
__device__ __forceinline__ void cpa16(uint32_t s, const void* g) {
    asm volatile("cp.async.cg.shared.global [%0], [%1], 16;" :: "r"(s), "l"(g));
}
#define CP_COMMIT() asm volatile("cp.async.commit_group;")
#define CP_WAIT(N)  asm volatile("cp.async.wait_group %0;" :: "n"(N))
#define RN(x) ((x) + 0x1000u)

#define MMA_TF32(acc, av, bv)                                               \
    asm volatile(                                                           \
        "mma.sync.aligned.m16n8k8.row.col.f32.tf32.tf32.f32 "               \
        "{%0,%1,%2,%3}, {%4,%5,%6,%7}, {%8,%9}, {%0,%1,%2,%3};"             \
        : "+f"(acc[0]), "+f"(acc[1]), "+f"(acc[2]), "+f"(acc[3])            \
        : "r"(av[0]), "r"(av[1]), "r"(av[2]), "r"(av[3]),                   \
          "r"(bv[0]), "r"(bv[1]))

#define MMA_F16(acc, av, bv)                                                \
    asm volatile(                                                           \
        "mma.sync.aligned.m16n8k16.row.col.f32.f16.f16.f32 "                \
        "{%0,%1,%2,%3}, {%4,%5,%6,%7}, {%8,%9}, {%0,%1,%2,%3};"             \
        : "+f"(acc[0]), "+f"(acc[1]), "+f"(acc[2]), "+f"(acc[3])            \
        : "r"(av[0]), "r"(av[1]), "r"(av[2]), "r"(av[3]),                   \
          "r"(bv[0]), "r"(bv[1]))

#define LDSM_X4(r0, r1, r2, r3, addr)                                       \
    asm volatile("ldmatrix.sync.aligned.m8n8.x4.shared.b16 {%0,%1,%2,%3}, [%4];" \
        : "=r"(r0), "=r"(r1), "=r"(r2), "=r"(r3) : "r"(addr))
#define LDSM_X4T(r0, r1, r2, r3, addr)                                      \
    asm volatile("ldmatrix.sync.aligned.m8n8.x4.trans.shared.b16 {%0,%1,%2,%3}, [%4];" \
        : "=r"(r0), "=r"(r1), "=r"(r2), "=r"(r3) : "r"(addr))

// ----------------------------------------------------------------------------
// fp32 -> fp16 conversion (8 elems/thread)
// ----------------------------------------------------------------------------
__global__ __launch_bounds__(256) void cvt_k(
    const float* __restrict__ src, __half* __restrict__ dst)
{
    const int i = (blockIdx.x * 256 + threadIdx.x) * 8;
    const float4 a = *(const float4*)(src + i);
    const float4 b = *(const float4*)(src + i + 4);
    __half2 h[4];
    h[0] = __floats2half2_rn(a.x, a.y);
    h[1] = __floats2half2_rn(a.z, a.w);
    h[2] = __floats2half2_rn(b.x, b.y);
    h[3] = __floats2half2_rn(b.z, b.w);
    *(uint4*)(dst + i) = *(uint4*)h;
}

// ----------------------------------------------------------------------------
// Dense fp16 tensor-core GEMM: C[M,N](+bias)(+resid)(relu) = A16 @ B16.
// 3-stage cp.async, 128x128x32 tiles, 256 threads, ldmatrix fragments.
// HOUT=1: fp16-only output. HOUT=0: fp32 output.
// ----------------------------------------------------------------------------
#define ASTR 40    // A smem stride in halves (32k + 8 pad)
#define BSTR 136   // B smem stride in halves (128n + 8 pad)

template <int HOUT>
__global__ __launch_bounds__(256, 2) void gemm_h(
    const __half* __restrict__ A, int lda,
    const __half* __restrict__ B,
    const float* __restrict__ bias, const float* __restrict__ resid, int doRelu,
    void* __restrict__ Cv, int M, int N, int Kd)
{
    __shared__ __half As[3][128 * ASTR];
    __shared__ __half Bs[3][32 * BSTR];

    const int tid  = threadIdx.x;
    const int warp = tid >> 5, lane = tid & 31;
    const int lr = lane >> 2, lc = lane & 3;
    const int bm = blockIdx.y * 128, bn = blockIdx.x * 128;
    const int wm = (warp & 1) * 64;
    const int wn = (warp >> 1) * 32;

    float acc[4][4][4];
#pragma unroll
    for (int mt = 0; mt < 4; mt++)
#pragma unroll
        for (int nt = 0; nt < 4; nt++)
#pragma unroll
            for (int q = 0; q < 4; q++) acc[mt][nt][q] = 0.f;

    // loader geometry: A 128 rows x 32 halves (4 chunks of 8 halves per row),
    // B 32 rows x 128 halves (16 chunks per row). 512 chunks each, 2/thread.
    const __half* aPtr[2];
    const __half* bPtr[2];
    uint32_t aDst[2], bDst[2];
#pragma unroll
    for (int h = 0; h < 2; h++) {
        const int ch = tid + h * 256;
        const int ar = ch >> 2, ao = (ch & 3) * 8;
        aPtr[h] = A + (long long)(bm + ar) * lda + ao;
        aDst[h] = (uint32_t)__cvta_generic_to_shared(&As[0][ar * ASTR + ao]);
        const int br = ch >> 4, bo = (ch & 15) * 8;
        bPtr[h] = B + (long long)br * N + bn + bo;
        bDst[h] = (uint32_t)__cvta_generic_to_shared(&Bs[0][br * BSTR + bo]);
    }
    const long long bStep = (long long)32 * N;

    auto load = [&](int kt, int s) {
#pragma unroll
        for (int h = 0; h < 2; h++)
            cpa16(aDst[h] + s * 128 * ASTR * 2, aPtr[h] + kt * 32);
#pragma unroll
        for (int h = 0; h < 2; h++)
            cpa16(bDst[h] + s * 32 * BSTR * 2, bPtr[h] + kt * bStep);
    };

    // ldmatrix per-thread address components
    const int aRow = lane & 15;                 // row within 16-row tile
    const int selOff = (lane >> 4) << 3;        // 0 or 8 (second k/n half)
    const uint32_t asBase = (uint32_t)__cvta_generic_to_shared(&As[0][0]);
    const uint32_t bsBase = (uint32_t)__cvta_generic_to_shared(&Bs[0][0]);

    const int nk = Kd >> 5;
    load(0, 0); CP_COMMIT();
    load(1, 1); CP_COMMIT();

    for (int kt = 0; kt < nk; kt++) {
        const int s = kt % 3;
        CP_WAIT(1);
        __syncthreads();
        if (kt + 2 < nk) load(kt + 2, (kt + 2) % 3);
        CP_COMMIT();

        const uint32_t aS = asBase + (uint32_t)(s * 128 * ASTR * 2);
        const uint32_t bS = bsBase + (uint32_t)(s * 32 * BSTR * 2);
#pragma unroll
        for (int kk = 0; kk < 32; kk += 16) {
            uint32_t af[4][4], bf[4][2];
#pragma unroll
            for (int mt = 0; mt < 4; mt++) {
                const uint32_t addr = aS +
                    (uint32_t)(((wm + mt * 16 + aRow) * ASTR + kk + selOff) * 2);
                LDSM_X4(af[mt][0], af[mt][1], af[mt][2], af[mt][3], addr);
            }
#pragma unroll
            for (int ntp = 0; ntp < 2; ntp++) {
                const uint32_t addr = bS +
                    (uint32_t)(((kk + aRow) * BSTR + wn + ntp * 16 + selOff) * 2);
                LDSM_X4T(bf[2 * ntp][0], bf[2 * ntp][1],
                         bf[2 * ntp + 1][0], bf[2 * ntp + 1][1], addr);
            }
#pragma unroll
            for (int mt = 0; mt < 4; mt++)
#pragma unroll
                for (int nt = 0; nt < 4; nt++)
                    MMA_F16(acc[mt][nt], af[mt], bf[nt]);
        }
    }

    // epilogue
#pragma unroll
    for (int mt = 0; mt < 4; mt++) {
#pragma unroll
        for (int nt = 0; nt < 4; nt++) {
            const int col = bn + wn + nt * 8 + lc * 2;
#pragma unroll
            for (int half = 0; half < 2; half++) {
                const int row = bm + wm + mt * 16 + lr + half * 8;
                float v0 = acc[mt][nt][half * 2 + 0];
                float v1 = acc[mt][nt][half * 2 + 1];
                if (bias) { v0 += bias[col]; v1 += bias[col + 1]; }
                if (resid) {
                    const float* rp = resid + (long long)row * N + col;
                    v0 += rp[0]; v1 += rp[1];
                }
                if (doRelu) { v0 = fmaxf(v0, 0.f); v1 = fmaxf(v1, 0.f); }
                if (HOUT) {
                    *(__half2*)((__half*)Cv + (long long)row * N + col) =
                        __floats2half2_rn(v0, v1);
                } else {
                    float* cp = (float*)Cv + (long long)row * N + col;
                    cp[0] = v0; cp[1] = v1;
                }
            }
        }
    }
}

// ----------------------------------------------------------------------------
// rbias[n][c] = rrb_n . rk_c
// ----------------------------------------------------------------------------
__global__ __launch_bounds__(256) void rbias_k(
    const float* __restrict__ rrb, const float* __restrict__ rk,
    float* __restrict__ rbias)
{
    const int idx = blockIdx.x * 256 + threadIdx.x;
    const int c = idx >> 4, n = idx & 15;
    const float* rp = rk + (size_t)c * DMODEL + n * DHEAD;
    const float* bp = rrb + n * DHEAD;
    float s = 0.f;
#pragma unroll
    for (int d = 0; d < DHEAD; d++) s += rp[d] * bp[d];
    rbias[n * KLEN + c] = s;
}

// ----------------------------------------------------------------------------
// BD GEMM (tf32, proven): BD[bn][i][c] = q_i . rk_c (+rbias), fp16 out.
// ----------------------------------------------------------------------------
__global__ __launch_bounds__(256, 2) void bd_gemm(
    const float* __restrict__ Q, const float* __restrict__ RK,
    const float* __restrict__ rbias, __half* __restrict__ BD)
{
    __shared__ uint32_t As[3][2560];
    __shared__ uint32_t Bs[3][2560];

    const int tid = threadIdx.x;
    const int warp = tid >> 5, lane = tid & 31;
    const int lr = lane >> 2, lc = lane & 3;
    const int bm = blockIdx.y * 128, bn = blockIdx.x * 128;
    if (bm + bn < 769) return;
    const int bnidx = blockIdx.z;
    const int b = bnidx >> 4, n = bnidx & 15;
    const int wm = (warp & 1) * 64;
    const int wn = (warp >> 1) * 32;

    float acc[4][4][4];
#pragma unroll
    for (int mt = 0; mt < 4; mt++)
#pragma unroll
        for (int nt = 0; nt < 4; nt++)
#pragma unroll
            for (int q = 0; q < 4; q++) acc[mt][nt][q] = 0.f;

    const float* aPtr[2];
    const float* bPtr[2];
    uint32_t aDst[2], bDst[2];
#pragma unroll
    for (int h = 0; h < 2; h++) {
        const int ch = tid + h * 256;
        const int row = ch >> 2, kc = (ch & 3) * 4;
        aPtr[h] = Q + (size_t)(bm + row) * (BSZ * H3) + (size_t)b * H3 + n * DHEAD + kc;
        aDst[h] = (uint32_t)__cvta_generic_to_shared(&As[0][row * 20 + kc]);
        bPtr[h] = RK + (size_t)(bn + row) * DMODEL + n * DHEAD + kc;
        bDst[h] = (uint32_t)__cvta_generic_to_shared(&Bs[0][row * 20 + kc]);
    }

    auto load = [&](int kt, int s) {
#pragma unroll
        for (int h = 0; h < 2; h++)
            cpa16(aDst[h] + s * 2560 * 4, aPtr[h] + kt * 16);
#pragma unroll
        for (int h = 0; h < 2; h++)
            cpa16(bDst[h] + s * 2560 * 4, bPtr[h] + kt * 16);
    };

    const int nk = 4;
    load(0, 0); CP_COMMIT();
    load(1, 1); CP_COMMIT();

    for (int kt = 0; kt < nk; kt++) {
        const int s = kt % 3;
        CP_WAIT(1);
        __syncthreads();
        if (kt + 2 < nk) load(kt + 2, (kt + 2) % 3);
        CP_COMMIT();

#pragma unroll
        for (int kk = 0; kk < 16; kk += 8) {
            uint32_t af[4][4], bf[4][2];
#pragma unroll
            for (int mt = 0; mt < 4; mt++) {
                const int m0 = wm + mt * 16 + lr;
                af[mt][0] = RN(As[s][m0 * 20 + kk + lc]);
                af[mt][1] = RN(As[s][(m0 + 8) * 20 + kk + lc]);
                af[mt][2] = RN(As[s][m0 * 20 + kk + 4 + lc]);
                af[mt][3] = RN(As[s][(m0 + 8) * 20 + kk + 4 + lc]);
            }
#pragma unroll
            for (int nt = 0; nt < 4; nt++) {
                const int n0 = wn + nt * 8 + lr;
                bf[nt][0] = RN(Bs[s][n0 * 20 + kk + lc]);
                bf[nt][1] = RN(Bs[s][n0 * 20 + kk + 4 + lc]);
            }
#pragma unroll
            for (int mt = 0; mt < 4; mt++)
#pragma unroll
                for (int nt = 0; nt < 4; nt++)
                    MMA_TF32(acc[mt][nt], af[mt], bf[nt]);
        }
    }

#pragma unroll
    for (int mt = 0; mt < 4; mt++) {
#pragma unroll
        for (int nt = 0; nt < 4; nt++) {
            const int col = bn + wn + nt * 8 + lc * 2;
            const float rb0 = rbias[n * KLEN + col];
            const float rb1 = rbias[n * KLEN + col + 1];
#pragma unroll
            for (int half = 0; half < 2; half++) {
                const int row = bm + wm + mt * 16 + lr + half * 8;
                const float v0 = acc[mt][nt][half * 2 + 0] + rb0;
                const float v1 = acc[mt][nt][half * 2 + 1] + rb1;
                __half2* cp = (__half2*)(BD + ((size_t)bnidx * QLEN + row) * KLEN + col);
                *cp = __floats2half2_rn(v0, v1);
            }
        }
    }
}

// ----------------------------------------------------------------------------
// Flash attention (proven): 512 threads, cp.async K/V, fp16 BD, fp16 av out.
// ----------------------------------------------------------------------------
#define QSS 68
#define SSS 132
#define FLASH_SMEM ((128 * QSS + 2 * 128 * QSS + 128 * QSS + 128 * SSS + 3 * 128) * 4)

__global__ __launch_bounds__(512, 1) void flash_k(
    const float* __restrict__ heads, const __half* __restrict__ BD,
    const float* __restrict__ rwb, __half* __restrict__ av16)
{
    extern __shared__ float sm[];
    float* Qs  = sm;
    float* Ks  = Qs + 128 * QSS;
    float* Vs  = Ks + 2 * 128 * QSS;
    float* Ss  = Vs + 128 * QSS;
    float* m_s = Ss + 128 * SSS;
    float* l_s = m_s + 128;
    float* sc_s = l_s + 128;
    uint32_t* Qsu = (uint32_t*)Qs;
    uint32_t* Ksu = (uint32_t*)Ks;
    uint32_t* Vsu = (uint32_t*)Vs;
    uint32_t* Ssu = (uint32_t*)Ss;
    const uint32_t ks_base = (uint32_t)__cvta_generic_to_shared(Ks);
    const uint32_t vs_base = (uint32_t)__cvta_generic_to_shared(Vs);

    const int tid = threadIdx.x;
    const int warp = tid >> 5, lane = tid & 31;
    const int lr = lane >> 2, lc = lane & 3;
    const int qt = (int)gridDim.x - 1 - (int)blockIdx.x;
    const int i0 = qt * 128;
    const int bn = blockIdx.y;
    const int b = bn >> 4, n = bn & 15;
    const int wm  = (warp & 3) * 32;
    const int wn  = (warp >> 2) * 32;
    const int wn2 = (warp >> 2) * 16;
    const int njt = qt + 9;

    auto loadK = [&](int jt, int buf) {
        const int j0 = jt * 128;
#pragma unroll
        for (int it = 0; it < 4; it++) {
            const int c = tid + it * 512;
            const int row = c >> 4, seg = (c & 15) << 2;
            const float* g = heads + ((size_t)(j0 + row) * BSZ + b) * H3 + DMODEL + n * DHEAD + seg;
            cpa16(ks_base + (uint32_t)((((buf << 7) + row) * QSS + seg) << 2), g);
        }
        CP_COMMIT();
    };
    auto loadV = [&](int jt) {
        const int j0 = jt * 128;
#pragma unroll
        for (int it = 0; it < 4; it++) {
            const int c = tid + it * 512;
            const int row = c >> 4, seg = (c & 15) << 2;
            const float* g = heads + ((size_t)(j0 + row) * BSZ + b) * H3 + 2 * DMODEL + n * DHEAD + seg;
            cpa16(vs_base + (uint32_t)((row * QSS + seg) << 2), g);
        }
        CP_COMMIT();
    };

    loadK(0, 0);
    const float* qbase = heads + (size_t)MEMLEN * BSZ * H3;
#pragma unroll
    for (int it = 0; it < 4; it++) {
        const int idx = tid + it * 512;
        const int row = idx >> 4, c4 = (idx & 15) * 4;
        float4 v = *(const float4*)(qbase + ((size_t)(i0 + row) * BSZ + b) * H3 + n * DHEAD + c4);
        const float4 bb = *(const float4*)(rwb + n * DHEAD + c4);
        uint32_t* d = &Qsu[row * QSS + c4];
        d[0] = f2tf32(v.x + bb.x); d[1] = f2tf32(v.y + bb.y);
        d[2] = f2tf32(v.z + bb.z); d[3] = f2tf32(v.w + bb.w);
    }
    if (tid < 128) { m_s[tid] = -1e30f; l_s[tid] = 0.f; }

    float accO[2][2][4];
#pragma unroll
    for (int mt = 0; mt < 2; mt++)
#pragma unroll
        for (int nt = 0; nt < 2; nt++)
#pragma unroll
            for (int q = 0; q < 4; q++) accO[mt][nt][q] = 0.f;

    CP_WAIT(0);
    __syncthreads();

    for (int jt = 0; jt < njt; jt++) {
        const int j0 = jt * 128;
        const int cur = jt & 1;
        const bool more = (jt + 1 < njt);

        loadV(jt);
        if (more) loadK(jt + 1, cur ^ 1);

        float accS[2][4][4];
#pragma unroll
        for (int mt = 0; mt < 2; mt++)
#pragma unroll
            for (int nt = 0; nt < 4; nt++)
#pragma unroll
                for (int q = 0; q < 4; q++) accS[mt][nt][q] = 0.f;

#pragma unroll
        for (int kk = 0; kk < 64; kk += 8) {
            uint32_t af[2][4], bf[4][2];
#pragma unroll
            for (int mt = 0; mt < 2; mt++) {
                const int m0 = wm + mt * 16 + lr;
                af[mt][0] = Qsu[m0 * QSS + kk + lc];
                af[mt][1] = Qsu[(m0 + 8) * QSS + kk + lc];
                af[mt][2] = Qsu[m0 * QSS + kk + 4 + lc];
                af[mt][3] = Qsu[(m0 + 8) * QSS + kk + 4 + lc];
            }
#pragma unroll
            for (int nt = 0; nt < 4; nt++) {
                const int n0 = (cur << 7) + wn + nt * 8 + lr;
                bf[nt][0] = RN(Ksu[n0 * QSS + kk + lc]);
                bf[nt][1] = RN(Ksu[n0 * QSS + kk + 4 + lc]);
            }
#pragma unroll
            for (int mt = 0; mt < 2; mt++)
#pragma unroll
                for (int nt = 0; nt < 4; nt++)
                    MMA_TF32(accS[mt][nt], af[mt], bf[nt]);
        }

#pragma unroll
        for (int mt = 0; mt < 2; mt++) {
            const int r0 = wm + mt * 16 + lr;
#pragma unroll
            for (int nt = 0; nt < 4; nt++) {
                const int col = wn + nt * 8 + 2 * lc;
                *(float2*)&Ss[r0 * SSS + col] =
                    make_float2(accS[mt][nt][0], accS[mt][nt][1]);
                *(float2*)&Ss[(r0 + 8) * SSS + col] =
                    make_float2(accS[mt][nt][2], accS[mt][nt][3]);
            }
        }
        __syncthreads();

#pragma unroll 2
        for (int rr = 0; rr < 8; rr++) {
            const int row = warp * 8 + rr;
            const int i = i0 + row;
            const __half* bdp = BD + ((size_t)bn * QLEN + i) * KLEN + (j0 - i + QLEN - 1);
            const int vmax = i + MEMLEN - j0;
            float sv[4];
            float mloc = -1e30f;
#pragma unroll
            for (int k2 = 0; k2 < 4; k2++) {
                const int c = lane + 32 * k2;
                float s = -1e30f;
                if (c <= vmax) s = (Ss[row * SSS + c] + __half2float(__ldg(bdp + c))) * 0.125f;
                sv[k2] = s;
                mloc = fmaxf(mloc, s);
            }
#pragma unroll
            for (int o = 16; o; o >>= 1)
                mloc = fmaxf(mloc, __shfl_xor_sync(0xffffffffu, mloc, o));
            const float mo = m_s[row];
            const float nm = fmaxf(mo, mloc);
            float lsum = 0.f;
#pragma unroll
            for (int k2 = 0; k2 < 4; k2++) {
                const int c = lane + 32 * k2;
                float p = __expf(sv[k2] - nm);
                const uint32_t pb = __float_as_uint(p) & 0xFFFFE000u;
                const float pt = __uint_as_float(pb);
                lsum += pt;
                Ssu[row * SSS + c] = pb;
            }
#pragma unroll
            for (int o = 16; o; o >>= 1)
                lsum += __shfl_xor_sync(0xffffffffu, lsum, o);
            if (lane == 0) {
                const float alpha = __expf(mo - nm);
                m_s[row] = nm;
                l_s[row] = l_s[row] * alpha + lsum;
                sc_s[row] = alpha;
            }
        }

        if (more) { CP_WAIT(1); } else { CP_WAIT(0); }
        __syncthreads();

#pragma unroll
        for (int mt = 0; mt < 2; mt++) {
            const int r = wm + mt * 16 + lr;
            const float s0 = sc_s[r], s1 = sc_s[r + 8];
#pragma unroll
            for (int nt = 0; nt < 2; nt++) {
                accO[mt][nt][0] *= s0; accO[mt][nt][1] *= s0;
                accO[mt][nt][2] *= s1; accO[mt][nt][3] *= s1;
            }
        }
#pragma unroll
        for (int jj = 0; jj < 128; jj += 8) {
            uint32_t af[2][4], bf[2][2];
#pragma unroll
            for (int mt = 0; mt < 2; mt++) {
                const int m0 = wm + mt * 16 + lr;
                af[mt][0] = Ssu[m0 * SSS + jj + lc];
                af[mt][1] = Ssu[(m0 + 8) * SSS + jj + lc];
                af[mt][2] = Ssu[m0 * SSS + jj + 4 + lc];
                af[mt][3] = Ssu[(m0 + 8) * SSS + jj + 4 + lc];
            }
#pragma unroll
            for (int nt = 0; nt < 2; nt++) {
                const int n0 = wn2 + nt * 8 + lr;
                bf[nt][0] = RN(Vsu[(jj + lc) * QSS + n0]);
                bf[nt][1] = RN(Vsu[(jj + 4 + lc) * QSS + n0]);
            }
#pragma unroll
            for (int mt = 0; mt < 2; mt++)
#pragma unroll
                for (int nt = 0; nt < 2; nt++)
                    MMA_TF32(accO[mt][nt], af[mt], bf[nt]);
        }

        if (more) CP_WAIT(0);
        __syncthreads();
    }

    // finalize: O /= l, write fp16 av
#pragma unroll
    for (int mt = 0; mt < 2; mt++) {
        const int r = wm + mt * 16 + lr;
        const float inv0 = 1.f / l_s[r];
        const float inv1 = 1.f / l_s[r + 8];
#pragma unroll
        for (int nt = 0; nt < 2; nt++) {
            const int col = wn2 + nt * 8 + 2 * lc;
            __half2* p0 = (__half2*)(av16 + ((size_t)(i0 + r) * BSZ + b) * DMODEL + n * DHEAD + col);
            *p0 = __floats2half2_rn(accO[mt][nt][0] * inv0, accO[mt][nt][1] * inv0);
            __half2* p1 = (__half2*)(av16 + ((size_t)(i0 + r + 8) * BSZ + b) * DMODEL + n * DHEAD + col);
            *p1 = __floats2half2_rn(accO[mt][nt][2] * inv1, accO[mt][nt][3] * inv1);
        }
    }
}

// ----------------------------------------------------------------------------
// Row LayerNorm over D=1024; optional fp16 dual output.
// ----------------------------------------------------------------------------
__device__ __forceinline__ float warpSum(float v) {
#pragma unroll
    for (int o = 16; o; o >>= 1) v += __shfl_xor_sync(0xffffffffu, v, o);
    return v;
}

__global__ __launch_bounds__(256) void ln_k(
    const float* __restrict__ X, const float* __restrict__ gam,
    const float* __restrict__ bet, float* __restrict__ Y,
    __half* __restrict__ Y16)
{
    __shared__ float red[8];
    const size_t row = blockIdx.x;
    const int tid = threadIdx.x;
    const float4 v = *(const float4*)(X + row * DMODEL + tid * 4);
    float s = v.x + v.y + v.z + v.w;
    float q = v.x * v.x + v.y * v.y + v.z * v.z + v.w * v.w;

    float ws = warpSum(s);
    if ((tid & 31) == 0) red[tid >> 5] = ws;
    __syncthreads();
    if (tid < 32) {
        float t = (tid < 8) ? red[tid] : 0.f;
        t = warpSum(t);
        if (tid == 0) red[0] = t;
    }
    __syncthreads();
    const float mu = red[0] * (1.f / DMODEL);
    __syncthreads();

    float wq = warpSum(q);
    if ((tid & 31) == 0) red[tid >> 5] = wq;
    __syncthreads();
    if (tid < 32) {
        float t = (tid < 8) ? red[tid] : 0.f;
        t = warpSum(t);
        if (tid == 0) red[0] = t;
    }
    __syncthreads();
    const float var = red[0] * (1.f / DMODEL) - mu * mu;
    const float rs = rsqrtf(var + 1e-5f);

    const float4 gv = *(const float4*)(gam + tid * 4);
    const float4 bv = *(const float4*)(bet + tid * 4);
    float4 o;
    o.x = (v.x - mu) * rs * gv.x + bv.x;
    o.y = (v.y - mu) * rs * gv.y + bv.y;
    o.z = (v.z - mu) * rs * gv.z + bv.z;
    o.w = (v.w - mu) * rs * gv.w + bv.w;
    *(float4*)(Y + row * DMODEL + tid * 4) = o;
    if (Y16) {
        __half2 h[2] = { __floats2half2_rn(o.x, o.y), __floats2half2_rn(o.z, o.w) };
        *(uint2*)(Y16 + row * DMODEL + tid * 4) = *(uint2*)h;
    }
}

// ----------------------------------------------------------------------------
extern "C" void kernel_launch(void* const* d_in, const int* in_sizes, int n_in,
                              void* d_out, int out_size)
{
    (void)in_sizes; (void)n_in; (void)out_size;
    const float* w       = (const float*)d_in[0];
    const float* r       = (const float*)d_in[1];
    const float* mems    = (const float*)d_in[2];
    const float* qkv_w   = (const float*)d_in[3];
    const float* r_net_w = (const float*)d_in[4];
    const float* o_w     = (const float*)d_in[5];
    const float* rwb     = (const float*)d_in[6];
    const float* rrb     = (const float*)d_in[7];
    const float* ln1g    = (const float*)d_in[8];
    const float* ln1b    = (const float*)d_in[9];
    const float* ffw1    = (const float*)d_in[10];
    const float* ffb1    = (const float*)d_in[11];
    const float* ffw2    = (const float*)d_in[12];
    const float* ffb2    = (const float*)d_in[13];
    const float* ln2g    = (const float*)d_in[14];
    const float* ln2b    = (const float*)d_in[15];
    float* out = (float*)d_out;

    float *heads, *rk, *rbias, *tmp, *out1;
    __half *BD, *av16, *out116, *ffh16;
    __half *cat16, *r16, *qkvw16, *rnw16, *ow16, *ffw116, *ffw216;
    cudaGetSymbolAddress((void**)&heads,  g_heads);
    cudaGetSymbolAddress((void**)&rk,     g_rk);
    cudaGetSymbolAddress((void**)&rbias,  g_rbias);
    cudaGetSymbolAddress((void**)&BD,     g_BD);
    cudaGetSymbolAddress((void**)&av16,   g_av16);
    cudaGetSymbolAddress((void**)&tmp,    g_tmp);
    cudaGetSymbolAddress((void**)&out1,   g_out1);
    cudaGetSymbolAddress((void**)&out116, g_out116);
    cudaGetSymbolAddress((void**)&ffh16,  g_ffh16);
    cudaGetSymbolAddress((void**)&cat16,  g_cat16);
    cudaGetSymbolAddress((void**)&r16,    g_r16);
    cudaGetSymbolAddress((void**)&qkvw16, g_qkvw16);
    cudaGetSymbolAddress((void**)&rnw16,  g_rnw16);
    cudaGetSymbolAddress((void**)&ow16,   g_ow16);
    cudaGetSymbolAddress((void**)&ffw116, g_ffw116);
    cudaGetSymbolAddress((void**)&ffw216, g_ffw216);

    static int s_attr_done = 0;
    if (!s_attr_done) {
        cudaFuncSetAttribute(flash_k, cudaFuncAttributeMaxDynamicSharedMemorySize,
                             FLASH_SMEM);
        s_attr_done = 1;
    }

    const dim3 blk(256);
    const float* qbase = heads + (size_t)MEMLEN * BSZ * H3;

    // 0) fp32 -> fp16 conversions (inputs + weights)
    cvt_k<<<(MEMLEN * BSZ * DMODEL) / 2048, blk>>>(mems, cat16);
    cvt_k<<<(QLEN * BSZ * DMODEL) / 2048, blk>>>(w, cat16 + (size_t)MEMLEN * BSZ * DMODEL);
    cvt_k<<<(KLEN * DMODEL) / 2048, blk>>>(r, r16);
    cvt_k<<<(DMODEL * H3) / 2048, blk>>>(qkv_w, qkvw16);
    cvt_k<<<(DMODEL * DMODEL) / 2048, blk>>>(r_net_w, rnw16);
    cvt_k<<<(DMODEL * DMODEL) / 2048, blk>>>(o_w, ow16);
    cvt_k<<<(DMODEL * DINNER) / 2048, blk>>>(ffw1, ffw116);
    cvt_k<<<(DINNER * DMODEL) / 2048, blk>>>(ffw2, ffw216);

    // 1) heads = cat16 @ qkvw16                   [8192 x 3072 x 1024] fp32 out
    gemm_h<0><<<dim3(H3 / 128, (KLEN * BSZ) / 128), blk>>>(
        cat16, DMODEL, qkvw16, nullptr, nullptr, 0,
        heads, KLEN * BSZ, H3, DMODEL);

    // 2) rk = r16 @ rnw16                          [2048 x 1024 x 1024] fp32 out
    gemm_h<0><<<dim3(DMODEL / 128, KLEN / 128), blk>>>(
        r16, DMODEL, rnw16, nullptr, nullptr, 0,
        rk, KLEN, DMODEL, DMODEL);

    // 3) rbias
    rbias_k<<<(NHEAD * KLEN) / 256, blk>>>(rrb, rk, rbias);

    // 4) BD (tf32, fp16 out, diag skip)
    bd_gemm<<<dim3(KLEN / 128, QLEN / 128, BSZ * NHEAD), blk>>>(
        qbase, rk, rbias, BD);

    // 5) flash -> av16 (fp16)
    flash_k<<<dim3(QLEN / 128, BSZ * NHEAD), dim3(512), FLASH_SMEM>>>(heads, BD, rwb, av16);

    // 6) attn_out = av16 @ ow16 + w                [4096 x 1024 x 1024]
    gemm_h<0><<<dim3(DMODEL / 128, (QLEN * BSZ) / 128), blk>>>(
        av16, DMODEL, ow16, nullptr, w, 0,
        tmp, QLEN * BSZ, DMODEL, DMODEL);

    // 7) LN1 (dual fp32 + fp16)
    ln_k<<<QLEN * BSZ, blk>>>(tmp, ln1g, ln1b, out1, out116);

    // 8) ffh16 = relu(out116 @ ffw116 + b1)        [4096 x 4096 x 1024] fp16 out
    gemm_h<1><<<dim3(DINNER / 128, (QLEN * BSZ) / 128), blk>>>(
        out116, DMODEL, ffw116, ffb1, nullptr, 1,
        ffh16, QLEN * BSZ, DINNER, DMODEL);

    // 9) tmp = ffh16 @ ffw216 + b2 + out1          [4096 x 1024 x 4096]
    gemm_h<0><<<dim3(DMODEL / 128, (QLEN * BSZ) / 128), blk>>>(
        ffh16, DINNER, ffw216, ffb2, out1, 0,
        tmp, QLEN * BSZ, DMODEL, DINNER);

    // 10) LN2 -> output
    ln_k<<<QLEN * BSZ, blk>>>(tmp, ln2g, ln2b, out, nullptr);
}

// round 10
// speedup vs baseline: 2.1693x; 1.1350x over previous
#include <cuda_runtime.h>
#include <cuda_fp16.h>
#include <math.h>
#include <stdint.h>

#define QLEN   1024
#define BSZ    4
#define DMODEL 1024
#define NHEAD  16
#define DHEAD  64
#define DINNER 4096
#define MEMLEN 1024
#define KLEN   2048
#define H3     (3 * DMODEL)   // 3072
#define QK     ((long long)QLEN * KLEN)

// ---- static device scratch (no cudaMalloc allowed) ----
__device__ float  g_heads[(size_t)KLEN * BSZ * H3];          // fp32 (Q third valid)
__device__ __half g_heads16[(size_t)KLEN * BSZ * H3];        // fp16 full
__device__ float  g_rk[(size_t)KLEN * DMODEL];
__device__ float  g_rbias[(size_t)NHEAD * KLEN];
__device__ __half g_BD[(size_t)BSZ * NHEAD * QLEN * KLEN];
__device__ __half g_av16[(size_t)QLEN * BSZ * DMODEL];
__device__ float  g_tmp[(size_t)QLEN * BSZ * DMODEL];
__device__ float  g_out1[(size_t)QLEN * BSZ * DMODEL];
__device__ __half g_out116[(size_t)QLEN * BSZ * DMODEL];
__device__ __half g_ffh16[(size_t)QLEN * BSZ * DINNER];
__device__ __half g_cat16[(size_t)KLEN * BSZ * DMODEL];
__device__ __half g_r16[(size_t)KLEN * DMODEL];
__device__ __half g_qkvw16[(size_t)DMODEL * H3];
__device__ __half g_rnw16[(size_t)DMODEL * DMODEL];
__device__ __half g_ow16[(size_t)DMODEL * DMODEL];
__device__ __half g_ffw116[(size_t)DMODEL * DINNER];
__device__ __half g_ffw216[(size_t)DINNER * DMODEL];

__device__ __forceinline__ void cpa16(uint32_t s, const void* g) {
    asm volatile("cp.async.cg.shared.global [%0], [%1], 16;" :: "r"(s), "l"(g));
}
#define CP_COMMIT() asm volatile("cp.async.commit_group;")
#define CP_WAIT(N)  asm volatile("cp.async.wait_group %0;" :: "n"(N))
#define RN(x) ((x) + 0x1000u)

#define MMA_TF32(acc, av, bv)                                               \
    asm volatile(                                                           \
        "mma.sync.aligned.m16n8k8.row.col.f32.tf32.tf32.f32 "               \
        "{%0,%1,%2,%3}, {%4,%5,%6,%7}, {%8,%9}, {%0,%1,%2,%3};"             \
        : "+f"(acc[0]), "+f"(acc[1]), "+f"(acc[2]), "+f"(acc[3])            \
        : "r"(av[0]), "r"(av[1]), "r"(av[2]), "r"(av[3]),                   \
          "r"(bv[0]), "r"(bv[1]))

#define MMA_F16(acc, av, bv)                                                \
    asm volatile(                                                           \
        "mma.sync.aligned.m16n8k16.row.col.f32.f16.f16.f32 "                \
        "{%0,%1,%2,%3}, {%4,%5,%6,%7}, {%8,%9}, {%0,%1,%2,%3};"             \
        : "+f"(acc[0]), "+f"(acc[1]), "+f"(acc[2]), "+f"(acc[3])            \
        : "r"(av[0]), "r"(av[1]), "r"(av[2]), "r"(av[3]),                   \
          "r"(bv[0]), "r"(bv[1]))

#define LDSM_X4(r0, r1, r2, r3, addr)                                       \
    asm volatile("ldmatrix.sync.aligned.m8n8.x4.shared.b16 {%0,%1,%2,%3}, [%4];" \
        : "=r"(r0), "=r"(r1), "=r"(r2), "=r"(r3) : "r"(addr))
#define LDSM_X4T(r0, r1, r2, r3, addr)                                      \
    asm volatile("ldmatrix.sync.aligned.m8n8.x4.trans.shared.b16 {%0,%1,%2,%3}, [%4];" \
        : "=r"(r0), "=r"(r1), "=r"(r2), "=r"(r3) : "r"(addr))

// ----------------------------------------------------------------------------
__global__ __launch_bounds__(256) void cvt_k(
    const float* __restrict__ src, __half* __restrict__ dst)
{
    const int i = (blockIdx.x * 256 + threadIdx.x) * 8;
    const float4 a = *(const float4*)(src + i);
    const float4 b = *(const float4*)(src + i + 4);
    __half2 h[4];
    h[0] = __floats2half2_rn(a.x, a.y);
    h[1] = __floats2half2_rn(a.z, a.w);
    h[2] = __floats2half2_rn(b.x, b.y);
    h[3] = __floats2half2_rn(b.z, b.w);
    *(uint4*)(dst + i) = *(uint4*)h;
}

// ----------------------------------------------------------------------------
// Dense fp16 GEMM. HOUT=0: fp32 out. HOUT=1: fp16 out. HOUT=2: fp32 (col <
// f32lim) + fp16 dual out.
// ----------------------------------------------------------------------------
#define ASTR 40
#define BSTR 136

template <int HOUT>
__global__ __launch_bounds__(256, 2) void gemm_h(
    const __half* __restrict__ A, int lda,
    const __half* __restrict__ B,
    const float* __restrict__ bias, const float* __restrict__ resid, int doRelu,
    void* __restrict__ Cv, __half* __restrict__ C16, int f32lim,
    int M, int N, int Kd)
{
    __shared__ __half As[3][128 * ASTR];
    __shared__ __half Bs[3][32 * BSTR];

    const int tid  = threadIdx.x;
    const int warp = tid >> 5, lane = tid & 31;
    const int lr = lane >> 2, lc = lane & 3;
    const int bm = blockIdx.y * 128, bn = blockIdx.x * 128;
    const int wm = (warp & 1) * 64;
    const int wn = (warp >> 1) * 32;

    float acc[4][4][4];
#pragma unroll
    for (int mt = 0; mt < 4; mt++)
#pragma unroll
        for (int nt = 0; nt < 4; nt++)
#pragma unroll
            for (int q = 0; q < 4; q++) acc[mt][nt][q] = 0.f;

    const __half* aPtr[2];
    const __half* bPtr[2];
    uint32_t aDst[2], bDst[2];
#pragma unroll
    for (int h = 0; h < 2; h++) {
        const int ch = tid + h * 256;
        const int ar = ch >> 2, ao = (ch & 3) * 8;
        aPtr[h] = A + (long long)(bm + ar) * lda + ao;
        aDst[h] = (uint32_t)__cvta_generic_to_shared(&As[0][ar * ASTR + ao]);
        const int br = ch >> 4, bo = (ch & 15) * 8;
        bPtr[h] = B + (long long)br * N + bn + bo;
        bDst[h] = (uint32_t)__cvta_generic_to_shared(&Bs[0][br * BSTR + bo]);
    }
    const long long bStep = (long long)32 * N;

    auto load = [&](int kt, int s) {
#pragma unroll
        for (int h = 0; h < 2; h++)
            cpa16(aDst[h] + s * 128 * ASTR * 2, aPtr[h] + kt * 32);
#pragma unroll
        for (int h = 0; h < 2; h++)
            cpa16(bDst[h] + s * 32 * BSTR * 2, bPtr[h] + kt * bStep);
    };

    const int aRow = lane & 15;
    const int selOff = (lane >> 4) << 3;
    const uint32_t asBase = (uint32_t)__cvta_generic_to_shared(&As[0][0]);
    const uint32_t bsBase = (uint32_t)__cvta_generic_to_shared(&Bs[0][0]);

    const int nk = Kd >> 5;
    load(0, 0); CP_COMMIT();
    load(1, 1); CP_COMMIT();

    for (int kt = 0; kt < nk; kt++) {
        const int s = kt % 3;
        CP_WAIT(1);
        __syncthreads();
        if (kt + 2 < nk) load(kt + 2, (kt + 2) % 3);
        CP_COMMIT();

        const uint32_t aS = asBase + (uint32_t)(s * 128 * ASTR * 2);
        const uint32_t bS = bsBase + (uint32_t)(s * 32 * BSTR * 2);
#pragma unroll
        for (int kk = 0; kk < 32; kk += 16) {
            uint32_t af[4][4], bf[4][2];
#pragma unroll
            for (int mt = 0; mt < 4; mt++) {
                const uint32_t addr = aS +
                    (uint32_t)(((wm + mt * 16 + aRow) * ASTR + kk + selOff) * 2);
                LDSM_X4(af[mt][0], af[mt][1], af[mt][2], af[mt][3], addr);
            }
#pragma unroll
            for (int ntp = 0; ntp < 2; ntp++) {
                const uint32_t addr = bS +
                    (uint32_t)(((kk + aRow) * BSTR + wn + ntp * 16 + selOff) * 2);
                LDSM_X4T(bf[2 * ntp][0], bf[2 * ntp][1],
                         bf[2 * ntp + 1][0], bf[2 * ntp + 1][1], addr);
            }
#pragma unroll
            for (int mt = 0; mt < 4; mt++)
#pragma unroll
                for (int nt = 0; nt < 4; nt++)
                    MMA_F16(acc[mt][nt], af[mt], bf[nt]);
        }
    }

#pragma unroll
    for (int mt = 0; mt < 4; mt++) {
#pragma unroll
        for (int nt = 0; nt < 4; nt++) {
            const int col = bn + wn + nt * 8 + lc * 2;
#pragma unroll
            for (int half = 0; half < 2; half++) {
                const int row = bm + wm + mt * 16 + lr + half * 8;
                float v0 = acc[mt][nt][half * 2 + 0];
                float v1 = acc[mt][nt][half * 2 + 1];
                if (bias) { v0 += bias[col]; v1 += bias[col + 1]; }
                if (resid) {
                    const float* rp = resid + (long long)row * N + col;
                    v0 += rp[0]; v1 += rp[1];
                }
                if (doRelu) { v0 = fmaxf(v0, 0.f); v1 = fmaxf(v1, 0.f); }
                if (HOUT == 1) {
                    *(__half2*)((__half*)Cv + (long long)row * N + col) =
                        __floats2half2_rn(v0, v1);
                } else {
                    if (HOUT == 0 || col < f32lim) {
                        float* cp = (float*)Cv + (long long)row * N + col;
                        cp[0] = v0; cp[1] = v1;
                    }
                    if (HOUT == 2)
                        *(__half2*)(C16 + (long long)row * N + col) =
                            __floats2half2_rn(v0, v1);
                }
            }
        }
    }
}

// ----------------------------------------------------------------------------
__global__ __launch_bounds__(256) void rbias_k(
    const float* __restrict__ rrb, const float* __restrict__ rk,
    float* __restrict__ rbias)
{
    const int idx = blockIdx.x * 256 + threadIdx.x;
    const int c = idx >> 4, n = idx & 15;
    const float* rp = rk + (size_t)c * DMODEL + n * DHEAD;
    const float* bp = rrb + n * DHEAD;
    float s = 0.f;
#pragma unroll
    for (int d = 0; d < DHEAD; d++) s += rp[d] * bp[d];
    rbias[n * KLEN + c] = s;
}

// ----------------------------------------------------------------------------
// BD GEMM (tf32, proven): BD[bn][i][c] = q_i . rk_c (+rbias), fp16 out.
// ----------------------------------------------------------------------------
__global__ __launch_bounds__(256, 2) void bd_gemm(
    const float* __restrict__ Q, const float* __restrict__ RK,
    const float* __restrict__ rbias, __half* __restrict__ BD)
{
    __shared__ uint32_t As[3][2560];
    __shared__ uint32_t Bs[3][2560];

    const int tid = threadIdx.x;
    const int warp = tid >> 5, lane = tid & 31;
    const int lr = lane >> 2, lc = lane & 3;
    const int bm = blockIdx.y * 128, bn = blockIdx.x * 128;
    if (bm + bn < 769) return;
    const int bnidx = blockIdx.z;
    const int b = bnidx >> 4, n = bnidx & 15;
    const int wm = (warp & 1) * 64;
    const int wn = (warp >> 1) * 32;

    float acc[4][4][4];
#pragma unroll
    for (int mt = 0; mt < 4; mt++)
#pragma unroll
        for (int nt = 0; nt < 4; nt++)
#pragma unroll
            for (int q = 0; q < 4; q++) acc[mt][nt][q] = 0.f;

    const float* aPtr[2];
    const float* bPtr[2];
    uint32_t aDst[2], bDst[2];
#pragma unroll
    for (int h = 0; h < 2; h++) {
        const int ch = tid + h * 256;
        const int row = ch >> 2, kc = (ch & 3) * 4;
        aPtr[h] = Q + (size_t)(bm + row) * (BSZ * H3) + (size_t)b * H3 + n * DHEAD + kc;
        aDst[h] = (uint32_t)__cvta_generic_to_shared(&As[0][row * 20 + kc]);
        bPtr[h] = RK + (size_t)(bn + row) * DMODEL + n * DHEAD + kc;
        bDst[h] = (uint32_t)__cvta_generic_to_shared(&Bs[0][row * 20 + kc]);
    }

    auto load = [&](int kt, int s) {
#pragma unroll
        for (int h = 0; h < 2; h++)
            cpa16(aDst[h] + s * 2560 * 4, aPtr[h] + kt * 16);
#pragma unroll
        for (int h = 0; h < 2; h++)
            cpa16(bDst[h] + s * 2560 * 4, bPtr[h] + kt * 16);
    };

    const int nk = 4;
    load(0, 0); CP_COMMIT();
    load(1, 1); CP_COMMIT();

    for (int kt = 0; kt < nk; kt++) {
        const int s = kt % 3;
        CP_WAIT(1);
        __syncthreads();
        if (kt + 2 < nk) load(kt + 2, (kt + 2) % 3);
        CP_COMMIT();

#pragma unroll
        for (int kk = 0; kk < 16; kk += 8) {
            uint32_t af[4][4], bf[4][2];
#pragma unroll
            for (int mt = 0; mt < 4; mt++) {
                const int m0 = wm + mt * 16 + lr;
                af[mt][0] = RN(As[s][m0 * 20 + kk + lc]);
                af[mt][1] = RN(As[s][(m0 + 8) * 20 + kk + lc]);
                af[mt][2] = RN(As[s][m0 * 20 + kk + 4 + lc]);
                af[mt][3] = RN(As[s][(m0 + 8) * 20 + kk + 4 + lc]);
            }
#pragma unroll
            for (int nt = 0; nt < 4; nt++) {
                const int n0 = wn + nt * 8 + lr;
                bf[nt][0] = RN(Bs[s][n0 * 20 + kk + lc]);
                bf[nt][1] = RN(Bs[s][n0 * 20 + kk + 4 + lc]);
            }
#pragma unroll
            for (int mt = 0; mt < 4; mt++)
#pragma unroll
                for (int nt = 0; nt < 4; nt++)
                    MMA_TF32(acc[mt][nt], af[mt], bf[nt]);
        }
    }

#pragma unroll
    for (int mt = 0; mt < 4; mt++) {
#pragma unroll
        for (int nt = 0; nt < 4; nt++) {
            const int col = bn + wn + nt * 8 + lc * 2;
            const float rb0 = rbias[n * KLEN + col];
            const float rb1 = rbias[n * KLEN + col + 1];
#pragma unroll
            for (int half = 0; half < 2; half++) {
                const int row = bm + wm + mt * 16 + lr + half * 8;
                const float v0 = acc[mt][nt][half * 2 + 0] + rb0;
                const float v1 = acc[mt][nt][half * 2 + 1] + rb1;
                __half2* cp = (__half2*)(BD + ((size_t)bnidx * QLEN + row) * KLEN + col);
                *cp = __floats2half2_rn(v0, v1);
            }
        }
    }
}

// ----------------------------------------------------------------------------
// Flash attention v4: fp16 MMAs via ldmatrix, 512 threads, cp.async fp16 K/V.
// Smem: Qs16/Ks16(x2)/Vs16 [row][72]h, Ssf [row][132]f, Ps16 [row][136]h.
// ----------------------------------------------------------------------------
#define KSTR 72
#define SSS  132
#define PSTR 136
#define FLASH_SMEM (128*KSTR*2 + 2*128*KSTR*2 + 128*KSTR*2 + 128*SSS*4 + 128*PSTR*2 + 3*128*4)

__global__ __launch_bounds__(512, 1) void flash_k(
    const float* __restrict__ heads, const __half* __restrict__ heads16,
    const __half* __restrict__ BD,
    const float* __restrict__ rwb, __half* __restrict__ av16)
{
    extern __shared__ char smc[];
    __half* Qs16 = (__half*)smc;                       // 128*72
    __half* Ks16 = Qs16 + 128 * KSTR;                  // 2*128*72
    __half* Vs16 = Ks16 + 2 * 128 * KSTR;              // 128*72
    float*  Ssf  = (float*)(Vs16 + 128 * KSTR);        // 128*132
    __half* Ps16 = (__half*)(Ssf + 128 * SSS);         // 128*136
    float*  m_s  = (float*)(Ps16 + 128 * PSTR);
    float*  l_s  = m_s + 128;
    float*  sc_s = l_s + 128;
    const uint32_t qs_b = (uint32_t)__cvta_generic_to_shared(Qs16);
    const uint32_t ks_b = (uint32_t)__cvta_generic_to_shared(Ks16);
    const uint32_t vs_b = (uint32_t)__cvta_generic_to_shared(Vs16);
    const uint32_t ps_b = (uint32_t)__cvta_generic_to_shared(Ps16);

    const int tid = threadIdx.x;
    const int warp = tid >> 5, lane = tid & 31;
    const int lr = lane >> 2, lc = lane & 3;
    const int aRow = lane & 15;
    const int selOff = (lane >> 4) << 3;
    const int qt = (int)gridDim.x - 1 - (int)blockIdx.x;
    const int i0 = qt * 128;
    const int bn = blockIdx.y;
    const int b = bn >> 4, n = bn & 15;
    const int wm  = (warp & 3) * 32;
    const int wn  = (warp >> 2) * 32;
    const int wn2 = (warp >> 2) * 16;
    const int njt = qt + 9;

    auto loadK = [&](int jt, int buf) {
        const int j0 = jt * 128;
#pragma unroll
        for (int it = 0; it < 2; it++) {
            const int c = tid + it * 512;
            const int row = c >> 3, seg = (c & 7) << 3;
            const __half* g = heads16 + ((size_t)(j0 + row) * BSZ + b) * H3 + DMODEL + n * DHEAD + seg;
            cpa16(ks_b + (uint32_t)((((buf << 7) + row) * KSTR + seg) << 1), g);
        }
        CP_COMMIT();
    };
    auto loadV = [&](int jt) {
        const int j0 = jt * 128;
#pragma unroll
        for (int it = 0; it < 2; it++) {
            const int c = tid + it * 512;
            const int row = c >> 3, seg = (c & 7) << 3;
            const __half* g = heads16 + ((size_t)(j0 + row) * BSZ + b) * H3 + 2 * DMODEL + n * DHEAD + seg;
            cpa16(vs_b + (uint32_t)((row * KSTR + seg) << 1), g);
        }
        CP_COMMIT();
    };

    loadK(0, 0);
    const float* qbase = heads + (size_t)MEMLEN * BSZ * H3;
#pragma unroll
    for (int it = 0; it < 4; it++) {
        const int idx = tid + it * 512;
        const int row = idx >> 4, c4 = (idx & 15) * 4;
        float4 v = *(const float4*)(qbase + ((size_t)(i0 + row) * BSZ + b) * H3 + n * DHEAD + c4);
        const float4 bb = *(const float4*)(rwb + n * DHEAD + c4);
        __half2 h0 = __floats2half2_rn(v.x + bb.x, v.y + bb.y);
        __half2 h1 = __floats2half2_rn(v.z + bb.z, v.w + bb.w);
        *(__half2*)(Qs16 + row * KSTR + c4) = h0;
        *(__half2*)(Qs16 + row * KSTR + c4 + 2) = h1;
    }
    if (tid < 128) { m_s[tid] = -1e30f; l_s[tid] = 0.f; }

    float accO[2][2][4];
#pragma unroll
    for (int mt = 0; mt < 2; mt++)
#pragma unroll
        for (int nt = 0; nt < 2; nt++)
#pragma unroll
            for (int q = 0; q < 4; q++) accO[mt][nt][q] = 0.f;

    CP_WAIT(0);
    __syncthreads();

    for (int jt = 0; jt < njt; jt++) {
        const int j0 = jt * 128;
        const int cur = jt & 1;
        const bool more = (jt + 1 < njt);

        loadV(jt);
        if (more) loadK(jt + 1, cur ^ 1);

        // ---- S = Qw . K[cur]^T (128x128, K=64 fp16); warp tile 32x32 ----
        float accS[2][4][4];
#pragma unroll
        for (int mt = 0; mt < 2; mt++)
#pragma unroll
            for (int nt = 0; nt < 4; nt++)
#pragma unroll
                for (int q = 0; q < 4; q++) accS[mt][nt][q] = 0.f;

#pragma unroll
        for (int kk = 0; kk < 64; kk += 16) {
            uint32_t af[2][4], bfr[4][2];
#pragma unroll
            for (int mt = 0; mt < 2; mt++) {
                const uint32_t addr = qs_b +
                    (uint32_t)(((wm + mt * 16 + aRow) * KSTR + kk + selOff) << 1);
                LDSM_X4(af[mt][0], af[mt][1], af[mt][2], af[mt][3], addr);
            }
#pragma unroll
            for (int p = 0; p < 2; p++) {
                uint32_t r0, r1, r2, r3;
                const uint32_t addr = ks_b +
                    (uint32_t)(((((cur << 7) + wn + p * 16 + aRow)) * KSTR + kk + selOff) << 1);
                LDSM_X4(r0, r1, r2, r3, addr);
                bfr[2 * p][0] = r0; bfr[2 * p][1] = r2;
                bfr[2 * p + 1][0] = r1; bfr[2 * p + 1][1] = r3;
            }
#pragma unroll
            for (int mt = 0; mt < 2; mt++)
#pragma unroll
                for (int nt = 0; nt < 4; nt++)
                    MMA_F16(accS[mt][nt], af[mt], bfr[nt]);
        }

        // ---- stage raw AC scores to smem (fp32) ----
#pragma unroll
        for (int mt = 0; mt < 2; mt++) {
            const int r0 = wm + mt * 16 + lr;
#pragma unroll
            for (int nt = 0; nt < 4; nt++) {
                const int col = wn + nt * 8 + 2 * lc;
                *(float2*)&Ssf[r0 * SSS + col] =
                    make_float2(accS[mt][nt][0], accS[mt][nt][1]);
                *(float2*)&Ssf[(r0 + 8) * SSS + col] =
                    make_float2(accS[mt][nt][2], accS[mt][nt][3]);
            }
        }
        __syncthreads();

        // ---- softmax: one warp per row; P stored fp16 ----
#pragma unroll 2
        for (int rr = 0; rr < 8; rr++) {
            const int row = warp * 8 + rr;
            const int i = i0 + row;
            const __half* bdp = BD + ((size_t)bn * QLEN + i) * KLEN + (j0 - i + QLEN - 1);
            const int vmax = i + MEMLEN - j0;
            float sv[4];
            float mloc = -1e30f;
#pragma unroll
            for (int k2 = 0; k2 < 4; k2++) {
                const int c = lane + 32 * k2;
                float s = -1e30f;
                if (c <= vmax) s = (Ssf[row * SSS + c] + __half2float(__ldg(bdp + c))) * 0.125f;
                sv[k2] = s;
                mloc = fmaxf(mloc, s);
            }
#pragma unroll
            for (int o = 16; o; o >>= 1)
                mloc = fmaxf(mloc, __shfl_xor_sync(0xffffffffu, mloc, o));
            const float mo = m_s[row];
            const float nm = fmaxf(mo, mloc);
            float lsum = 0.f;
#pragma unroll
            for (int k2 = 0; k2 < 4; k2++) {
                const int c = lane + 32 * k2;
                const float p = __expf(sv[k2] - nm);
                const __half ph = __float2half_rn(p);
                lsum += __half2float(ph);
                Ps16[row * PSTR + c] = ph;
            }
#pragma unroll
            for (int o = 16; o; o >>= 1)
                lsum += __shfl_xor_sync(0xffffffffu, lsum, o);
            if (lane == 0) {
                const float alpha = __expf(mo - nm);
                m_s[row] = nm;
                l_s[row] = l_s[row] * alpha + lsum;
                sc_s[row] = alpha;
            }
        }

        // ---- single barrier: P/stats visible AND V(jt) resident ----
        if (more) { CP_WAIT(1); } else { CP_WAIT(0); }
        __syncthreads();

        // ---- rescale O, then O += P . V (128x64, K=128 fp16) ----
#pragma unroll
        for (int mt = 0; mt < 2; mt++) {
            const int r = wm + mt * 16 + lr;
            const float s0 = sc_s[r], s1 = sc_s[r + 8];
#pragma unroll
            for (int nt = 0; nt < 2; nt++) {
                accO[mt][nt][0] *= s0; accO[mt][nt][1] *= s0;
                accO[mt][nt][2] *= s1; accO[mt][nt][3] *= s1;
            }
        }
#pragma unroll
        for (int jj = 0; jj < 128; jj += 16) {
            uint32_t af[2][4], bf[2][2];
#pragma unroll
            for (int mt = 0; mt < 2; mt++) {
                const uint32_t addr = ps_b +
                    (uint32_t)(((wm + mt * 16 + aRow) * PSTR + jj + selOff) << 1);
                LDSM_X4(af[mt][0], af[mt][1], af[mt][2], af[mt][3], addr);
            }
            {
                const uint32_t addr = vs_b +
                    (uint32_t)(((jj + aRow) * KSTR + wn2 + selOff) << 1);
                LDSM_X4T(bf[0][0], bf[0][1], bf[1][0], bf[1][1], addr);
            }
#pragma unroll
            for (int mt = 0; mt < 2; mt++)
#pragma unroll
                for (int nt = 0; nt < 2; nt++)
                    MMA_F16(accO[mt][nt], af[mt], bf[nt]);
        }

        if (more) CP_WAIT(0);
        __syncthreads();
    }

    // ---- finalize ----
#pragma unroll
    for (int mt = 0; mt < 2; mt++) {
        const int r = wm + mt * 16 + lr;
        const float inv0 = 1.f / l_s[r];
        const float inv1 = 1.f / l_s[r + 8];
#pragma unroll
        for (int nt = 0; nt < 2; nt++) {
            const int col = wn2 + nt * 8 + 2 * lc;
            __half2* p0 = (__half2*)(av16 + ((size_t)(i0 + r) * BSZ + b) * DMODEL + n * DHEAD + col);
            *p0 = __floats2half2_rn(accO[mt][nt][0] * inv0, accO[mt][nt][1] * inv0);
            __half2* p1 = (__half2*)(av16 + ((size_t)(i0 + r + 8) * BSZ + b) * DMODEL + n * DHEAD + col);
            *p1 = __floats2half2_rn(accO[mt][nt][2] * inv1, accO[mt][nt][3] * inv1);
        }
    }
}

// ----------------------------------------------------------------------------
__device__ __forceinline__ float warpSum(float v) {
#pragma unroll
    for (int o = 16; o; o >>= 1) v += __shfl_xor_sync(0xffffffffu, v, o);
    return v;
}

__global__ __launch_bounds__(256) void ln_k(
    const float* __restrict__ X, const float* __restrict__ gam,
    const float* __restrict__ bet, float* __restrict__ Y,
    __half* __restrict__ Y16)
{
    __shared__ float red[8];
    const size_t row = blockIdx.x;
    const int tid = threadIdx.x;
    const float4 v = *(const float4*)(X + row * DMODEL + tid * 4);
    float s = v.x + v.y + v.z + v.w;
    float q = v.x * v.x + v.y * v.y + v.z * v.z + v.w * v.w;

    float ws = warpSum(s);
    if ((tid & 31) == 0) red[tid >> 5] = ws;
    __syncthreads();
    if (tid < 32) {
        float t = (tid < 8) ? red[tid] : 0.f;
        t = warpSum(t);
        if (tid == 0) red[0] = t;
    }
    __syncthreads();
    const float mu = red[0] * (1.f / DMODEL);
    __syncthreads();

    float wq = warpSum(q);
    if ((tid & 31) == 0) red[tid >> 5] = wq;
    __syncthreads();
    if (tid < 32) {
        float t = (tid < 8) ? red[tid] : 0.f;
        t = warpSum(t);
        if (tid == 0) red[0] = t;
    }
    __syncthreads();
    const float var = red[0] * (1.f / DMODEL) - mu * mu;
    const float rs = rsqrtf(var + 1e-5f);

    const float4 gv = *(const float4*)(gam + tid * 4);
    const float4 bv = *(const float4*)(bet + tid * 4);
    float4 o;
    o.x = (v.x - mu) * rs * gv.x + bv.x;
    o.y = (v.y - mu) * rs * gv.y + bv.y;
    o.z = (v.z - mu) * rs * gv.z + bv.z;
    o.w = (v.w - mu) * rs * gv.w + bv.w;
    *(float4*)(Y + row * DMODEL + tid * 4) = o;
    if (Y16) {
        __half2 h[2] = { __floats2half2_rn(o.x, o.y), __floats2half2_rn(o.z, o.w) };
        *(uint2*)(Y16 + row * DMODEL + tid * 4) = *(uint2*)h;
    }
}

// ----------------------------------------------------------------------------
extern "C" void kernel_launch(void* const* d_in, const int* in_sizes, int n_in,
                              void* d_out, int out_size)
{
    (void)in_sizes; (void)n_in; (void)out_size;
    const float* w       = (const float*)d_in[0];
    const float* r       = (const float*)d_in[1];
    const float* mems    = (const float*)d_in[2];
    const float* qkv_w   = (const float*)d_in[3];
    const float* r_net_w = (const float*)d_in[4];
    const float* o_w     = (const float*)d_in[5];
    const float* rwb     = (const float*)d_in[6];
    const float* rrb     = (const float*)d_in[7];
    const float* ln1g    = (const float*)d_in[8];
    const float* ln1b    = (const float*)d_in[9];
    const float* ffw1    = (const float*)d_in[10];
    const float* ffb1    = (const float*)d_in[11];
    const float* ffw2    = (const float*)d_in[12];
    const float* ffb2    = (const float*)d_in[13];
    const float* ln2g    = (const float*)d_in[14];
    const float* ln2b    = (const float*)d_in[15];
    float* out = (float*)d_out;

    float *heads, *rk, *rbias, *tmp, *out1;
    __half *heads16, *BD, *av16, *out116, *ffh16;
    __half *cat16, *r16, *qkvw16, *rnw16, *ow16, *ffw116, *ffw216;
    cudaGetSymbolAddress((void**)&heads,   g_heads);
    cudaGetSymbolAddress((void**)&heads16, g_heads16);
    cudaGetSymbolAddress((void**)&rk,      g_rk);
    cudaGetSymbolAddress((void**)&rbias,   g_rbias);
    cudaGetSymbolAddress((void**)&BD,      g_BD);
    cudaGetSymbolAddress((void**)&av16,    g_av16);
    cudaGetSymbolAddress((void**)&tmp,     g_tmp);
    cudaGetSymbolAddress((void**)&out1,    g_out1);
    cudaGetSymbolAddress((void**)&out116,  g_out116);
    cudaGetSymbolAddress((void**)&ffh16,   g_ffh16);
    cudaGetSymbolAddress((void**)&cat16,   g_cat16);
    cudaGetSymbolAddress((void**)&r16,     g_r16);
    cudaGetSymbolAddress((void**)&qkvw16,  g_qkvw16);
    cudaGetSymbolAddress((void**)&rnw16,   g_rnw16);
    cudaGetSymbolAddress((void**)&ow16,    g_ow16);
    cudaGetSymbolAddress((void**)&ffw116,  g_ffw116);
    cudaGetSymbolAddress((void**)&ffw216,  g_ffw216);

    static int s_attr_done = 0;
    if (!s_attr_done) {
        cudaFuncSetAttribute(flash_k, cudaFuncAttributeMaxDynamicSharedMemorySize,
                             FLASH_SMEM);
        s_attr_done = 1;
    }

    const dim3 blk(256);
    const int BIG = 1 << 30;
    const float* qbase = heads + (size_t)MEMLEN * BSZ * H3;

    // 0) fp32 -> fp16 conversions
    cvt_k<<<(MEMLEN * BSZ * DMODEL) / 2048, blk>>>(mems, cat16);
    cvt_k<<<(QLEN * BSZ * DMODEL) / 2048, blk>>>(w, cat16 + (size_t)MEMLEN * BSZ * DMODEL);
    cvt_k<<<(KLEN * DMODEL) / 2048, blk>>>(r, r16);
    cvt_k<<<(DMODEL * H3) / 2048, blk>>>(qkv_w, qkvw16);
    cvt_k<<<(DMODEL * DMODEL) / 2048, blk>>>(r_net_w, rnw16);
    cvt_k<<<(DMODEL * DMODEL) / 2048, blk>>>(o_w, ow16);
    cvt_k<<<(DMODEL * DINNER) / 2048, blk>>>(ffw1, ffw116);
    cvt_k<<<(DINNER * DMODEL) / 2048, blk>>>(ffw2, ffw216);

    // 1) heads = cat16 @ qkvw16 — fp32 (Q cols only) + fp16 dual out
    gemm_h<2><<<dim3(H3 / 128, (KLEN * BSZ) / 128), blk>>>(
        cat16, DMODEL, qkvw16, nullptr, nullptr, 0,
        heads, heads16, DMODEL, KLEN * BSZ, H3, DMODEL);

    // 2) rk = r16 @ rnw16 (fp32 out)
    gemm_h<0><<<dim3(DMODEL / 128, KLEN / 128), blk>>>(
        r16, DMODEL, rnw16, nullptr, nullptr, 0,
        rk, nullptr, BIG, KLEN, DMODEL, DMODEL);

    // 3) rbias
    rbias_k<<<(NHEAD * KLEN) / 256, blk>>>(rrb, rk, rbias);

    // 4) BD (tf32, fp16 out, diag skip)
    bd_gemm<<<dim3(KLEN / 128, QLEN / 128, BSZ * NHEAD), blk>>>(
        qbase, rk, rbias, BD);

    // 5) flash (fp16 MMAs) -> av16
    flash_k<<<dim3(QLEN / 128, BSZ * NHEAD), dim3(512), FLASH_SMEM>>>(
        heads, heads16, BD, rwb, av16);

    // 6) attn_out = av16 @ ow16 + w
    gemm_h<0><<<dim3(DMODEL / 128, (QLEN * BSZ) / 128), blk>>>(
        av16, DMODEL, ow16, nullptr, w, 0,
        tmp, nullptr, BIG, QLEN * BSZ, DMODEL, DMODEL);

    // 7) LN1 (dual fp32 + fp16)
    ln_k<<<QLEN * BSZ, blk>>>(tmp, ln1g, ln1b, out1, out116);

    // 8) ffh16 = relu(out116 @ ffw116 + b1) (fp16 out)
    gemm_h<1><<<dim3(DINNER / 128, (QLEN * BSZ) / 128), blk>>>(
        out116, DMODEL, ffw116, ffb1, nullptr, 1,
        ffh16, nullptr, BIG, QLEN * BSZ, DINNER, DMODEL);

    // 9) tmp = ffh16 @ ffw216 + b2 + out1
    gemm_h<0><<<dim3(DMODEL / 128, (QLEN * BSZ) / 128), blk>>>(
        ffh16, DINNER, ffw216, ffb2, out1, 0,
        tmp, nullptr, BIG, QLEN * BSZ, DMODEL, DINNER);

    // 10) LN2 -> output
    ln_k<<<QLEN * BSZ, blk>>>(tmp, ln2g, ln2b, out, nullptr);
}

// round 11
// speedup vs baseline: 2.2856x; 1.0536x over previous
#include <cuda_runtime.h>
#include <cuda_fp16.h>
#include <math.h>
#include <stdint.h>

#define QLEN   1024
#define BSZ    4
#define DMODEL 1024
#define NHEAD  16
#define DHEAD  64
#define DINNER 4096
#define MEMLEN 1024
#define KLEN   2048
#define H3     (3 * DMODEL)   // 3072
#define QK     ((long long)QLEN * KLEN)

// ---- static device scratch (no cudaMalloc allowed) ----
__device__ __half g_heads16[(size_t)KLEN * BSZ * H3];        // fp16 QKV heads
__device__ float  g_rk[(size_t)KLEN * DMODEL];               // fp32 (for rbias)
__device__ __half g_rk16[(size_t)KLEN * DMODEL];             // fp16 (for bd16)
__device__ float  g_rbias[(size_t)NHEAD * KLEN];
__device__ __half g_BD[(size_t)BSZ * NHEAD * QLEN * KLEN];
__device__ __half g_av16[(size_t)QLEN * BSZ * DMODEL];
__device__ float  g_tmp[(size_t)QLEN * BSZ * DMODEL];
__device__ float  g_out1[(size_t)QLEN * BSZ * DMODEL];
__device__ __half g_out116[(size_t)QLEN * BSZ * DMODEL];
__device__ __half g_ffh16[(size_t)QLEN * BSZ * DINNER];
__device__ __half g_cat16[(size_t)KLEN * BSZ * DMODEL];
__device__ __half g_r16[(size_t)KLEN * DMODEL];
__device__ __half g_qkvw16[(size_t)DMODEL * H3];
__device__ __half g_rnw16[(size_t)DMODEL * DMODEL];
__device__ __half g_ow16[(size_t)DMODEL * DMODEL];
__device__ __half g_ffw116[(size_t)DMODEL * DINNER];
__device__ __half g_ffw216[(size_t)DINNER * DMODEL];

__device__ __forceinline__ void cpa16(uint32_t s, const void* g) {
    asm volatile("cp.async.cg.shared.global [%0], [%1], 16;" :: "r"(s), "l"(g));
}
#define CP_COMMIT() asm volatile("cp.async.commit_group;")
#define CP_WAIT(N)  asm volatile("cp.async.wait_group %0;" :: "n"(N))

#define MMA_F16(acc, av, bv)                                                \
    asm volatile(                                                           \
        "mma.sync.aligned.m16n8k16.row.col.f32.f16.f16.f32 "                \
        "{%0,%1,%2,%3}, {%4,%5,%6,%7}, {%8,%9}, {%0,%1,%2,%3};"             \
        : "+f"(acc[0]), "+f"(acc[1]), "+f"(acc[2]), "+f"(acc[3])            \
        : "r"(av[0]), "r"(av[1]), "r"(av[2]), "r"(av[3]),                   \
          "r"(bv[0]), "r"(bv[1]))

#define LDSM_X4(r0, r1, r2, r3, addr)                                       \
    asm volatile("ldmatrix.sync.aligned.m8n8.x4.shared.b16 {%0,%1,%2,%3}, [%4];" \
        : "=r"(r0), "=r"(r1), "=r"(r2), "=r"(r3) : "r"(addr))
#define LDSM_X4T(r0, r1, r2, r3, addr)                                      \
    asm volatile("ldmatrix.sync.aligned.m8n8.x4.trans.shared.b16 {%0,%1,%2,%3}, [%4];" \
        : "=r"(r0), "=r"(r1), "=r"(r2), "=r"(r3) : "r"(addr))

// ----------------------------------------------------------------------------
__global__ __launch_bounds__(256) void cvt_k(
    const float* __restrict__ src, __half* __restrict__ dst)
{
    const int i = (blockIdx.x * 256 + threadIdx.x) * 8;
    const float4 a = *(const float4*)(src + i);
    const float4 b = *(const float4*)(src + i + 4);
    __half2 h[4];
    h[0] = __floats2half2_rn(a.x, a.y);
    h[1] = __floats2half2_rn(a.z, a.w);
    h[2] = __floats2half2_rn(b.x, b.y);
    h[3] = __floats2half2_rn(b.z, b.w);
    *(uint4*)(dst + i) = *(uint4*)h;
}

// ----------------------------------------------------------------------------
// Dense fp16 GEMM. HOUT=0: fp32 out. HOUT=1: fp16 out. HOUT=2: fp32+fp16 dual.
// ----------------------------------------------------------------------------
#define ASTR 40
#define BSTR 136

template <int HOUT>
__global__ __launch_bounds__(256, 2) void gemm_h(
    const __half* __restrict__ A, int lda,
    const __half* __restrict__ B,
    const float* __restrict__ bias, const float* __restrict__ resid, int doRelu,
    void* __restrict__ Cv, __half* __restrict__ C16,
    int M, int N, int Kd)
{
    __shared__ __half As[3][128 * ASTR];
    __shared__ __half Bs[3][32 * BSTR];

    const int tid  = threadIdx.x;
    const int warp = tid >> 5, lane = tid & 31;
    const int lr = lane >> 2, lc = lane & 3;
    const int bm = blockIdx.y * 128, bn = blockIdx.x * 128;
    const int wm = (warp & 1) * 64;
    const int wn = (warp >> 1) * 32;

    float acc[4][4][4];
#pragma unroll
    for (int mt = 0; mt < 4; mt++)
#pragma unroll
        for (int nt = 0; nt < 4; nt++)
#pragma unroll
            for (int q = 0; q < 4; q++) acc[mt][nt][q] = 0.f;

    const __half* aPtr[2];
    const __half* bPtr[2];
    uint32_t aDst[2], bDst[2];
#pragma unroll
    for (int h = 0; h < 2; h++) {
        const int ch = tid + h * 256;
        const int ar = ch >> 2, ao = (ch & 3) * 8;
        aPtr[h] = A + (long long)(bm + ar) * lda + ao;
        aDst[h] = (uint32_t)__cvta_generic_to_shared(&As[0][ar * ASTR + ao]);
        const int br = ch >> 4, bo = (ch & 15) * 8;
        bPtr[h] = B + (long long)br * N + bn + bo;
        bDst[h] = (uint32_t)__cvta_generic_to_shared(&Bs[0][br * BSTR + bo]);
    }
    const long long bStep = (long long)32 * N;

    auto load = [&](int kt, int s) {
#pragma unroll
        for (int h = 0; h < 2; h++)
            cpa16(aDst[h] + s * 128 * ASTR * 2, aPtr[h] + kt * 32);
#pragma unroll
        for (int h = 0; h < 2; h++)
            cpa16(bDst[h] + s * 32 * BSTR * 2, bPtr[h] + kt * bStep);
    };

    const int aRow = lane & 15;
    const int selOff = (lane >> 4) << 3;
    const uint32_t asBase = (uint32_t)__cvta_generic_to_shared(&As[0][0]);
    const uint32_t bsBase = (uint32_t)__cvta_generic_to_shared(&Bs[0][0]);

    const int nk = Kd >> 5;
    load(0, 0); CP_COMMIT();
    load(1, 1); CP_COMMIT();

    for (int kt = 0; kt < nk; kt++) {
        const int s = kt % 3;
        CP_WAIT(1);
        __syncthreads();
        if (kt + 2 < nk) load(kt + 2, (kt + 2) % 3);
        CP_COMMIT();

        const uint32_t aS = asBase + (uint32_t)(s * 128 * ASTR * 2);
        const uint32_t bS = bsBase + (uint32_t)(s * 32 * BSTR * 2);
#pragma unroll
        for (int kk = 0; kk < 32; kk += 16) {
            uint32_t af[4][4], bf[4][2];
#pragma unroll
            for (int mt = 0; mt < 4; mt++) {
                const uint32_t addr = aS +
                    (uint32_t)(((wm + mt * 16 + aRow) * ASTR + kk + selOff) * 2);
                LDSM_X4(af[mt][0], af[mt][1], af[mt][2], af[mt][3], addr);
            }
#pragma unroll
            for (int ntp = 0; ntp < 2; ntp++) {
                const uint32_t addr = bS +
                    (uint32_t)(((kk + aRow) * BSTR + wn + ntp * 16 + selOff) * 2);
                LDSM_X4T(bf[2 * ntp][0], bf[2 * ntp][1],
                         bf[2 * ntp + 1][0], bf[2 * ntp + 1][1], addr);
            }
#pragma unroll
            for (int mt = 0; mt < 4; mt++)
#pragma unroll
                for (int nt = 0; nt < 4; nt++)
                    MMA_F16(acc[mt][nt], af[mt], bf[nt]);
        }
    }

#pragma unroll
    for (int mt = 0; mt < 4; mt++) {
#pragma unroll
        for (int nt = 0; nt < 4; nt++) {
            const int col = bn + wn + nt * 8 + lc * 2;
#pragma unroll
            for (int half = 0; half < 2; half++) {
                const int row = bm + wm + mt * 16 + lr + half * 8;
                float v0 = acc[mt][nt][half * 2 + 0];
                float v1 = acc[mt][nt][half * 2 + 1];
                if (bias) { v0 += bias[col]; v1 += bias[col + 1]; }
                if (resid) {
                    const float* rp = resid + (long long)row * N + col;
                    v0 += rp[0]; v1 += rp[1];
                }
                if (doRelu) { v0 = fmaxf(v0, 0.f); v1 = fmaxf(v1, 0.f); }
                if (HOUT == 1) {
                    *(__half2*)((__half*)Cv + (long long)row * N + col) =
                        __floats2half2_rn(v0, v1);
                } else {
                    float* cp = (float*)Cv + (long long)row * N + col;
                    cp[0] = v0; cp[1] = v1;
                    if (HOUT == 2)
                        *(__half2*)(C16 + (long long)row * N + col) =
                            __floats2half2_rn(v0, v1);
                }
            }
        }
    }
}

// ----------------------------------------------------------------------------
__global__ __launch_bounds__(256) void rbias_k(
    const float* __restrict__ rrb, const float* __restrict__ rk,
    float* __restrict__ rbias)
{
    const int idx = blockIdx.x * 256 + threadIdx.x;
    const int c = idx >> 4, n = idx & 15;
    const float* rp = rk + (size_t)c * DMODEL + n * DHEAD;
    const float* bp = rrb + n * DHEAD;
    float s = 0.f;
#pragma unroll
    for (int d = 0; d < DHEAD; d++) s += rp[d] * bp[d];
    rbias[n * KLEN + c] = s;
}

// ----------------------------------------------------------------------------
// BD GEMM fp16: BD[bn][i][c] = q16_i . rk16_c (+rbias), fp16 out, diag skip.
// 128x128 tile, K=64 single-shot, 8 warps (2x4) of 64x32, ldmatrix + k16 MMA.
// ----------------------------------------------------------------------------
#define BDSTR 72

__global__ __launch_bounds__(256, 2) void bd16_gemm(
    const __half* __restrict__ Q16,   // query rows of g_heads16
    const __half* __restrict__ RK16,
    const float* __restrict__ rbias, __half* __restrict__ BD)
{
    __shared__ __half As[128 * BDSTR];
    __shared__ __half Bs[128 * BDSTR];

    const int tid = threadIdx.x;
    const int warp = tid >> 5, lane = tid & 31;
    const int lr = lane >> 2, lc = lane & 3;
    const int bm = blockIdx.y * 128, bn = blockIdx.x * 128;
    if (bm + bn < 769) return;   // fully masked tile, never read by flash
    const int bnidx = blockIdx.z;
    const int b = bnidx >> 4, n = bnidx & 15;
    const int wm = (warp & 1) * 64;
    const int wn = (warp >> 1) * 32;
    const int aRow = lane & 15;
    const int selOff = (lane >> 4) << 3;
    const uint32_t as_b = (uint32_t)__cvta_generic_to_shared(As);
    const uint32_t bs_b = (uint32_t)__cvta_generic_to_shared(Bs);

    // load A (Q rows) and B (rk rows), 64 halves each row
#pragma unroll
    for (int h = 0; h < 4; h++) {
        const int ch = tid + h * 256;
        const int row = ch >> 3, seg = (ch & 7) * 8;
        const __half* ga = Q16 + ((size_t)(bm + row) * BSZ + b) * H3 + n * DHEAD + seg;
        cpa16(as_b + (uint32_t)((row * BDSTR + seg) << 1), ga);
    }
#pragma unroll
    for (int h = 0; h < 4; h++) {
        const int ch = tid + h * 256;
        const int row = ch >> 3, seg = (ch & 7) * 8;
        const __half* gb = RK16 + (size_t)(bn + row) * DMODEL + n * DHEAD + seg;
        cpa16(bs_b + (uint32_t)((row * BDSTR + seg) << 1), gb);
    }
    CP_COMMIT();

    float acc[4][4][4];
#pragma unroll
    for (int mt = 0; mt < 4; mt++)
#pragma unroll
        for (int nt = 0; nt < 4; nt++)
#pragma unroll
            for (int q = 0; q < 4; q++) acc[mt][nt][q] = 0.f;

    CP_WAIT(0);
    __syncthreads();

#pragma unroll
    for (int kk = 0; kk < 64; kk += 16) {
        uint32_t af[4][4], bfr[4][2];
#pragma unroll
        for (int mt = 0; mt < 4; mt++) {
            const uint32_t addr = as_b +
                (uint32_t)(((wm + mt * 16 + aRow) * BDSTR + kk + selOff) << 1);
            LDSM_X4(af[mt][0], af[mt][1], af[mt][2], af[mt][3], addr);
        }
#pragma unroll
        for (int p = 0; p < 2; p++) {
            uint32_t r0, r1, r2, r3;
            const uint32_t addr = bs_b +
                (uint32_t)(((wn + p * 16 + aRow) * BDSTR + kk + selOff) << 1);
            LDSM_X4(r0, r1, r2, r3, addr);
            bfr[2 * p][0] = r0; bfr[2 * p][1] = r2;
            bfr[2 * p + 1][0] = r1; bfr[2 * p + 1][1] = r3;
        }
#pragma unroll
        for (int mt = 0; mt < 4; mt++)
#pragma unroll
            for (int nt = 0; nt < 4; nt++)
                MMA_F16(acc[mt][nt], af[mt], bfr[nt]);
    }

    // epilogue: + rbias, fp16 store
#pragma unroll
    for (int mt = 0; mt < 4; mt++) {
#pragma unroll
        for (int nt = 0; nt < 4; nt++) {
            const int col = bn + wn + nt * 8 + lc * 2;
            const float rb0 = rbias[n * KLEN + col];
            const float rb1 = rbias[n * KLEN + col + 1];
#pragma unroll
            for (int half = 0; half < 2; half++) {
                const int row = bm + wm + mt * 16 + lr + half * 8;
                const float v0 = acc[mt][nt][half * 2 + 0] + rb0;
                const float v1 = acc[mt][nt][half * 2 + 1] + rb1;
                __half2* cp = (__half2*)(BD + ((size_t)bnidx * QLEN + row) * KLEN + col);
                *cp = __floats2half2_rn(v0, v1);
            }
        }
    }
}

// ----------------------------------------------------------------------------
// Flash attention: fp16 MMAs via ldmatrix, 512 threads, cp.async fp16 K/V.
// ----------------------------------------------------------------------------
#define KSTR 72
#define SSS  132
#define PSTR 136
#define FLASH_SMEM (128*KSTR*2 + 2*128*KSTR*2 + 128*KSTR*2 + 128*SSS*4 + 128*PSTR*2 + 3*128*4)

__global__ __launch_bounds__(512, 1) void flash_k(
    const __half* __restrict__ heads16,
    const __half* __restrict__ BD,
    const float* __restrict__ rwb, __half* __restrict__ av16)
{
    extern __shared__ char smc[];
    __half* Qs16 = (__half*)smc;
    __half* Ks16 = Qs16 + 128 * KSTR;
    __half* Vs16 = Ks16 + 2 * 128 * KSTR;
    float*  Ssf  = (float*)(Vs16 + 128 * KSTR);
    __half* Ps16 = (__half*)(Ssf + 128 * SSS);
    float*  m_s  = (float*)(Ps16 + 128 * PSTR);
    float*  l_s  = m_s + 128;
    float*  sc_s = l_s + 128;
    const uint32_t qs_b = (uint32_t)__cvta_generic_to_shared(Qs16);
    const uint32_t ks_b = (uint32_t)__cvta_generic_to_shared(Ks16);
    const uint32_t vs_b = (uint32_t)__cvta_generic_to_shared(Vs16);
    const uint32_t ps_b = (uint32_t)__cvta_generic_to_shared(Ps16);

    const int tid = threadIdx.x;
    const int warp = tid >> 5, lane = tid & 31;
    const int lr = lane >> 2, lc = lane & 3;
    const int aRow = lane & 15;
    const int selOff = (lane >> 4) << 3;
    const int qt = (int)gridDim.x - 1 - (int)blockIdx.x;
    const int i0 = qt * 128;
    const int bn = blockIdx.y;
    const int b = bn >> 4, n = bn & 15;
    const int wm  = (warp & 3) * 32;
    const int wn  = (warp >> 2) * 32;
    const int wn2 = (warp >> 2) * 16;
    const int njt = qt + 9;

    auto loadK = [&](int jt, int buf) {
        const int j0 = jt * 128;
#pragma unroll
        for (int it = 0; it < 2; it++) {
            const int c = tid + it * 512;
            const int row = c >> 3, seg = (c & 7) << 3;
            const __half* g = heads16 + ((size_t)(j0 + row) * BSZ + b) * H3 + DMODEL + n * DHEAD + seg;
            cpa16(ks_b + (uint32_t)((((buf << 7) + row) * KSTR + seg) << 1), g);
        }
        CP_COMMIT();
    };
    auto loadV = [&](int jt) {
        const int j0 = jt * 128;
#pragma unroll
        for (int it = 0; it < 2; it++) {
            const int c = tid + it * 512;
            const int row = c >> 3, seg = (c & 7) << 3;
            const __half* g = heads16 + ((size_t)(j0 + row) * BSZ + b) * H3 + 2 * DMODEL + n * DHEAD + seg;
            cpa16(vs_b + (uint32_t)((row * KSTR + seg) << 1), g);
        }
        CP_COMMIT();
    };

    loadK(0, 0);
    const __half* qb16 = heads16 + (size_t)MEMLEN * BSZ * H3;
#pragma unroll
    for (int it = 0; it < 4; it++) {
        const int idx = tid + it * 512;
        const int row = idx >> 4, c4 = (idx & 15) * 4;
        const __half2* qp = (const __half2*)(qb16 + ((size_t)(i0 + row) * BSZ + b) * H3 + n * DHEAD + c4);
        const float2 q0 = __half22float2(qp[0]);
        const float2 q1 = __half22float2(qp[1]);
        const float4 bb = *(const float4*)(rwb + n * DHEAD + c4);
        *(__half2*)(Qs16 + row * KSTR + c4)     = __floats2half2_rn(q0.x + bb.x, q0.y + bb.y);
        *(__half2*)(Qs16 + row * KSTR + c4 + 2) = __floats2half2_rn(q1.x + bb.z, q1.y + bb.w);
    }
    if (tid < 128) { m_s[tid] = -1e30f; l_s[tid] = 0.f; }

    float accO[2][2][4];
#pragma unroll
    for (int mt = 0; mt < 2; mt++)
#pragma unroll
        for (int nt = 0; nt < 2; nt++)
#pragma unroll
            for (int q = 0; q < 4; q++) accO[mt][nt][q] = 0.f;

    CP_WAIT(0);
    __syncthreads();

    for (int jt = 0; jt < njt; jt++) {
        const int j0 = jt * 128;
        const int cur = jt & 1;
        const bool more = (jt + 1 < njt);

        loadV(jt);
        if (more) loadK(jt + 1, cur ^ 1);

        // ---- S = Qw . K[cur]^T (128x128, K=64 fp16) ----
        float accS[2][4][4];
#pragma unroll
        for (int mt = 0; mt < 2; mt++)
#pragma unroll
            for (int nt = 0; nt < 4; nt++)
#pragma unroll
                for (int q = 0; q < 4; q++) accS[mt][nt][q] = 0.f;

#pragma unroll
        for (int kk = 0; kk < 64; kk += 16) {
            uint32_t af[2][4], bfr[4][2];
#pragma unroll
            for (int mt = 0; mt < 2; mt++) {
                const uint32_t addr = qs_b +
                    (uint32_t)(((wm + mt * 16 + aRow) * KSTR + kk + selOff) << 1);
                LDSM_X4(af[mt][0], af[mt][1], af[mt][2], af[mt][3], addr);
            }
#pragma unroll
            for (int p = 0; p < 2; p++) {
                uint32_t r0, r1, r2, r3;
                const uint32_t addr = ks_b +
                    (uint32_t)(((((cur << 7) + wn + p * 16 + aRow)) * KSTR + kk + selOff) << 1);
                LDSM_X4(r0, r1, r2, r3, addr);
                bfr[2 * p][0] = r0; bfr[2 * p][1] = r2;
                bfr[2 * p + 1][0] = r1; bfr[2 * p + 1][1] = r3;
            }
#pragma unroll
            for (int mt = 0; mt < 2; mt++)
#pragma unroll
                for (int nt = 0; nt < 4; nt++)
                    MMA_F16(accS[mt][nt], af[mt], bfr[nt]);
        }

        // ---- stage raw AC scores to smem (fp32) ----
#pragma unroll
        for (int mt = 0; mt < 2; mt++) {
            const int r0 = wm + mt * 16 + lr;
#pragma unroll
            for (int nt = 0; nt < 4; nt++) {
                const int col = wn + nt * 8 + 2 * lc;
                *(float2*)&Ssf[r0 * SSS + col] =
                    make_float2(accS[mt][nt][0], accS[mt][nt][1]);
                *(float2*)&Ssf[(r0 + 8) * SSS + col] =
                    make_float2(accS[mt][nt][2], accS[mt][nt][3]);
            }
        }
        __syncthreads();

        // ---- softmax: one warp per row; P stored fp16 ----
#pragma unroll 2
        for (int rr = 0; rr < 8; rr++) {
            const int row = warp * 8 + rr;
            const int i = i0 + row;
            const __half* bdp = BD + ((size_t)bn * QLEN + i) * KLEN + (j0 - i + QLEN - 1);
            const int vmax = i + MEMLEN - j0;
            float sv[4];
            float mloc = -1e30f;
#pragma unroll
            for (int k2 = 0; k2 < 4; k2++) {
                const int c = lane + 32 * k2;
                float s = -1e30f;
                if (c <= vmax) s = (Ssf[row * SSS + c] + __half2float(__ldg(bdp + c))) * 0.125f;
                sv[k2] = s;
                mloc = fmaxf(mloc, s);
            }
#pragma unroll
            for (int o = 16; o; o >>= 1)
                mloc = fmaxf(mloc, __shfl_xor_sync(0xffffffffu, mloc, o));
            const float mo = m_s[row];
            const float nm = fmaxf(mo, mloc);
            float lsum = 0.f;
#pragma unroll
            for (int k2 = 0; k2 < 4; k2++) {
                const int c = lane + 32 * k2;
                const float p = __expf(sv[k2] - nm);
                const __half ph = __float2half_rn(p);
                lsum += __half2float(ph);
                Ps16[row * PSTR + c] = ph;
            }
#pragma unroll
            for (int o = 16; o; o >>= 1)
                lsum += __shfl_xor_sync(0xffffffffu, lsum, o);
            if (lane == 0) {
                const float alpha = __expf(mo - nm);
                m_s[row] = nm;
                l_s[row] = l_s[row] * alpha + lsum;
                sc_s[row] = alpha;
            }
        }

        // ---- single barrier: P/stats visible AND V(jt) resident ----
        if (more) { CP_WAIT(1); } else { CP_WAIT(0); }
        __syncthreads();

        // ---- rescale O, then O += P . V ----
#pragma unroll
        for (int mt = 0; mt < 2; mt++) {
            const int r = wm + mt * 16 + lr;
            const float s0 = sc_s[r], s1 = sc_s[r + 8];
#pragma unroll
            for (int nt = 0; nt < 2; nt++) {
                accO[mt][nt][0] *= s0; accO[mt][nt][1] *= s0;
                accO[mt][nt][2] *= s1; accO[mt][nt][3] *= s1;
            }
        }
#pragma unroll
        for (int jj = 0; jj < 128; jj += 16) {
            uint32_t af[2][4], bf[2][2];
#pragma unroll
            for (int mt = 0; mt < 2; mt++) {
                const uint32_t addr = ps_b +
                    (uint32_t)(((wm + mt * 16 + aRow) * PSTR + jj + selOff) << 1);
                LDSM_X4(af[mt][0], af[mt][1], af[mt][2], af[mt][3], addr);
            }
            {
                const uint32_t addr = vs_b +
                    (uint32_t)(((jj + aRow) * KSTR + wn2 + selOff) << 1);
                LDSM_X4T(bf[0][0], bf[0][1], bf[1][0], bf[1][1], addr);
            }
#pragma unroll
            for (int mt = 0; mt < 2; mt++)
#pragma unroll
                for (int nt = 0; nt < 2; nt++)
                    MMA_F16(accO[mt][nt], af[mt], bf[nt]);
        }

        if (more) CP_WAIT(0);
        __syncthreads();
    }

    // ---- finalize ----
#pragma unroll
    for (int mt = 0; mt < 2; mt++) {
        const int r = wm + mt * 16 + lr;
        const float inv0 = 1.f / l_s[r];
        const float inv1 = 1.f / l_s[r + 8];
#pragma unroll
        for (int nt = 0; nt < 2; nt++) {
            const int col = wn2 + nt * 8 + 2 * lc;
            __half2* p0 = (__half2*)(av16 + ((size_t)(i0 + r) * BSZ + b) * DMODEL + n * DHEAD + col);
            *p0 = __floats2half2_rn(accO[mt][nt][0] * inv0, accO[mt][nt][1] * inv0);
            __half2* p1 = (__half2*)(av16 + ((size_t)(i0 + r + 8) * BSZ + b) * DMODEL + n * DHEAD + col);
            *p1 = __floats2half2_rn(accO[mt][nt][2] * inv1, accO[mt][nt][3] * inv1);
        }
    }
}

// ----------------------------------------------------------------------------
__device__ __forceinline__ float warpSum(float v) {
#pragma unroll
    for (int o = 16; o; o >>= 1) v += __shfl_xor_sync(0xffffffffu, v, o);
    return v;
}

__global__ __launch_bounds__(256) void ln_k(
    const float* __restrict__ X, const float* __restrict__ gam,
    const float* __restrict__ bet, float* __restrict__ Y,
    __half* __restrict__ Y16)
{
    __shared__ float red[8];
    const size_t row = blockIdx.x;
    const int tid = threadIdx.x;
    const float4 v = *(const float4*)(X + row * DMODEL + tid * 4);
    float s = v.x + v.y + v.z + v.w;
    float q = v.x * v.x + v.y * v.y + v.z * v.z + v.w * v.w;

    float ws = warpSum(s);
    if ((tid & 31) == 0) red[tid >> 5] = ws;
    __syncthreads();
    if (tid < 32) {
        float t = (tid < 8) ? red[tid] : 0.f;
        t = warpSum(t);
        if (tid == 0) red[0] = t;
    }
    __syncthreads();
    const float mu = red[0] * (1.f / DMODEL);
    __syncthreads();

    float wq = warpSum(q);
    if ((tid & 31) == 0) red[tid >> 5] = wq;
    __syncthreads();
    if (tid < 32) {
        float t = (tid < 8) ? red[tid] : 0.f;
        t = warpSum(t);
        if (tid == 0) red[0] = t;
    }
    __syncthreads();
    const float var = red[0] * (1.f / DMODEL) - mu * mu;
    const float rs = rsqrtf(var + 1e-5f);

    const float4 gv = *(const float4*)(gam + tid * 4);
    const float4 bv = *(const float4*)(bet + tid * 4);
    float4 o;
    o.x = (v.x - mu) * rs * gv.x + bv.x;
    o.y = (v.y - mu) * rs * gv.y + bv.y;
    o.z = (v.z - mu) * rs * gv.z + bv.z;
    o.w = (v.w - mu) * rs * gv.w + bv.w;
    *(float4*)(Y + row * DMODEL + tid * 4) = o;
    if (Y16) {
        __half2 h[2] = { __floats2half2_rn(o.x, o.y), __floats2half2_rn(o.z, o.w) };
        *(uint2*)(Y16 + row * DMODEL + tid * 4) = *(uint2*)h;
    }
}

// ----------------------------------------------------------------------------
extern "C" void kernel_launch(void* const* d_in, const int* in_sizes, int n_in,
                              void* d_out, int out_size)
{
    (void)in_sizes; (void)n_in; (void)out_size;
    const float* w       = (const float*)d_in[0];
    const float* r       = (const float*)d_in[1];
    const float* mems    = (const float*)d_in[2];
    const float* qkv_w   = (const float*)d_in[3];
    const float* r_net_w = (const float*)d_in[4];
    const float* o_w     = (const float*)d_in[5];
    const float* rwb     = (const float*)d_in[6];
    const float* rrb     = (const float*)d_in[7];
    const float* ln1g    = (const float*)d_in[8];
    const float* ln1b    = (const float*)d_in[9];
    const float* ffw1    = (const float*)d_in[10];
    const float* ffb1    = (const float*)d_in[11];
    const float* ffw2    = (const float*)d_in[12];
    const float* ffb2    = (const float*)d_in[13];
    const float* ln2g    = (const float*)d_in[14];
    const float* ln2b    = (const float*)d_in[15];
    float* out = (float*)d_out;

    float *rk, *rbias, *tmp, *out1;
    __half *heads16, *rk16, *BD, *av16, *out116, *ffh16;
    __half *cat16, *r16, *qkvw16, *rnw16, *ow16, *ffw116, *ffw216;
    cudaGetSymbolAddress((void**)&heads16, g_heads16);
    cudaGetSymbolAddress((void**)&rk,      g_rk);
    cudaGetSymbolAddress((void**)&rk16,    g_rk16);
    cudaGetSymbolAddress((void**)&rbias,   g_rbias);
    cudaGetSymbolAddress((void**)&BD,      g_BD);
    cudaGetSymbolAddress((void**)&av16,    g_av16);
    cudaGetSymbolAddress((void**)&tmp,     g_tmp);
    cudaGetSymbolAddress((void**)&out1,    g_out1);
    cudaGetSymbolAddress((void**)&out116,  g_out116);
    cudaGetSymbolAddress((void**)&ffh16,   g_ffh16);
    cudaGetSymbolAddress((void**)&cat16,   g_cat16);
    cudaGetSymbolAddress((void**)&r16,     g_r16);
    cudaGetSymbolAddress((void**)&qkvw16,  g_qkvw16);
    cudaGetSymbolAddress((void**)&rnw16,   g_rnw16);
    cudaGetSymbolAddress((void**)&ow16,    g_ow16);
    cudaGetSymbolAddress((void**)&ffw116,  g_ffw116);
    cudaGetSymbolAddress((void**)&ffw216,  g_ffw216);

    static int s_attr_done = 0;
    if (!s_attr_done) {
        cudaFuncSetAttribute(flash_k, cudaFuncAttributeMaxDynamicSharedMemorySize,
                             FLASH_SMEM);
        s_attr_done = 1;
    }

    const dim3 blk(256);
    const __half* qb16 = heads16 + (size_t)MEMLEN * BSZ * H3;  // query rows

    // 0) fp32 -> fp16 conversions
    cvt_k<<<(MEMLEN * BSZ * DMODEL) / 2048, blk>>>(mems, cat16);
    cvt_k<<<(QLEN * BSZ * DMODEL) / 2048, blk>>>(w, cat16 + (size_t)MEMLEN * BSZ * DMODEL);
    cvt_k<<<(KLEN * DMODEL) / 2048, blk>>>(r, r16);
    cvt_k<<<(DMODEL * H3) / 2048, blk>>>(qkv_w, qkvw16);
    cvt_k<<<(DMODEL * DMODEL) / 2048, blk>>>(r_net_w, rnw16);
    cvt_k<<<(DMODEL * DMODEL) / 2048, blk>>>(o_w, ow16);
    cvt_k<<<(DMODEL * DINNER) / 2048, blk>>>(ffw1, ffw116);
    cvt_k<<<(DINNER * DMODEL) / 2048, blk>>>(ffw2, ffw216);

    // 1) heads16 = cat16 @ qkvw16 (pure fp16 out)
    gemm_h<1><<<dim3(H3 / 128, (KLEN * BSZ) / 128), blk>>>(
        cat16, DMODEL, qkvw16, nullptr, nullptr, 0,
        heads16, nullptr, KLEN * BSZ, H3, DMODEL);

    // 2) rk = r16 @ rnw16 (fp32 + fp16 dual out)
    gemm_h<2><<<dim3(DMODEL / 128, KLEN / 128), blk>>>(
        r16, DMODEL, rnw16, nullptr, nullptr, 0,
        rk, rk16, KLEN, DMODEL, DMODEL);

    // 3) rbias
    rbias_k<<<(NHEAD * KLEN) / 256, blk>>>(rrb, rk, rbias);

    // 4) BD (fp16 MMAs, fp16 out, diag skip)
    bd16_gemm<<<dim3(KLEN / 128, QLEN / 128, BSZ * NHEAD), blk>>>(
        qb16, rk16, rbias, BD);

    // 5) flash (fp16 MMAs) -> av16
    flash_k<<<dim3(QLEN / 128, BSZ * NHEAD), dim3(512), FLASH_SMEM>>>(
        heads16, BD, rwb, av16);

    // 6) attn_out = av16 @ ow16 + w
    gemm_h<0><<<dim3(DMODEL / 128, (QLEN * BSZ) / 128), blk>>>(
        av16, DMODEL, ow16, nullptr, w, 0,
        tmp, nullptr, QLEN * BSZ, DMODEL, DMODEL);

    // 7) LN1 (dual fp32 + fp16)
    ln_k<<<QLEN * BSZ, blk>>>(tmp, ln1g, ln1b, out1, out116);

    // 8) ffh16 = relu(out116 @ ffw116 + b1) (fp16 out)
    gemm_h<1><<<dim3(DINNER / 128, (QLEN * BSZ) / 128), blk>>>(
        out116, DMODEL, ffw116, ffb1, nullptr, 1,
        ffh16, nullptr, QLEN * BSZ, DINNER, DMODEL);

    // 9) tmp = ffh16 @ ffw216 + b2 + out1
    gemm_h<0><<<dim3(DMODEL / 128, (QLEN * BSZ) / 128), blk>>>(
        ffh16, DINNER, ffw216, ffb2, out1, 0,
        tmp, nullptr, QLEN * BSZ, DMODEL, DINNER);

    // 10) LN2 -> output
    ln_k<<<QLEN * BSZ, blk>>>(tmp, ln2g, ln2b, out, nullptr);
}

// round 12
// speedup vs baseline: 2.4378x; 1.0666x over previous
#include <cuda_runtime.h>
#include <cuda_fp16.h>
#include <math.h>
#include <stdint.h>

#define QLEN   1024
#define BSZ    4
#define DMODEL 1024
#define NHEAD  16
#define DHEAD  64
#define DINNER 4096
#define MEMLEN 1024
#define KLEN   2048
#define H3     (3 * DMODEL)   // 3072

// ---- static device scratch (no cudaMalloc allowed) ----
__device__ __half g_heads16[(size_t)KLEN * BSZ * H3];        // fp16 QKV heads
__device__ float  g_rk[(size_t)KLEN * DMODEL];               // fp32 (for rbias)
__device__ __half g_rk16[(size_t)KLEN * DMODEL];             // fp16 (for bd16)
__device__ float  g_rbias[(size_t)NHEAD * KLEN];
__device__ __half g_BD[(size_t)BSZ * NHEAD * QLEN * KLEN];   // j-indexed BDr
__device__ __half g_av16[(size_t)QLEN * BSZ * DMODEL];
__device__ float  g_tmp[(size_t)QLEN * BSZ * DMODEL];
__device__ float  g_out1[(size_t)QLEN * BSZ * DMODEL];
__device__ __half g_out116[(size_t)QLEN * BSZ * DMODEL];
__device__ __half g_ffh16[(size_t)QLEN * BSZ * DINNER];
__device__ __half g_cat16[(size_t)KLEN * BSZ * DMODEL];
__device__ __half g_r16[(size_t)KLEN * DMODEL];
__device__ __half g_qkvw16[(size_t)DMODEL * H3];
__device__ __half g_rnw16[(size_t)DMODEL * DMODEL];
__device__ __half g_ow16[(size_t)DMODEL * DMODEL];
__device__ __half g_ffw116[(size_t)DMODEL * DINNER];
__device__ __half g_ffw216[(size_t)DINNER * DMODEL];

__device__ __forceinline__ void cpa16(uint32_t s, const void* g) {
    asm volatile("cp.async.cg.shared.global [%0], [%1], 16;" :: "r"(s), "l"(g));
}
#define CP_COMMIT() asm volatile("cp.async.commit_group;")
#define CP_WAIT(N)  asm volatile("cp.async.wait_group %0;" :: "n"(N))

#define MMA_F16(acc, av, bv)                                                \
    asm volatile(                                                           \
        "mma.sync.aligned.m16n8k16.row.col.f32.f16.f16.f32 "                \
        "{%0,%1,%2,%3}, {%4,%5,%6,%7}, {%8,%9}, {%0,%1,%2,%3};"             \
        : "+f"(acc[0]), "+f"(acc[1]), "+f"(acc[2]), "+f"(acc[3])            \
        : "r"(av[0]), "r"(av[1]), "r"(av[2]), "r"(av[3]),                   \
          "r"(bv[0]), "r"(bv[1]))

#define LDSM_X4(r0, r1, r2, r3, addr)                                       \
    asm volatile("ldmatrix.sync.aligned.m8n8.x4.shared.b16 {%0,%1,%2,%3}, [%4];" \
        : "=r"(r0), "=r"(r1), "=r"(r2), "=r"(r3) : "r"(addr))
#define LDSM_X4T(r0, r1, r2, r3, addr)                                      \
    asm volatile("ldmatrix.sync.aligned.m8n8.x4.trans.shared.b16 {%0,%1,%2,%3}, [%4];" \
        : "=r"(r0), "=r"(r1), "=r"(r2), "=r"(r3) : "r"(addr))

// ----------------------------------------------------------------------------
__global__ __launch_bounds__(256) void cvt_k(
    const float* __restrict__ src, __half* __restrict__ dst)
{
    const int i = (blockIdx.x * 256 + threadIdx.x) * 8;
    const float4 a = *(const float4*)(src + i);
    const float4 b = *(const float4*)(src + i + 4);
    __half2 h[4];
    h[0] = __floats2half2_rn(a.x, a.y);
    h[1] = __floats2half2_rn(a.z, a.w);
    h[2] = __floats2half2_rn(b.x, b.y);
    h[3] = __floats2half2_rn(b.z, b.w);
    *(uint4*)(dst + i) = *(uint4*)h;
}

// ----------------------------------------------------------------------------
// Dense fp16 GEMM. HOUT=0: fp32 out. HOUT=1: fp16 out. HOUT=2: fp32+fp16 dual.
// ----------------------------------------------------------------------------
#define ASTR 40
#define BSTR 136

template <int HOUT>
__global__ __launch_bounds__(256, 2) void gemm_h(
    const __half* __restrict__ A, int lda,
    const __half* __restrict__ B,
    const float* __restrict__ bias, const float* __restrict__ resid, int doRelu,
    void* __restrict__ Cv, __half* __restrict__ C16,
    int M, int N, int Kd)
{
    __shared__ __half As[3][128 * ASTR];
    __shared__ __half Bs[3][32 * BSTR];

    const int tid  = threadIdx.x;
    const int warp = tid >> 5, lane = tid & 31;
    const int lr = lane >> 2, lc = lane & 3;
    const int bm = blockIdx.y * 128, bn = blockIdx.x * 128;
    const int wm = (warp & 1) * 64;
    const int wn = (warp >> 1) * 32;

    float acc[4][4][4];
#pragma unroll
    for (int mt = 0; mt < 4; mt++)
#pragma unroll
        for (int nt = 0; nt < 4; nt++)
#pragma unroll
            for (int q = 0; q < 4; q++) acc[mt][nt][q] = 0.f;

    const __half* aPtr[2];
    const __half* bPtr[2];
    uint32_t aDst[2], bDst[2];
#pragma unroll
    for (int h = 0; h < 2; h++) {
        const int ch = tid + h * 256;
        const int ar = ch >> 2, ao = (ch & 3) * 8;
        aPtr[h] = A + (long long)(bm + ar) * lda + ao;
        aDst[h] = (uint32_t)__cvta_generic_to_shared(&As[0][ar * ASTR + ao]);
        const int br = ch >> 4, bo = (ch & 15) * 8;
        bPtr[h] = B + (long long)br * N + bn + bo;
        bDst[h] = (uint32_t)__cvta_generic_to_shared(&Bs[0][br * BSTR + bo]);
    }
    const long long bStep = (long long)32 * N;

    auto load = [&](int kt, int s) {
#pragma unroll
        for (int h = 0; h < 2; h++)
            cpa16(aDst[h] + s * 128 * ASTR * 2, aPtr[h] + kt * 32);
#pragma unroll
        for (int h = 0; h < 2; h++)
            cpa16(bDst[h] + s * 32 * BSTR * 2, bPtr[h] + kt * bStep);
    };

    const int aRow = lane & 15;
    const int selOff = (lane >> 4) << 3;
    const uint32_t asBase = (uint32_t)__cvta_generic_to_shared(&As[0][0]);
    const uint32_t bsBase = (uint32_t)__cvta_generic_to_shared(&Bs[0][0]);

    const int nk = Kd >> 5;
    load(0, 0); CP_COMMIT();
    load(1, 1); CP_COMMIT();

    for (int kt = 0; kt < nk; kt++) {
        const int s = kt % 3;
        CP_WAIT(1);
        __syncthreads();
        if (kt + 2 < nk) load(kt + 2, (kt + 2) % 3);
        CP_COMMIT();

        const uint32_t aS = asBase + (uint32_t)(s * 128 * ASTR * 2);
        const uint32_t bS = bsBase + (uint32_t)(s * 32 * BSTR * 2);
#pragma unroll
        for (int kk = 0; kk < 32; kk += 16) {
            uint32_t af[4][4], bf[4][2];
#pragma unroll
            for (int mt = 0; mt < 4; mt++) {
                const uint32_t addr = aS +
                    (uint32_t)(((wm + mt * 16 + aRow) * ASTR + kk + selOff) * 2);
                LDSM_X4(af[mt][0], af[mt][1], af[mt][2], af[mt][3], addr);
            }
#pragma unroll
            for (int ntp = 0; ntp < 2; ntp++) {
                const uint32_t addr = bS +
                    (uint32_t)(((kk + aRow) * BSTR + wn + ntp * 16 + selOff) * 2);
                LDSM_X4T(bf[2 * ntp][0], bf[2 * ntp][1],
                         bf[2 * ntp + 1][0], bf[2 * ntp + 1][1], addr);
            }
#pragma unroll
            for (int mt = 0; mt < 4; mt++)
#pragma unroll
                for (int nt = 0; nt < 4; nt++)
                    MMA_F16(acc[mt][nt], af[mt], bf[nt]);
        }
    }

#pragma unroll
    for (int mt = 0; mt < 4; mt++) {
#pragma unroll
        for (int nt = 0; nt < 4; nt++) {
            const int col = bn + wn + nt * 8 + lc * 2;
#pragma unroll
            for (int half = 0; half < 2; half++) {
                const int row = bm + wm + mt * 16 + lr + half * 8;
                float v0 = acc[mt][nt][half * 2 + 0];
                float v1 = acc[mt][nt][half * 2 + 1];
                if (bias) { v0 += bias[col]; v1 += bias[col + 1]; }
                if (resid) {
                    const float* rp = resid + (long long)row * N + col;
                    v0 += rp[0]; v1 += rp[1];
                }
                if (doRelu) { v0 = fmaxf(v0, 0.f); v1 = fmaxf(v1, 0.f); }
                if (HOUT == 1) {
                    *(__half2*)((__half*)Cv + (long long)row * N + col) =
                        __floats2half2_rn(v0, v1);
                } else {
                    float* cp = (float*)Cv + (long long)row * N + col;
                    cp[0] = v0; cp[1] = v1;
                    if (HOUT == 2)
                        *(__half2*)(C16 + (long long)row * N + col) =
                            __floats2half2_rn(v0, v1);
                }
            }
        }
    }
}

// ----------------------------------------------------------------------------
__global__ __launch_bounds__(256) void rbias_k(
    const float* __restrict__ rrb, const float* __restrict__ rk,
    float* __restrict__ rbias)
{
    const int idx = blockIdx.x * 256 + threadIdx.x;
    const int c = idx >> 4, n = idx & 15;
    const float* rp = rk + (size_t)c * DMODEL + n * DHEAD;
    const float* bp = rrb + n * DHEAD;
    float s = 0.f;
#pragma unroll
    for (int d = 0; d < DHEAD; d++) s += rp[d] * bp[d];
    rbias[n * KLEN + c] = s;
}

// ----------------------------------------------------------------------------
// BD GEMM fp16, j-indexed output: BDr[bn][i][j] = q_i . rk_{j-i+1023} + rbias.
// Epilogue applies the rel-shift: element (i, c) stored at j = c + i - 1023.
// ----------------------------------------------------------------------------
#define BDSTR 72

__global__ __launch_bounds__(256, 2) void bd16_gemm(
    const __half* __restrict__ Q16,   // query rows of g_heads16
    const __half* __restrict__ RK16,
    const float* __restrict__ rbias, __half* __restrict__ BD)
{
    __shared__ __half As[128 * BDSTR];
    __shared__ __half Bs[128 * BDSTR];

    const int tid = threadIdx.x;
    const int warp = tid >> 5, lane = tid & 31;
    const int lr = lane >> 2, lc = lane & 3;
    const int bm = blockIdx.y * 128, bn = blockIdx.x * 128;
    if (bm + bn < 769) return;   // whole tile lands at j < 0, never read
    const int bnidx = blockIdx.z;
    const int b = bnidx >> 4, n = bnidx & 15;
    const int wm = (warp & 1) * 64;
    const int wn = (warp >> 1) * 32;
    const int aRow = lane & 15;
    const int selOff = (lane >> 4) << 3;
    const uint32_t as_b = (uint32_t)__cvta_generic_to_shared(As);
    const uint32_t bs_b = (uint32_t)__cvta_generic_to_shared(Bs);

#pragma unroll
    for (int h = 0; h < 4; h++) {
        const int ch = tid + h * 256;
        const int row = ch >> 3, seg = (ch & 7) * 8;
        const __half* ga = Q16 + ((size_t)(bm + row) * BSZ + b) * H3 + n * DHEAD + seg;
        cpa16(as_b + (uint32_t)((row * BDSTR + seg) << 1), ga);
    }
#pragma unroll
    for (int h = 0; h < 4; h++) {
        const int ch = tid + h * 256;
        const int row = ch >> 3, seg = (ch & 7) * 8;
        const __half* gb = RK16 + (size_t)(bn + row) * DMODEL + n * DHEAD + seg;
        cpa16(bs_b + (uint32_t)((row * BDSTR + seg) << 1), gb);
    }
    CP_COMMIT();

    float acc[4][4][4];
#pragma unroll
    for (int mt = 0; mt < 4; mt++)
#pragma unroll
        for (int nt = 0; nt < 4; nt++)
#pragma unroll
            for (int q = 0; q < 4; q++) acc[mt][nt][q] = 0.f;

    CP_WAIT(0);
    __syncthreads();

#pragma unroll
    for (int kk = 0; kk < 64; kk += 16) {
        uint32_t af[4][4], bfr[4][2];
#pragma unroll
        for (int mt = 0; mt < 4; mt++) {
            const uint32_t addr = as_b +
                (uint32_t)(((wm + mt * 16 + aRow) * BDSTR + kk + selOff) << 1);
            LDSM_X4(af[mt][0], af[mt][1], af[mt][2], af[mt][3], addr);
        }
#pragma unroll
        for (int p = 0; p < 2; p++) {
            uint32_t r0, r1, r2, r3;
            const uint32_t addr = bs_b +
                (uint32_t)(((wn + p * 16 + aRow) * BDSTR + kk + selOff) << 1);
            LDSM_X4(r0, r1, r2, r3, addr);
            bfr[2 * p][0] = r0; bfr[2 * p][1] = r2;
            bfr[2 * p + 1][0] = r1; bfr[2 * p + 1][1] = r3;
        }
#pragma unroll
        for (int mt = 0; mt < 4; mt++)
#pragma unroll
            for (int nt = 0; nt < 4; nt++)
                MMA_F16(acc[mt][nt], af[mt], bfr[nt]);
    }

    // epilogue: + rbias, rel-shifted fp16 store (j = c + i - 1023)
#pragma unroll
    for (int mt = 0; mt < 4; mt++) {
#pragma unroll
        for (int nt = 0; nt < 4; nt++) {
            const int col = bn + wn + nt * 8 + lc * 2;
            const float rb0 = rbias[n * KLEN + col];
            const float rb1 = rbias[n * KLEN + col + 1];
#pragma unroll
            for (int half = 0; half < 2; half++) {
                const int row = bm + wm + mt * 16 + lr + half * 8;
                const float v0 = acc[mt][nt][half * 2 + 0] + rb0;
                const float v1 = acc[mt][nt][half * 2 + 1] + rb1;
                __half* rowp = BD + ((size_t)bnidx * QLEN + row) * KLEN;
                const int j = col + row - (QLEN - 1);
                if (j >= 0)     rowp[j]     = __float2half_rn(v0);
                if (j + 1 >= 0) rowp[j + 1] = __float2half_rn(v1);
            }
        }
    }
}

// ----------------------------------------------------------------------------
// Flash attention v5 (FA2-style): register-resident P, 512 threads / 16 warps
// = 8 row-groups x 2 col-halves. Warp tile: S 16x64, O 16x64 (partial, summed
// across col-halves at the end). BD loaded as aligned j-indexed tiles.
// ----------------------------------------------------------------------------
#define KSTR  72
#define BDF   136
#define OSTR  72
#define FLASH_SMEM (128*KSTR*2 /*Q*/ + 2*128*KSTR*2 /*K*/ + 128*KSTR*2 /*V*/ \
                    + 128*BDF*2 /*Bd*/ + 2*128*4 /*pmax*/ + 2*128*4 /*psum*/)

__global__ __launch_bounds__(512, 1) void flash_k(
    const __half* __restrict__ heads16,
    const __half* __restrict__ BD,
    const float* __restrict__ rwb, __half* __restrict__ av16)
{
    extern __shared__ char smc[];
    __half* Qs16 = (__half*)smc;                  // 128*72
    __half* Ks16 = Qs16 + 128 * KSTR;             // 2*128*72 (reused as Osum at end)
    __half* Vs16 = Ks16 + 2 * 128 * KSTR;         // 128*72
    __half* Bds  = Vs16 + 128 * KSTR;             // 128*136
    float*  pmax = (float*)(Bds + 128 * BDF);     // [2][128]
    float*  psum = pmax + 2 * 128;                // [2][128]
    float*  Osum = (float*)Ks16;                  // 128*72 floats (fits in K region)
    const uint32_t qs_b = (uint32_t)__cvta_generic_to_shared(Qs16);
    const uint32_t ks_b = (uint32_t)__cvta_generic_to_shared(Ks16);
    const uint32_t vs_b = (uint32_t)__cvta_generic_to_shared(Vs16);
    const uint32_t bd_b = (uint32_t)__cvta_generic_to_shared(Bds);

    const int tid = threadIdx.x;
    const int warp = tid >> 5, lane = tid & 31;
    const int lr = lane >> 2, lc = lane & 3;
    const int aRow = lane & 15;
    const int selOff = (lane >> 4) << 3;
    const int qt = (int)gridDim.x - 1 - (int)blockIdx.x;   // longest-first
    const int i0 = qt * 128;
    const int bn = blockIdx.y;
    const int b = bn >> 4, n = bn & 15;
    const int rg  = warp & 7;           // row group
    const int chh = warp >> 3;          // col half (0/1)
    const int wm  = rg * 16;
    const int njt = qt + 9;

    auto loadK = [&](int jt, int buf) {
        const int j0 = jt * 128;
#pragma unroll
        for (int it = 0; it < 2; it++) {
            const int c = tid + it * 512;
            const int row = c >> 3, seg = (c & 7) << 3;
            const __half* g = heads16 + ((size_t)(j0 + row) * BSZ + b) * H3 + DMODEL + n * DHEAD + seg;
            cpa16(ks_b + (uint32_t)((((buf << 7) + row) * KSTR + seg) << 1), g);
        }
    };
    auto loadV = [&](int jt) {
        const int j0 = jt * 128;
#pragma unroll
        for (int it = 0; it < 2; it++) {
            const int c = tid + it * 512;
            const int row = c >> 3, seg = (c & 7) << 3;
            const __half* g = heads16 + ((size_t)(j0 + row) * BSZ + b) * H3 + 2 * DMODEL + n * DHEAD + seg;
            cpa16(vs_b + (uint32_t)((row * KSTR + seg) << 1), g);
        }
    };
    auto loadBd = [&](int jt) {
        const int j0 = jt * 128;
#pragma unroll
        for (int it = 0; it < 4; it++) {
            const int c = tid + it * 512;
            const int row = c >> 4, seg = (c & 15) << 3;
            const __half* g = BD + ((size_t)bn * QLEN + i0 + row) * KLEN + j0 + seg;
            cpa16(bd_b + (uint32_t)((row * BDF + seg) << 1), g);
        }
    };

    // ---- prologue: K(0), Q(+rwb) to smem, init stats ----
    loadK(0, 0); CP_COMMIT();
    const __half* qb16 = heads16 + (size_t)MEMLEN * BSZ * H3;
#pragma unroll
    for (int it = 0; it < 4; it++) {
        const int idx = tid + it * 512;
        const int row = idx >> 4, c4 = (idx & 15) * 4;
        const __half2* qp = (const __half2*)(qb16 + ((size_t)(i0 + row) * BSZ + b) * H3 + n * DHEAD + c4);
        const float2 q0 = __half22float2(qp[0]);
        const float2 q1 = __half22float2(qp[1]);
        const float4 bb = *(const float4*)(rwb + n * DHEAD + c4);
        *(__half2*)(Qs16 + row * KSTR + c4)     = __floats2half2_rn(q0.x + bb.x, q0.y + bb.y);
        *(__half2*)(Qs16 + row * KSTR + c4 + 2) = __floats2half2_rn(q1.x + bb.z, q1.y + bb.w);
    }

    // per-thread (redundant per row) online-softmax state for rows lr, lr+8
    float m0 = -1e30f, m1 = -1e30f, l0 = 0.f, l1 = 0.f;

    float accO[8][4];
#pragma unroll
    for (int nt = 0; nt < 8; nt++)
#pragma unroll
        for (int q = 0; q < 4; q++) accO[nt][q] = 0.f;

    CP_WAIT(0);
    __syncthreads();

    for (int jt = 0; jt < njt; jt++) {
        const int j0 = jt * 128;
        const int cur = jt & 1;
        const bool more = (jt + 1 < njt);

        loadV(jt); loadBd(jt); CP_COMMIT();           // group A
        if (more) { loadK(jt + 1, cur ^ 1); CP_COMMIT(); }  // group B

        // ---- S = Qw . K^T : warp tile 16 rows x 64 cols ----
        float accS[8][4];
#pragma unroll
        for (int nt = 0; nt < 8; nt++)
#pragma unroll
            for (int q = 0; q < 4; q++) accS[nt][q] = 0.f;

#pragma unroll
        for (int kk = 0; kk < 64; kk += 16) {
            uint32_t af[4], bfr[8][2];
            {
                const uint32_t addr = qs_b +
                    (uint32_t)(((wm + aRow) * KSTR + kk + selOff) << 1);
                LDSM_X4(af[0], af[1], af[2], af[3], addr);
            }
#pragma unroll
            for (int p = 0; p < 4; p++) {
                uint32_t r0, r1, r2, r3;
                const uint32_t addr = ks_b +
                    (uint32_t)((((cur << 7) + chh * 64 + p * 16 + aRow) * KSTR + kk + selOff) << 1);
                LDSM_X4(r0, r1, r2, r3, addr);
                bfr[2 * p][0] = r0; bfr[2 * p][1] = r2;
                bfr[2 * p + 1][0] = r1; bfr[2 * p + 1][1] = r3;
            }
#pragma unroll
            for (int nt = 0; nt < 8; nt++)
                MMA_F16(accS[nt], af, bfr[nt]);
        }

        // ---- wait Bd+V, then in-register softmax ----
        if (more) { CP_WAIT(1); } else { CP_WAIT(0); }
        __syncthreads();   // Bd/V visible; pmax/psum reusable

        // add BD + mask + scale; partial row max
        const int dcol = j0 + chh * 64 - (i0 + wm);      // j - i = dcol + cl - lr
        const int lim0 = lr + MEMLEN - dcol;             // valid: cl <= lim0 (row lr)
        const int lim1 = lim0 + 8;                       // row lr+8
        float mx0 = -1e30f, mx1 = -1e30f;
#pragma unroll
        for (int nt = 0; nt < 8; nt++) {
            const int cl = nt * 8 + 2 * lc;
            const float2 b0 = __half22float2(*(const __half2*)&Bds[(wm + lr) * BDF + chh * 64 + nt * 8 + 2 * lc]);
            const float2 b1 = __half22float2(*(const __half2*)&Bds[(wm + lr + 8) * BDF + chh * 64 + nt * 8 + 2 * lc]);
            accS[nt][0] = (cl     <= lim0) ? (accS[nt][0] + b0.x) * 0.125f : -1e30f;
            accS[nt][1] = (cl + 1 <= lim0) ? (accS[nt][1] + b0.y) * 0.125f : -1e30f;
            accS[nt][2] = (cl     <= lim1) ? (accS[nt][2] + b1.x) * 0.125f : -1e30f;
            accS[nt][3] = (cl + 1 <= lim1) ? (accS[nt][3] + b1.y) * 0.125f : -1e30f;
            mx0 = fmaxf(mx0, fmaxf(accS[nt][0], accS[nt][1]));
            mx1 = fmaxf(mx1, fmaxf(accS[nt][2], accS[nt][3]));
        }
#pragma unroll
        for (int o = 1; o <= 2; o <<= 1) {
            mx0 = fmaxf(mx0, __shfl_xor_sync(0xffffffffu, mx0, o));
            mx1 = fmaxf(mx1, __shfl_xor_sync(0xffffffffu, mx1, o));
        }
        if (lc == 0) {
            pmax[chh * 128 + wm + lr] = mx0;
            pmax[chh * 128 + wm + lr + 8] = mx1;
        }
        __syncthreads();

        const float nm0 = fmaxf(m0, fmaxf(pmax[wm + lr], pmax[128 + wm + lr]));
        const float nm1 = fmaxf(m1, fmaxf(pmax[wm + lr + 8], pmax[128 + wm + lr + 8]));

        // exp (in-register), pack P to fp16 A-fragments, partial row sums
        uint32_t pLo[8], pHi[8];
        float ls0 = 0.f, ls1 = 0.f;
#pragma unroll
        for (int nt = 0; nt < 8; nt++) {
            const __half2 h0 = __floats2half2_rn(__expf(accS[nt][0] - nm0),
                                                 __expf(accS[nt][1] - nm0));
            const __half2 h1 = __floats2half2_rn(__expf(accS[nt][2] - nm1),
                                                 __expf(accS[nt][3] - nm1));
            pLo[nt] = *(const uint32_t*)&h0;
            pHi[nt] = *(const uint32_t*)&h1;
            const float2 f0 = __half22float2(h0);
            const float2 f1 = __half22float2(h1);
            ls0 += f0.x + f0.y;
            ls1 += f1.x + f1.y;
        }
#pragma unroll
        for (int o = 1; o <= 2; o <<= 1) {
            ls0 += __shfl_xor_sync(0xffffffffu, ls0, o);
            ls1 += __shfl_xor_sync(0xffffffffu, ls1, o);
        }
        if (lc == 0) {
            psum[chh * 128 + wm + lr] = ls0;
            psum[chh * 128 + wm + lr + 8] = ls1;
        }
        __syncthreads();

        const float lt0 = psum[wm + lr] + psum[128 + wm + lr];
        const float lt1 = psum[wm + lr + 8] + psum[128 + wm + lr + 8];
        const float a0 = __expf(m0 - nm0);
        const float a1 = __expf(m1 - nm1);
        m0 = nm0; m1 = nm1;
        l0 = l0 * a0 + lt0;
        l1 = l1 * a1 + lt1;

        // ---- rescale O, then O += P . V (P from registers) ----
#pragma unroll
        for (int nt = 0; nt < 8; nt++) {
            accO[nt][0] *= a0; accO[nt][1] *= a0;
            accO[nt][2] *= a1; accO[nt][3] *= a1;
        }
#pragma unroll
        for (int p = 0; p < 4; p++) {        // k-blocks of 16 within this j-half
            uint32_t af[4];
            af[0] = pLo[2 * p];     af[1] = pHi[2 * p];
            af[2] = pLo[2 * p + 1]; af[3] = pHi[2 * p + 1];
            uint32_t bf[8][2];
#pragma unroll
            for (int nb = 0; nb < 4; nb++) {  // O cols in blocks of 16
                const uint32_t addr = vs_b +
                    (uint32_t)(((chh * 64 + p * 16 + aRow) * KSTR + nb * 16 + selOff) << 1);
                LDSM_X4T(bf[2 * nb][0], bf[2 * nb][1],
                         bf[2 * nb + 1][0], bf[2 * nb + 1][1], addr);
            }
#pragma unroll
            for (int nt = 0; nt < 8; nt++)
                MMA_F16(accO[nt], af, bf[nt]);
        }

        if (more) CP_WAIT(0);
        __syncthreads();   // K(jt+1) resident; V/Bd reads done before overwrite
    }

    // ---- finalize: sum col-half partials through smem, write av16 ----
    if (chh == 1) {
#pragma unroll
        for (int nt = 0; nt < 8; nt++) {
            const int col = nt * 8 + 2 * lc;
            *(float2*)&Osum[(wm + lr) * OSTR + col] =
                make_float2(accO[nt][0], accO[nt][1]);
            *(float2*)&Osum[(wm + lr + 8) * OSTR + col] =
                make_float2(accO[nt][2], accO[nt][3]);
        }
    }
    __syncthreads();
    if (chh == 0) {
        const float inv0 = 1.f / l0;
        const float inv1 = 1.f / l1;
#pragma unroll
        for (int nt = 0; nt < 8; nt++) {
            const int col = nt * 8 + 2 * lc;
            const float2 s0 = *(const float2*)&Osum[(wm + lr) * OSTR + col];
            const float2 s1 = *(const float2*)&Osum[(wm + lr + 8) * OSTR + col];
            __half2* p0 = (__half2*)(av16 + ((size_t)(i0 + wm + lr) * BSZ + b) * DMODEL + n * DHEAD + col);
            *p0 = __floats2half2_rn((accO[nt][0] + s0.x) * inv0,
                                    (accO[nt][1] + s0.y) * inv0);
            __half2* p1 = (__half2*)(av16 + ((size_t)(i0 + wm + lr + 8) * BSZ + b) * DMODEL + n * DHEAD + col);
            *p1 = __floats2half2_rn((accO[nt][2] + s1.x) * inv1,
                                    (accO[nt][3] + s1.y) * inv1);
        }
    }
}

// ----------------------------------------------------------------------------
__device__ __forceinline__ float warpSum(float v) {
#pragma unroll
    for (int o = 16; o; o >>= 1) v += __shfl_xor_sync(0xffffffffu, v, o);
    return v;
}

__global__ __launch_bounds__(256) void ln_k(
    const float* __restrict__ X, const float* __restrict__ gam,
    const float* __restrict__ bet, float* __restrict__ Y,
    __half* __restrict__ Y16)
{
    __shared__ float red[8];
    const size_t row = blockIdx.x;
    const int tid = threadIdx.x;
    const float4 v = *(const float4*)(X + row * DMODEL + tid * 4);
    float s = v.x + v.y + v.z + v.w;
    float q = v.x * v.x + v.y * v.y + v.z * v.z + v.w * v.w;

    float ws = warpSum(s);
    if ((tid & 31) == 0) red[tid >> 5] = ws;
    __syncthreads();
    if (tid < 32) {
        float t = (tid < 8) ? red[tid] : 0.f;
        t = warpSum(t);
        if (tid == 0) red[0] = t;
    }
    __syncthreads();
    const float mu = red[0] * (1.f / DMODEL);
    __syncthreads();

    float wq = warpSum(q);
    if ((tid & 31) == 0) red[tid >> 5] = wq;
    __syncthreads();
    if (tid < 32) {
        float t = (tid < 8) ? red[tid] : 0.f;
        t = warpSum(t);
        if (tid == 0) red[0] = t;
    }
    __syncthreads();
    const float var = red[0] * (1.f / DMODEL) - mu * mu;
    const float rs = rsqrtf(var + 1e-5f);

    const float4 gv = *(const float4*)(gam + tid * 4);
    const float4 bv = *(const float4*)(bet + tid * 4);
    float4 o;
    o.x = (v.x - mu) * rs * gv.x + bv.x;
    o.y = (v.y - mu) * rs * gv.y + bv.y;
    o.z = (v.z - mu) * rs * gv.z + bv.z;
    o.w = (v.w - mu) * rs * gv.w + bv.w;
    *(float4*)(Y + row * DMODEL + tid * 4) = o;
    if (Y16) {
        __half2 h[2] = { __floats2half2_rn(o.x, o.y), __floats2half2_rn(o.z, o.w) };
        *(uint2*)(Y16 + row * DMODEL + tid * 4) = *(uint2*)h;
    }
}

// ----------------------------------------------------------------------------
extern "C" void kernel_launch(void* const* d_in, const int* in_sizes, int n_in,
                              void* d_out, int out_size)
{
    (void)in_sizes; (void)n_in; (void)out_size;
    const float* w       = (const float*)d_in[0];
    const float* r       = (const float*)d_in[1];
    const float* mems    = (const float*)d_in[2];
    const float* qkv_w   = (const float*)d_in[3];
    const float* r_net_w = (const float*)d_in[4];
    const float* o_w     = (const float*)d_in[5];
    const float* rwb     = (const float*)d_in[6];
    const float* rrb     = (const float*)d_in[7];
    const float* ln1g    = (const float*)d_in[8];
    const float* ln1b    = (const float*)d_in[9];
    const float* ffw1    = (const float*)d_in[10];
    const float* ffb1    = (const float*)d_in[11];
    const float* ffw2    = (const float*)d_in[12];
    const float* ffb2    = (const float*)d_in[13];
    const float* ln2g    = (const float*)d_in[14];
    const float* ln2b    = (const float*)d_in[15];
    float* out = (float*)d_out;

    float *rk, *rbias, *tmp, *out1;
    __half *heads16, *rk16, *BD, *av16, *out116, *ffh16;
    __half *cat16, *r16, *qkvw16, *rnw16, *ow16, *ffw116, *ffw216;
    cudaGetSymbolAddress((void**)&heads16, g_heads16);
    cudaGetSymbolAddress((void**)&rk,      g_rk);
    cudaGetSymbolAddress((void**)&rk16,    g_rk16);
    cudaGetSymbolAddress((void**)&rbias,   g_rbias);
    cudaGetSymbolAddress((void**)&BD,      g_BD);
    cudaGetSymbolAddress((void**)&av16,    g_av16);
    cudaGetSymbolAddress((void**)&tmp,     g_tmp);
    cudaGetSymbolAddress((void**)&out1,    g_out1);
    cudaGetSymbolAddress((void**)&out116,  g_out116);
    cudaGetSymbolAddress((void**)&ffh16,   g_ffh16);
    cudaGetSymbolAddress((void**)&cat16,   g_cat16);
    cudaGetSymbolAddress((void**)&r16,     g_r16);
    cudaGetSymbolAddress((void**)&qkvw16,  g_qkvw16);
    cudaGetSymbolAddress((void**)&rnw16,   g_rnw16);
    cudaGetSymbolAddress((void**)&ow16,    g_ow16);
    cudaGetSymbolAddress((void**)&ffw116,  g_ffw116);
    cudaGetSymbolAddress((void**)&ffw216,  g_ffw216);

    static int s_attr_done = 0;
    if (!s_attr_done) {
        cudaFuncSetAttribute(flash_k, cudaFuncAttributeMaxDynamicSharedMemorySize,
                             FLASH_SMEM);
        s_attr_done = 1;
    }

    const dim3 blk(256);
    const __half* qb16 = heads16 + (size_t)MEMLEN * BSZ * H3;  // query rows

    // 0) fp32 -> fp16 conversions
    cvt_k<<<(MEMLEN * BSZ * DMODEL) / 2048, blk>>>(mems, cat16);
    cvt_k<<<(QLEN * BSZ * DMODEL) / 2048, blk>>>(w, cat16 + (size_t)MEMLEN * BSZ * DMODEL);
    cvt_k<<<(KLEN * DMODEL) / 2048, blk>>>(r, r16);
    cvt_k<<<(DMODEL * H3) / 2048, blk>>>(qkv_w, qkvw16);
    cvt_k<<<(DMODEL * DMODEL) / 2048, blk>>>(r_net_w, rnw16);
    cvt_k<<<(DMODEL * DMODEL) / 2048, blk>>>(o_w, ow16);
    cvt_k<<<(DMODEL * DINNER) / 2048, blk>>>(ffw1, ffw116);
    cvt_k<<<(DINNER * DMODEL) / 2048, blk>>>(ffw2, ffw216);

    // 1) heads16 = cat16 @ qkvw16 (pure fp16 out)
    gemm_h<1><<<dim3(H3 / 128, (KLEN * BSZ) / 128), blk>>>(
        cat16, DMODEL, qkvw16, nullptr, nullptr, 0,
        heads16, nullptr, KLEN * BSZ, H3, DMODEL);

    // 2) rk = r16 @ rnw16 (fp32 + fp16 dual out)
    gemm_h<2><<<dim3(DMODEL / 128, KLEN / 128), blk>>>(
        r16, DMODEL, rnw16, nullptr, nullptr, 0,
        rk, rk16, KLEN, DMODEL, DMODEL);

    // 3) rbias
    rbias_k<<<(NHEAD * KLEN) / 256, blk>>>(rrb, rk, rbias);

    // 4) BDr (fp16 MMAs, j-indexed shifted fp16 out, diag skip)
    bd16_gemm<<<dim3(KLEN / 128, QLEN / 128, BSZ * NHEAD), blk>>>(
        qb16, rk16, rbias, BD);

    // 5) flash (register-resident P) -> av16
    flash_k<<<dim3(QLEN / 128, BSZ * NHEAD), dim3(512), FLASH_SMEM>>>(
        heads16, BD, rwb, av16);

    // 6) attn_out = av16 @ ow16 + w
    gemm_h<0><<<dim3(DMODEL / 128, (QLEN * BSZ) / 128), blk>>>(
        av16, DMODEL, ow16, nullptr, w, 0,
        tmp, nullptr, QLEN * BSZ, DMODEL, DMODEL);

    // 7) LN1 (dual fp32 + fp16)
    ln_k<<<QLEN * BSZ, blk>>>(tmp, ln1g, ln1b, out1, out116);

    // 8) ffh16 = relu(out116 @ ffw116 + b1) (fp16 out)
    gemm_h<1><<<dim3(DINNER / 128, (QLEN * BSZ) / 128), blk>>>(
        out116, DMODEL, ffw116, ffb1, nullptr, 1,
        ffh16, nullptr, QLEN * BSZ, DINNER, DMODEL);

    // 9) tmp = ffh16 @ ffw216 + b2 + out1
    gemm_h<0><<<dim3(DMODEL / 128, (QLEN * BSZ) / 128), blk>>>(
        ffh16, DINNER, ffw216, ffb2, out1, 0,
        tmp, nullptr, QLEN * BSZ, DMODEL, DINNER);

    // 10) LN2 -> output
    ln_k<<<QLEN * BSZ, blk>>>(tmp, ln2g, ln2b, out, nullptr);
}

// round 13
// speedup vs baseline: 2.5290x; 1.0374x over previous
#include <cuda_runtime.h>
#include <cuda_fp16.h>
#include <math.h>
#include <stdint.h>

#define QLEN   1024
#define BSZ    4
#define DMODEL 1024
#define NHEAD  16
#define DHEAD  64
#define DINNER 4096
#define MEMLEN 1024
#define KLEN   2048
#define H3     (3 * DMODEL)   // 3072

// ---- static device scratch (no cudaMalloc allowed) ----
__device__ __half g_heads16[(size_t)KLEN * BSZ * H3];        // fp16 QKV heads
__device__ __half g_rk16[(size_t)KLEN * DMODEL];             // fp16 rk
__device__ float  g_rbias[(size_t)NHEAD * KLEN];
__device__ __half g_BD[(size_t)BSZ * NHEAD * QLEN * KLEN];   // j-indexed BDr
__device__ __half g_av16[(size_t)QLEN * BSZ * DMODEL];
__device__ float  g_tmp[(size_t)QLEN * BSZ * DMODEL];
__device__ float  g_out1[(size_t)QLEN * BSZ * DMODEL];
__device__ __half g_out116[(size_t)QLEN * BSZ * DMODEL];
__device__ __half g_ffh16[(size_t)QLEN * BSZ * DINNER];
__device__ __half g_cat16[(size_t)KLEN * BSZ * DMODEL];
__device__ __half g_r16[(size_t)KLEN * DMODEL];
__device__ __half g_qkvw16[(size_t)DMODEL * H3];
__device__ __half g_rnw16[(size_t)DMODEL * DMODEL];
__device__ __half g_ow16[(size_t)DMODEL * DMODEL];
__device__ __half g_ffw116[(size_t)DMODEL * DINNER];
__device__ __half g_ffw216[(size_t)DINNER * DMODEL];

__device__ __forceinline__ void cpa16(uint32_t s, const void* g) {
    asm volatile("cp.async.cg.shared.global [%0], [%1], 16;" :: "r"(s), "l"(g));
}
#define CP_COMMIT() asm volatile("cp.async.commit_group;")
#define CP_WAIT(N)  asm volatile("cp.async.wait_group %0;" :: "n"(N))

#define MMA_F16(acc, av, bv)                                                \
    asm volatile(                                                           \
        "mma.sync.aligned.m16n8k16.row.col.f32.f16.f16.f32 "                \
        "{%0,%1,%2,%3}, {%4,%5,%6,%7}, {%8,%9}, {%0,%1,%2,%3};"             \
        : "+f"(acc[0]), "+f"(acc[1]), "+f"(acc[2]), "+f"(acc[3])            \
        : "r"(av[0]), "r"(av[1]), "r"(av[2]), "r"(av[3]),                   \
          "r"(bv[0]), "r"(bv[1]))

#define LDSM_X4(r0, r1, r2, r3, addr)                                       \
    asm volatile("ldmatrix.sync.aligned.m8n8.x4.shared.b16 {%0,%1,%2,%3}, [%4];" \
        : "=r"(r0), "=r"(r1), "=r"(r2), "=r"(r3) : "r"(addr))
#define LDSM_X4T(r0, r1, r2, r3, addr)                                      \
    asm volatile("ldmatrix.sync.aligned.m8n8.x4.trans.shared.b16 {%0,%1,%2,%3}, [%4];" \
        : "=r"(r0), "=r"(r1), "=r"(r2), "=r"(r3) : "r"(addr))

// ----------------------------------------------------------------------------
__global__ __launch_bounds__(256) void cvt_k(
    const float* __restrict__ src, __half* __restrict__ dst)
{
    const int i = (blockIdx.x * 256 + threadIdx.x) * 8;
    const float4 a = *(const float4*)(src + i);
    const float4 b = *(const float4*)(src + i + 4);
    __half2 h[4];
    h[0] = __floats2half2_rn(a.x, a.y);
    h[1] = __floats2half2_rn(a.z, a.w);
    h[2] = __floats2half2_rn(b.x, b.y);
    h[3] = __floats2half2_rn(b.z, b.w);
    *(uint4*)(dst + i) = *(uint4*)h;
}

// ----------------------------------------------------------------------------
// Dense fp16 GEMM. HOUT=0: fp32 out. HOUT=1: fp16 out.
// ----------------------------------------------------------------------------
#define ASTR 40
#define BSTR 136

template <int HOUT>
__global__ __launch_bounds__(256, 2) void gemm_h(
    const __half* __restrict__ A, int lda,
    const __half* __restrict__ B,
    const float* __restrict__ bias, const float* __restrict__ resid, int doRelu,
    void* __restrict__ Cv, __half* __restrict__ C16,
    int M, int N, int Kd)
{
    __shared__ __half As[3][128 * ASTR];
    __shared__ __half Bs[3][32 * BSTR];

    const int tid  = threadIdx.x;
    const int warp = tid >> 5, lane = tid & 31;
    const int lr = lane >> 2, lc = lane & 3;
    const int bm = blockIdx.y * 128, bn = blockIdx.x * 128;
    const int wm = (warp & 1) * 64;
    const int wn = (warp >> 1) * 32;

    float acc[4][4][4];
#pragma unroll
    for (int mt = 0; mt < 4; mt++)
#pragma unroll
        for (int nt = 0; nt < 4; nt++)
#pragma unroll
            for (int q = 0; q < 4; q++) acc[mt][nt][q] = 0.f;

    const __half* aPtr[2];
    const __half* bPtr[2];
    uint32_t aDst[2], bDst[2];
#pragma unroll
    for (int h = 0; h < 2; h++) {
        const int ch = tid + h * 256;
        const int ar = ch >> 2, ao = (ch & 3) * 8;
        aPtr[h] = A + (long long)(bm + ar) * lda + ao;
        aDst[h] = (uint32_t)__cvta_generic_to_shared(&As[0][ar * ASTR + ao]);
        const int br = ch >> 4, bo = (ch & 15) * 8;
        bPtr[h] = B + (long long)br * N + bn + bo;
        bDst[h] = (uint32_t)__cvta_generic_to_shared(&Bs[0][br * BSTR + bo]);
    }
    const long long bStep = (long long)32 * N;

    auto load = [&](int kt, int s) {
#pragma unroll
        for (int h = 0; h < 2; h++)
            cpa16(aDst[h] + s * 128 * ASTR * 2, aPtr[h] + kt * 32);
#pragma unroll
        for (int h = 0; h < 2; h++)
            cpa16(bDst[h] + s * 32 * BSTR * 2, bPtr[h] + kt * bStep);
    };

    const int aRow = lane & 15;
    const int selOff = (lane >> 4) << 3;
    const uint32_t asBase = (uint32_t)__cvta_generic_to_shared(&As[0][0]);
    const uint32_t bsBase = (uint32_t)__cvta_generic_to_shared(&Bs[0][0]);

    const int nk = Kd >> 5;
    load(0, 0); CP_COMMIT();
    load(1, 1); CP_COMMIT();

    for (int kt = 0; kt < nk; kt++) {
        const int s = kt % 3;
        CP_WAIT(1);
        __syncthreads();
        if (kt + 2 < nk) load(kt + 2, (kt + 2) % 3);
        CP_COMMIT();

        const uint32_t aS = asBase + (uint32_t)(s * 128 * ASTR * 2);
        const uint32_t bS = bsBase + (uint32_t)(s * 32 * BSTR * 2);
#pragma unroll
        for (int kk = 0; kk < 32; kk += 16) {
            uint32_t af[4][4], bf[4][2];
#pragma unroll
            for (int mt = 0; mt < 4; mt++) {
                const uint32_t addr = aS +
                    (uint32_t)(((wm + mt * 16 + aRow) * ASTR + kk + selOff) * 2);
                LDSM_X4(af[mt][0], af[mt][1], af[mt][2], af[mt][3], addr);
            }
#pragma unroll
            for (int ntp = 0; ntp < 2; ntp++) {
                const uint32_t addr = bS +
                    (uint32_t)(((kk + aRow) * BSTR + wn + ntp * 16 + selOff) * 2);
                LDSM_X4T(bf[2 * ntp][0], bf[2 * ntp][1],
                         bf[2 * ntp + 1][0], bf[2 * ntp + 1][1], addr);
            }
#pragma unroll
            for (int mt = 0; mt < 4; mt++)
#pragma unroll
                for (int nt = 0; nt < 4; nt++)
                    MMA_F16(acc[mt][nt], af[mt], bf[nt]);
        }
    }

#pragma unroll
    for (int mt = 0; mt < 4; mt++) {
#pragma unroll
        for (int nt = 0; nt < 4; nt++) {
            const int col = bn + wn + nt * 8 + lc * 2;
#pragma unroll
            for (int half = 0; half < 2; half++) {
                const int row = bm + wm + mt * 16 + lr + half * 8;
                float v0 = acc[mt][nt][half * 2 + 0];
                float v1 = acc[mt][nt][half * 2 + 1];
                if (bias) { v0 += bias[col]; v1 += bias[col + 1]; }
                if (resid) {
                    const float* rp = resid + (long long)row * N + col;
                    v0 += rp[0]; v1 += rp[1];
                }
                if (doRelu) { v0 = fmaxf(v0, 0.f); v1 = fmaxf(v1, 0.f); }
                if (HOUT == 1) {
                    *(__half2*)((__half*)Cv + (long long)row * N + col) =
                        __floats2half2_rn(v0, v1);
                } else {
                    float* cp = (float*)Cv + (long long)row * N + col;
                    cp[0] = v0; cp[1] = v1;
                }
            }
        }
    }
}

// ----------------------------------------------------------------------------
// rbias[n][c] = rrb_n . rk16_c  (fp32 accumulate over fp16 rk)
// ----------------------------------------------------------------------------
__global__ __launch_bounds__(256) void rbias_k(
    const float* __restrict__ rrb, const __half* __restrict__ rk16,
    float* __restrict__ rbias)
{
    const int idx = blockIdx.x * 256 + threadIdx.x;
    const int c = idx >> 4, n = idx & 15;
    const __half2* rp = (const __half2*)(rk16 + (size_t)c * DMODEL + n * DHEAD);
    const float* bp = rrb + n * DHEAD;
    float s = 0.f;
#pragma unroll
    for (int d = 0; d < 32; d++) {
        const float2 rv = __half22float2(rp[d]);
        s += rv.x * bp[2 * d] + rv.y * bp[2 * d + 1];
    }
    rbias[n * KLEN + c] = s;
}

// ----------------------------------------------------------------------------
// BD GEMM fp16, j-indexed output: BDr[bn][i][j] = q_i . rk_{j-i+1023} + rbias.
// ----------------------------------------------------------------------------
#define BDSTR 72

__global__ __launch_bounds__(256, 2) void bd16_gemm(
    const __half* __restrict__ Q16,
    const __half* __restrict__ RK16,
    const float* __restrict__ rbias, __half* __restrict__ BD)
{
    __shared__ __half As[128 * BDSTR];
    __shared__ __half Bs[128 * BDSTR];

    const int tid = threadIdx.x;
    const int warp = tid >> 5, lane = tid & 31;
    const int lr = lane >> 2, lc = lane & 3;
    const int bm = blockIdx.y * 128, bn = blockIdx.x * 128;
    if (bm + bn < 769) return;   // whole tile lands at j < 0, never read
    const int bnidx = blockIdx.z;
    const int b = bnidx >> 4, n = bnidx & 15;
    const int wm = (warp & 1) * 64;
    const int wn = (warp >> 1) * 32;
    const int aRow = lane & 15;
    const int selOff = (lane >> 4) << 3;
    const uint32_t as_b = (uint32_t)__cvta_generic_to_shared(As);
    const uint32_t bs_b = (uint32_t)__cvta_generic_to_shared(Bs);

#pragma unroll
    for (int h = 0; h < 4; h++) {
        const int ch = tid + h * 256;
        const int row = ch >> 3, seg = (ch & 7) * 8;
        const __half* ga = Q16 + ((size_t)(bm + row) * BSZ + b) * H3 + n * DHEAD + seg;
        cpa16(as_b + (uint32_t)((row * BDSTR + seg) << 1), ga);
    }
#pragma unroll
    for (int h = 0; h < 4; h++) {
        const int ch = tid + h * 256;
        const int row = ch >> 3, seg = (ch & 7) * 8;
        const __half* gb = RK16 + (size_t)(bn + row) * DMODEL + n * DHEAD + seg;
        cpa16(bs_b + (uint32_t)((row * BDSTR + seg) << 1), gb);
    }
    CP_COMMIT();

    float acc[4][4][4];
#pragma unroll
    for (int mt = 0; mt < 4; mt++)
#pragma unroll
        for (int nt = 0; nt < 4; nt++)
#pragma unroll
            for (int q = 0; q < 4; q++) acc[mt][nt][q] = 0.f;

    CP_WAIT(0);
    __syncthreads();

#pragma unroll
    for (int kk = 0; kk < 64; kk += 16) {
        uint32_t af[4][4], bfr[4][2];
#pragma unroll
        for (int mt = 0; mt < 4; mt++) {
            const uint32_t addr = as_b +
                (uint32_t)(((wm + mt * 16 + aRow) * BDSTR + kk + selOff) << 1);
            LDSM_X4(af[mt][0], af[mt][1], af[mt][2], af[mt][3], addr);
        }
#pragma unroll
        for (int p = 0; p < 2; p++) {
            uint32_t r0, r1, r2, r3;
            const uint32_t addr = bs_b +
                (uint32_t)(((wn + p * 16 + aRow) * BDSTR + kk + selOff) << 1);
            LDSM_X4(r0, r1, r2, r3, addr);
            bfr[2 * p][0] = r0; bfr[2 * p][1] = r2;
            bfr[2 * p + 1][0] = r1; bfr[2 * p + 1][1] = r3;
        }
#pragma unroll
        for (int mt = 0; mt < 4; mt++)
#pragma unroll
            for (int nt = 0; nt < 4; nt++)
                MMA_F16(acc[mt][nt], af[mt], bfr[nt]);
    }

    // epilogue: + rbias, rel-shifted fp16 store (j = c + i - 1023)
#pragma unroll
    for (int mt = 0; mt < 4; mt++) {
#pragma unroll
        for (int nt = 0; nt < 4; nt++) {
            const int col = bn + wn + nt * 8 + lc * 2;
            const float rb0 = rbias[n * KLEN + col];
            const float rb1 = rbias[n * KLEN + col + 1];
#pragma unroll
            for (int half = 0; half < 2; half++) {
                const int row = bm + wm + mt * 16 + lr + half * 8;
                const float v0 = acc[mt][nt][half * 2 + 0] + rb0;
                const float v1 = acc[mt][nt][half * 2 + 1] + rb1;
                __half* rowp = BD + ((size_t)bnidx * QLEN + row) * KLEN;
                const int j = col + row - (QLEN - 1);
                if (j >= 0)     rowp[j]     = __float2half_rn(v0);
                if (j + 1 >= 0) rowp[j + 1] = __float2half_rn(v1);
            }
        }
    }
}

// ----------------------------------------------------------------------------
// Flash attention (FA2-style, proven): register-resident P, 512 threads.
// ----------------------------------------------------------------------------
#define KSTR  72
#define BDF   136
#define OSTR  72
#define FLASH_SMEM (128*KSTR*2 /*Q*/ + 2*128*KSTR*2 /*K*/ + 128*KSTR*2 /*V*/ \
                    + 128*BDF*2 /*Bd*/ + 2*128*4 /*pmax*/ + 2*128*4 /*psum*/)

__global__ __launch_bounds__(512, 1) void flash_k(
    const __half* __restrict__ heads16,
    const __half* __restrict__ BD,
    const float* __restrict__ rwb, __half* __restrict__ av16)
{
    extern __shared__ char smc[];
    __half* Qs16 = (__half*)smc;
    __half* Ks16 = Qs16 + 128 * KSTR;
    __half* Vs16 = Ks16 + 2 * 128 * KSTR;
    __half* Bds  = Vs16 + 128 * KSTR;
    float*  pmax = (float*)(Bds + 128 * BDF);
    float*  psum = pmax + 2 * 128;
    float*  Osum = (float*)Ks16;
    const uint32_t qs_b = (uint32_t)__cvta_generic_to_shared(Qs16);
    const uint32_t ks_b = (uint32_t)__cvta_generic_to_shared(Ks16);
    const uint32_t vs_b = (uint32_t)__cvta_generic_to_shared(Vs16);
    const uint32_t bd_b = (uint32_t)__cvta_generic_to_shared(Bds);

    const int tid = threadIdx.x;
    const int warp = tid >> 5, lane = tid & 31;
    const int lr = lane >> 2, lc = lane & 3;
    const int aRow = lane & 15;
    const int selOff = (lane >> 4) << 3;
    const int qt = (int)gridDim.x - 1 - (int)blockIdx.x;   // longest-first
    const int i0 = qt * 128;
    const int bn = blockIdx.y;
    const int b = bn >> 4, n = bn & 15;
    const int rg  = warp & 7;
    const int chh = warp >> 3;
    const int wm  = rg * 16;
    const int njt = qt + 9;

    auto loadK = [&](int jt, int buf) {
        const int j0 = jt * 128;
#pragma unroll
        for (int it = 0; it < 2; it++) {
            const int c = tid + it * 512;
            const int row = c >> 3, seg = (c & 7) << 3;
            const __half* g = heads16 + ((size_t)(j0 + row) * BSZ + b) * H3 + DMODEL + n * DHEAD + seg;
            cpa16(ks_b + (uint32_t)((((buf << 7) + row) * KSTR + seg) << 1), g);
        }
    };
    auto loadV = [&](int jt) {
        const int j0 = jt * 128;
#pragma unroll
        for (int it = 0; it < 2; it++) {
            const int c = tid + it * 512;
            const int row = c >> 3, seg = (c & 7) << 3;
            const __half* g = heads16 + ((size_t)(j0 + row) * BSZ + b) * H3 + 2 * DMODEL + n * DHEAD + seg;
            cpa16(vs_b + (uint32_t)((row * KSTR + seg) << 1), g);
        }
    };
    auto loadBd = [&](int jt) {
        const int j0 = jt * 128;
#pragma unroll
        for (int it = 0; it < 4; it++) {
            const int c = tid + it * 512;
            const int row = c >> 4, seg = (c & 15) << 3;
            const __half* g = BD + ((size_t)bn * QLEN + i0 + row) * KLEN + j0 + seg;
            cpa16(bd_b + (uint32_t)((row * BDF + seg) << 1), g);
        }
    };

    loadK(0, 0); CP_COMMIT();
    const __half* qb16 = heads16 + (size_t)MEMLEN * BSZ * H3;
#pragma unroll
    for (int it = 0; it < 4; it++) {
        const int idx = tid + it * 512;
        const int row = idx >> 4, c4 = (idx & 15) * 4;
        const __half2* qp = (const __half2*)(qb16 + ((size_t)(i0 + row) * BSZ + b) * H3 + n * DHEAD + c4);
        const float2 q0 = __half22float2(qp[0]);
        const float2 q1 = __half22float2(qp[1]);
        const float4 bb = *(const float4*)(rwb + n * DHEAD + c4);
        *(__half2*)(Qs16 + row * KSTR + c4)     = __floats2half2_rn(q0.x + bb.x, q0.y + bb.y);
        *(__half2*)(Qs16 + row * KSTR + c4 + 2) = __floats2half2_rn(q1.x + bb.z, q1.y + bb.w);
    }

    float m0 = -1e30f, m1 = -1e30f, l0 = 0.f, l1 = 0.f;

    float accO[8][4];
#pragma unroll
    for (int nt = 0; nt < 8; nt++)
#pragma unroll
        for (int q = 0; q < 4; q++) accO[nt][q] = 0.f;

    CP_WAIT(0);
    __syncthreads();

    for (int jt = 0; jt < njt; jt++) {
        const int j0 = jt * 128;
        const int cur = jt & 1;
        const bool more = (jt + 1 < njt);

        loadV(jt); loadBd(jt); CP_COMMIT();
        if (more) { loadK(jt + 1, cur ^ 1); CP_COMMIT(); }

        float accS[8][4];
#pragma unroll
        for (int nt = 0; nt < 8; nt++)
#pragma unroll
            for (int q = 0; q < 4; q++) accS[nt][q] = 0.f;

#pragma unroll
        for (int kk = 0; kk < 64; kk += 16) {
            uint32_t af[4], bfr[8][2];
            {
                const uint32_t addr = qs_b +
                    (uint32_t)(((wm + aRow) * KSTR + kk + selOff) << 1);
                LDSM_X4(af[0], af[1], af[2], af[3], addr);
            }
#pragma unroll
            for (int p = 0; p < 4; p++) {
                uint32_t r0, r1, r2, r3;
                const uint32_t addr = ks_b +
                    (uint32_t)((((cur << 7) + chh * 64 + p * 16 + aRow) * KSTR + kk + selOff) << 1);
                LDSM_X4(r0, r1, r2, r3, addr);
                bfr[2 * p][0] = r0; bfr[2 * p][1] = r2;
                bfr[2 * p + 1][0] = r1; bfr[2 * p + 1][1] = r3;
            }
#pragma unroll
            for (int nt = 0; nt < 8; nt++)
                MMA_F16(accS[nt], af, bfr[nt]);
        }

        if (more) { CP_WAIT(1); } else { CP_WAIT(0); }
        __syncthreads();

        const int dcol = j0 + chh * 64 - (i0 + wm);
        const int lim0 = lr + MEMLEN - dcol;
        const int lim1 = lim0 + 8;
        float mx0 = -1e30f, mx1 = -1e30f;
#pragma unroll
        for (int nt = 0; nt < 8; nt++) {
            const int cl = nt * 8 + 2 * lc;
            const float2 b0 = __half22float2(*(const __half2*)&Bds[(wm + lr) * BDF + chh * 64 + nt * 8 + 2 * lc]);
            const float2 b1 = __half22float2(*(const __half2*)&Bds[(wm + lr + 8) * BDF + chh * 64 + nt * 8 + 2 * lc]);
            accS[nt][0] = (cl     <= lim0) ? (accS[nt][0] + b0.x) * 0.125f : -1e30f;
            accS[nt][1] = (cl + 1 <= lim0) ? (accS[nt][1] + b0.y) * 0.125f : -1e30f;
            accS[nt][2] = (cl     <= lim1) ? (accS[nt][2] + b1.x) * 0.125f : -1e30f;
            accS[nt][3] = (cl + 1 <= lim1) ? (accS[nt][3] + b1.y) * 0.125f : -1e30f;
            mx0 = fmaxf(mx0, fmaxf(accS[nt][0], accS[nt][1]));
            mx1 = fmaxf(mx1, fmaxf(accS[nt][2], accS[nt][3]));
        }
#pragma unroll
        for (int o = 1; o <= 2; o <<= 1) {
            mx0 = fmaxf(mx0, __shfl_xor_sync(0xffffffffu, mx0, o));
            mx1 = fmaxf(mx1, __shfl_xor_sync(0xffffffffu, mx1, o));
        }
        if (lc == 0) {
            pmax[chh * 128 + wm + lr] = mx0;
            pmax[chh * 128 + wm + lr + 8] = mx1;
        }
        __syncthreads();

        const float nm0 = fmaxf(m0, fmaxf(pmax[wm + lr], pmax[128 + wm + lr]));
        const float nm1 = fmaxf(m1, fmaxf(pmax[wm + lr + 8], pmax[128 + wm + lr + 8]));

        uint32_t pLo[8], pHi[8];
        float ls0 = 0.f, ls1 = 0.f;
#pragma unroll
        for (int nt = 0; nt < 8; nt++) {
            const __half2 h0 = __floats2half2_rn(__expf(accS[nt][0] - nm0),
                                                 __expf(accS[nt][1] - nm0));
            const __half2 h1 = __floats2half2_rn(__expf(accS[nt][2] - nm1),
                                                 __expf(accS[nt][3] - nm1));
            pLo[nt] = *(const uint32_t*)&h0;
            pHi[nt] = *(const uint32_t*)&h1;
            const float2 f0 = __half22float2(h0);
            const float2 f1 = __half22float2(h1);
            ls0 += f0.x + f0.y;
            ls1 += f1.x + f1.y;
        }
#pragma unroll
        for (int o = 1; o <= 2; o <<= 1) {
            ls0 += __shfl_xor_sync(0xffffffffu, ls0, o);
            ls1 += __shfl_xor_sync(0xffffffffu, ls1, o);
        }
        if (lc == 0) {
            psum[chh * 128 + wm + lr] = ls0;
            psum[chh * 128 + wm + lr + 8] = ls1;
        }
        __syncthreads();

        const float lt0 = psum[wm + lr] + psum[128 + wm + lr];
        const float lt1 = psum[wm + lr + 8] + psum[128 + wm + lr + 8];
        const float a0 = __expf(m0 - nm0);
        const float a1 = __expf(m1 - nm1);
        m0 = nm0; m1 = nm1;
        l0 = l0 * a0 + lt0;
        l1 = l1 * a1 + lt1;

#pragma unroll
        for (int nt = 0; nt < 8; nt++) {
            accO[nt][0] *= a0; accO[nt][1] *= a0;
            accO[nt][2] *= a1; accO[nt][3] *= a1;
        }
#pragma unroll
        for (int p = 0; p < 4; p++) {
            uint32_t af[4];
            af[0] = pLo[2 * p];     af[1] = pHi[2 * p];
            af[2] = pLo[2 * p + 1]; af[3] = pHi[2 * p + 1];
            uint32_t bf[8][2];
#pragma unroll
            for (int nb = 0; nb < 4; nb++) {
                const uint32_t addr = vs_b +
                    (uint32_t)(((chh * 64 + p * 16 + aRow) * KSTR + nb * 16 + selOff) << 1);
                LDSM_X4T(bf[2 * nb][0], bf[2 * nb][1],
                         bf[2 * nb + 1][0], bf[2 * nb + 1][1], addr);
            }
#pragma unroll
            for (int nt = 0; nt < 8; nt++)
                MMA_F16(accO[nt], af, bf[nt]);
        }

        if (more) CP_WAIT(0);
        __syncthreads();
    }

    if (chh == 1) {
#pragma unroll
        for (int nt = 0; nt < 8; nt++) {
            const int col = nt * 8 + 2 * lc;
            *(float2*)&Osum[(wm + lr) * OSTR + col] =
                make_float2(accO[nt][0], accO[nt][1]);
            *(float2*)&Osum[(wm + lr + 8) * OSTR + col] =
                make_float2(accO[nt][2], accO[nt][3]);
        }
    }
    __syncthreads();
    if (chh == 0) {
        const float inv0 = 1.f / l0;
        const float inv1 = 1.f / l1;
#pragma unroll
        for (int nt = 0; nt < 8; nt++) {
            const int col = nt * 8 + 2 * lc;
            const float2 s0 = *(const float2*)&Osum[(wm + lr) * OSTR + col];
            const float2 s1 = *(const float2*)&Osum[(wm + lr + 8) * OSTR + col];
            __half2* p0 = (__half2*)(av16 + ((size_t)(i0 + wm + lr) * BSZ + b) * DMODEL + n * DHEAD + col);
            *p0 = __floats2half2_rn((accO[nt][0] + s0.x) * inv0,
                                    (accO[nt][1] + s0.y) * inv0);
            __half2* p1 = (__half2*)(av16 + ((size_t)(i0 + wm + lr + 8) * BSZ + b) * DMODEL + n * DHEAD + col);
            *p1 = __floats2half2_rn((accO[nt][2] + s1.x) * inv1,
                                    (accO[nt][3] + s1.y) * inv1);
        }
    }
}

// ----------------------------------------------------------------------------
__device__ __forceinline__ float warpSum(float v) {
#pragma unroll
    for (int o = 16; o; o >>= 1) v += __shfl_xor_sync(0xffffffffu, v, o);
    return v;
}

__global__ __launch_bounds__(256) void ln_k(
    const float* __restrict__ X, const float* __restrict__ gam,
    const float* __restrict__ bet, float* __restrict__ Y,
    __half* __restrict__ Y16)
{
    __shared__ float red[8];
    const size_t row = blockIdx.x;
    const int tid = threadIdx.x;
    const float4 v = *(const float4*)(X + row * DMODEL + tid * 4);
    float s = v.x + v.y + v.z + v.w;
    float q = v.x * v.x + v.y * v.y + v.z * v.z + v.w * v.w;

    float ws = warpSum(s);
    if ((tid & 31) == 0) red[tid >> 5] = ws;
    __syncthreads();
    if (tid < 32) {
        float t = (tid < 8) ? red[tid] : 0.f;
        t = warpSum(t);
        if (tid == 0) red[0] = t;
    }
    __syncthreads();
    const float mu = red[0] * (1.f / DMODEL);
    __syncthreads();

    float wq = warpSum(q);
    if ((tid & 31) == 0) red[tid >> 5] = wq;
    __syncthreads();
    if (tid < 32) {
        float t = (tid < 8) ? red[tid] : 0.f;
        t = warpSum(t);
        if (tid == 0) red[0] = t;
    }
    __syncthreads();
    const float var = red[0] * (1.f / DMODEL) - mu * mu;
    const float rs = rsqrtf(var + 1e-5f);

    const float4 gv = *(const float4*)(gam + tid * 4);
    const float4 bv = *(const float4*)(bet + tid * 4);
    float4 o;
    o.x = (v.x - mu) * rs * gv.x + bv.x;
    o.y = (v.y - mu) * rs * gv.y + bv.y;
    o.z = (v.z - mu) * rs * gv.z + bv.z;
    o.w = (v.w - mu) * rs * gv.w + bv.w;
    *(float4*)(Y + row * DMODEL + tid * 4) = o;
    if (Y16) {
        __half2 h[2] = { __floats2half2_rn(o.x, o.y), __floats2half2_rn(o.z, o.w) };
        *(uint2*)(Y16 + row * DMODEL + tid * 4) = *(uint2*)h;
    }
}

// ----------------------------------------------------------------------------
extern "C" void kernel_launch(void* const* d_in, const int* in_sizes, int n_in,
                              void* d_out, int out_size)
{
    (void)in_sizes; (void)n_in; (void)out_size;
    const float* w       = (const float*)d_in[0];
    const float* r       = (const float*)d_in[1];
    const float* mems    = (const float*)d_in[2];
    const float* qkv_w   = (const float*)d_in[3];
    const float* r_net_w = (const float*)d_in[4];
    const float* o_w     = (const float*)d_in[5];
    const float* rwb     = (const float*)d_in[6];
    const float* rrb     = (const float*)d_in[7];
    const float* ln1g    = (const float*)d_in[8];
    const float* ln1b    = (const float*)d_in[9];
    const float* ffw1    = (const float*)d_in[10];
    const float* ffb1    = (const float*)d_in[11];
    const float* ffw2    = (const float*)d_in[12];
    const float* ffb2    = (const float*)d_in[13];
    const float* ln2g    = (const float*)d_in[14];
    const float* ln2b    = (const float*)d_in[15];
    float* out = (float*)d_out;

    float *rbias, *tmp, *out1;
    __half *heads16, *rk16, *BD, *av16, *out116, *ffh16;
    __half *cat16, *r16, *qkvw16, *rnw16, *ow16, *ffw116, *ffw216;
    cudaGetSymbolAddress((void**)&heads16, g_heads16);
    cudaGetSymbolAddress((void**)&rk16,    g_rk16);
    cudaGetSymbolAddress((void**)&rbias,   g_rbias);
    cudaGetSymbolAddress((void**)&BD,      g_BD);
    cudaGetSymbolAddress((void**)&av16,    g_av16);
    cudaGetSymbolAddress((void**)&tmp,     g_tmp);
    cudaGetSymbolAddress((void**)&out1,    g_out1);
    cudaGetSymbolAddress((void**)&out116,  g_out116);
    cudaGetSymbolAddress((void**)&ffh16,   g_ffh16);
    cudaGetSymbolAddress((void**)&cat16,   g_cat16);
    cudaGetSymbolAddress((void**)&r16,     g_r16);
    cudaGetSymbolAddress((void**)&qkvw16,  g_qkvw16);
    cudaGetSymbolAddress((void**)&rnw16,   g_rnw16);
    cudaGetSymbolAddress((void**)&ow16,    g_ow16);
    cudaGetSymbolAddress((void**)&ffw116,  g_ffw116);
    cudaGetSymbolAddress((void**)&ffw216,  g_ffw216);

    static cudaStream_t s1 = nullptr;
    static cudaEvent_t evFork = nullptr, evJoin = nullptr;
    static int s_init_done = 0;
    if (!s_init_done) {
        cudaFuncSetAttribute(flash_k, cudaFuncAttributeMaxDynamicSharedMemorySize,
                             FLASH_SMEM);
        cudaStreamCreateWithFlags(&s1, cudaStreamNonBlocking);
        cudaEventCreateWithFlags(&evFork, cudaEventDisableTiming);
        cudaEventCreateWithFlags(&evJoin, cudaEventDisableTiming);
        s_init_done = 1;
    }

    const dim3 blk(256);
    const __half* qb16 = heads16 + (size_t)MEMLEN * BSZ * H3;  // query rows

    // ---- fork side stream off the main (capture) stream ----
    cudaEventRecord(evFork, 0);
    cudaStreamWaitEvent(s1, evFork, 0);

    // side stream: r/weight conversions -> rk GEMM -> rbias
    cvt_k<<<(KLEN * DMODEL) / 2048, blk, 0, s1>>>(r, r16);
    cvt_k<<<(DMODEL * DMODEL) / 2048, blk, 0, s1>>>(r_net_w, rnw16);
    cvt_k<<<(DMODEL * DMODEL) / 2048, blk, 0, s1>>>(o_w, ow16);
    cvt_k<<<(DMODEL * DINNER) / 2048, blk, 0, s1>>>(ffw1, ffw116);
    cvt_k<<<(DINNER * DMODEL) / 2048, blk, 0, s1>>>(ffw2, ffw216);
    gemm_h<1><<<dim3(DMODEL / 128, KLEN / 128), blk, 0, s1>>>(
        r16, DMODEL, rnw16, nullptr, nullptr, 0,
        rk16, nullptr, KLEN, DMODEL, DMODEL);
    rbias_k<<<(NHEAD * KLEN) / 256, blk, 0, s1>>>(rrb, rk16, rbias);
    cudaEventRecord(evJoin, s1);

    // main stream: input conversions -> QKV GEMM
    cvt_k<<<(MEMLEN * BSZ * DMODEL) / 2048, blk>>>(mems, cat16);
    cvt_k<<<(QLEN * BSZ * DMODEL) / 2048, blk>>>(w, cat16 + (size_t)MEMLEN * BSZ * DMODEL);
    cvt_k<<<(DMODEL * H3) / 2048, blk>>>(qkv_w, qkvw16);
    gemm_h<1><<<dim3(H3 / 128, (KLEN * BSZ) / 128), blk>>>(
        cat16, DMODEL, qkvw16, nullptr, nullptr, 0,
        heads16, nullptr, KLEN * BSZ, H3, DMODEL);

    // ---- join: bd16 needs rk16 + rbias from side stream ----
    cudaStreamWaitEvent(0, evJoin, 0);

    // BDr (fp16 MMAs, j-indexed shifted fp16 out, diag skip)
    bd16_gemm<<<dim3(KLEN / 128, QLEN / 128, BSZ * NHEAD), blk>>>(
        qb16, rk16, rbias, BD);

    // flash (register-resident P) -> av16
    flash_k<<<dim3(QLEN / 128, BSZ * NHEAD), dim3(512), FLASH_SMEM>>>(
        heads16, BD, rwb, av16);

    // attn_out = av16 @ ow16 + w
    gemm_h<0><<<dim3(DMODEL / 128, (QLEN * BSZ) / 128), blk>>>(
        av16, DMODEL, ow16, nullptr, w, 0,
        tmp, nullptr, QLEN * BSZ, DMODEL, DMODEL);

    // LN1 (dual fp32 + fp16)
    ln_k<<<QLEN * BSZ, blk>>>(tmp, ln1g, ln1b, out1, out116);

    // ffh16 = relu(out116 @ ffw116 + b1) (fp16 out)
    gemm_h<1><<<dim3(DINNER / 128, (QLEN * BSZ) / 128), blk>>>(
        out116, DMODEL, ffw116, ffb1, nullptr, 1,
        ffh16, nullptr, QLEN * BSZ, DINNER, DMODEL);

    // tmp = ffh16 @ ffw216 + b2 + out1
    gemm_h<0><<<dim3(DMODEL / 128, (QLEN * BSZ) / 128), blk>>>(
        ffh16, DINNER, ffw216, ffb2, out1, 0,
        tmp, nullptr, QLEN * BSZ, DMODEL, DINNER);

    // LN2 -> output
    ln_k<<<QLEN * BSZ, blk>>>(tmp, ln2g, ln2b, out, nullptr);
}

// round 14
// speedup vs baseline: 2.5853x; 1.0222x over previous
#include <cuda_runtime.h>
#include <cuda_fp16.h>
#include <math.h>
#include <stdint.h>

#define QLEN   1024
#define BSZ    4
#define DMODEL 1024
#define NHEAD  16
#define DHEAD  64
#define DINNER 4096
#define MEMLEN 1024
#define KLEN   2048
#define H3     (3 * DMODEL)   // 3072

// ---- static device scratch (no cudaMalloc allowed) ----
__device__ __half g_heads16[(size_t)KLEN * BSZ * H3];        // fp16 QKV heads
__device__ __half g_rk16[(size_t)KLEN * DMODEL];             // fp16 rk
__device__ float  g_rbias[(size_t)NHEAD * KLEN];
__device__ __half g_BD[(size_t)BSZ * NHEAD * QLEN * KLEN];   // j-indexed BDr
__device__ __half g_av16[(size_t)QLEN * BSZ * DMODEL];
__device__ float  g_tmp[(size_t)QLEN * BSZ * DMODEL];
__device__ float  g_out1[(size_t)QLEN * BSZ * DMODEL];
__device__ __half g_out116[(size_t)QLEN * BSZ * DMODEL];
__device__ __half g_ffh16[(size_t)QLEN * BSZ * DINNER];
__device__ __half g_cat16[(size_t)KLEN * BSZ * DMODEL];
__device__ __half g_r16[(size_t)KLEN * DMODEL];
__device__ __half g_qkvw16[(size_t)DMODEL * H3];
__device__ __half g_rnw16[(size_t)DMODEL * DMODEL];
__device__ __half g_ow16[(size_t)DMODEL * DMODEL];
__device__ __half g_ffw116[(size_t)DMODEL * DINNER];
__device__ __half g_ffw216[(size_t)DINNER * DMODEL];

__device__ __forceinline__ void cpa16(uint32_t s, const void* g) {
    asm volatile("cp.async.cg.shared.global [%0], [%1], 16;" :: "r"(s), "l"(g));
}
#define CP_COMMIT() asm volatile("cp.async.commit_group;")
#define CP_WAIT(N)  asm volatile("cp.async.wait_group %0;" :: "n"(N))

#define MMA_F16(acc, av, bv)                                                \
    asm volatile(                                                           \
        "mma.sync.aligned.m16n8k16.row.col.f32.f16.f16.f32 "                \
        "{%0,%1,%2,%3}, {%4,%5,%6,%7}, {%8,%9}, {%0,%1,%2,%3};"             \
        : "+f"(acc[0]), "+f"(acc[1]), "+f"(acc[2]), "+f"(acc[3])            \
        : "r"(av[0]), "r"(av[1]), "r"(av[2]), "r"(av[3]),                   \
          "r"(bv[0]), "r"(bv[1]))

#define LDSM_X4(r0, r1, r2, r3, addr)                                       \
    asm volatile("ldmatrix.sync.aligned.m8n8.x4.shared.b16 {%0,%1,%2,%3}, [%4];" \
        : "=r"(r0), "=r"(r1), "=r"(r2), "=r"(r3) : "r"(addr))
#define LDSM_X4T(r0, r1, r2, r3, addr)                                      \
    asm volatile("ldmatrix.sync.aligned.m8n8.x4.trans.shared.b16 {%0,%1,%2,%3}, [%4];" \
        : "=r"(r0), "=r"(r1), "=r"(r2), "=r"(r3) : "r"(addr))

// ----------------------------------------------------------------------------
__global__ __launch_bounds__(256) void cvt_k(
    const float* __restrict__ src, __half* __restrict__ dst)
{
    const int i = (blockIdx.x * 256 + threadIdx.x) * 8;
    const float4 a = *(const float4*)(src + i);
    const float4 b = *(const float4*)(src + i + 4);
    __half2 h[4];
    h[0] = __floats2half2_rn(a.x, a.y);
    h[1] = __floats2half2_rn(a.z, a.w);
    h[2] = __floats2half2_rn(b.x, b.y);
    h[3] = __floats2half2_rn(b.z, b.w);
    *(uint4*)(dst + i) = *(uint4*)h;
}

// ----------------------------------------------------------------------------
// Dense fp16 GEMM. HOUT=0: fp32 out. HOUT=1: fp16 out.
// ----------------------------------------------------------------------------
#define ASTR 40
#define BSTR 136

template <int HOUT>
__global__ __launch_bounds__(256, 2) void gemm_h(
    const __half* __restrict__ A, int lda,
    const __half* __restrict__ B,
    const float* __restrict__ bias, const float* __restrict__ resid, int doRelu,
    void* __restrict__ Cv, __half* __restrict__ C16,
    int M, int N, int Kd)
{
    __shared__ __half As[3][128 * ASTR];
    __shared__ __half Bs[3][32 * BSTR];

    const int tid  = threadIdx.x;
    const int warp = tid >> 5, lane = tid & 31;
    const int lr = lane >> 2, lc = lane & 3;
    const int bm = blockIdx.y * 128, bn = blockIdx.x * 128;
    const int wm = (warp & 1) * 64;
    const int wn = (warp >> 1) * 32;

    float acc[4][4][4];
#pragma unroll
    for (int mt = 0; mt < 4; mt++)
#pragma unroll
        for (int nt = 0; nt < 4; nt++)
#pragma unroll
            for (int q = 0; q < 4; q++) acc[mt][nt][q] = 0.f;

    const __half* aPtr[2];
    const __half* bPtr[2];
    uint32_t aDst[2], bDst[2];
#pragma unroll
    for (int h = 0; h < 2; h++) {
        const int ch = tid + h * 256;
        const int ar = ch >> 2, ao = (ch & 3) * 8;
        aPtr[h] = A + (long long)(bm + ar) * lda + ao;
        aDst[h] = (uint32_t)__cvta_generic_to_shared(&As[0][ar * ASTR + ao]);
        const int br = ch >> 4, bo = (ch & 15) * 8;
        bPtr[h] = B + (long long)br * N + bn + bo;
        bDst[h] = (uint32_t)__cvta_generic_to_shared(&Bs[0][br * BSTR + bo]);
    }
    const long long bStep = (long long)32 * N;

    auto load = [&](int kt, int s) {
#pragma unroll
        for (int h = 0; h < 2; h++)
            cpa16(aDst[h] + s * 128 * ASTR * 2, aPtr[h] + kt * 32);
#pragma unroll
        for (int h = 0; h < 2; h++)
            cpa16(bDst[h] + s * 32 * BSTR * 2, bPtr[h] + kt * bStep);
    };

    const int aRow = lane & 15;
    const int selOff = (lane >> 4) << 3;
    const uint32_t asBase = (uint32_t)__cvta_generic_to_shared(&As[0][0]);
    const uint32_t bsBase = (uint32_t)__cvta_generic_to_shared(&Bs[0][0]);

    const int nk = Kd >> 5;
    load(0, 0); CP_COMMIT();
    load(1, 1); CP_COMMIT();

    for (int kt = 0; kt < nk; kt++) {
        const int s = kt % 3;
        CP_WAIT(1);
        __syncthreads();
        if (kt + 2 < nk) load(kt + 2, (kt + 2) % 3);
        CP_COMMIT();

        const uint32_t aS = asBase + (uint32_t)(s * 128 * ASTR * 2);
        const uint32_t bS = bsBase + (uint32_t)(s * 32 * BSTR * 2);
#pragma unroll
        for (int kk = 0; kk < 32; kk += 16) {
            uint32_t af[4][4], bf[4][2];
#pragma unroll
            for (int mt = 0; mt < 4; mt++) {
                const uint32_t addr = aS +
                    (uint32_t)(((wm + mt * 16 + aRow) * ASTR + kk + selOff) * 2);
                LDSM_X4(af[mt][0], af[mt][1], af[mt][2], af[mt][3], addr);
            }
#pragma unroll
            for (int ntp = 0; ntp < 2; ntp++) {
                const uint32_t addr = bS +
                    (uint32_t)(((kk + aRow) * BSTR + wn + ntp * 16 + selOff) * 2);
                LDSM_X4T(bf[2 * ntp][0], bf[2 * ntp][1],
                         bf[2 * ntp + 1][0], bf[2 * ntp + 1][1], addr);
            }
#pragma unroll
            for (int mt = 0; mt < 4; mt++)
#pragma unroll
                for (int nt = 0; nt < 4; nt++)
                    MMA_F16(acc[mt][nt], af[mt], bf[nt]);
        }
    }

#pragma unroll
    for (int mt = 0; mt < 4; mt++) {
#pragma unroll
        for (int nt = 0; nt < 4; nt++) {
            const int col = bn + wn + nt * 8 + lc * 2;
#pragma unroll
            for (int half = 0; half < 2; half++) {
                const int row = bm + wm + mt * 16 + lr + half * 8;
                float v0 = acc[mt][nt][half * 2 + 0];
                float v1 = acc[mt][nt][half * 2 + 1];
                if (bias) { v0 += bias[col]; v1 += bias[col + 1]; }
                if (resid) {
                    const float* rp = resid + (long long)row * N + col;
                    v0 += rp[0]; v1 += rp[1];
                }
                if (doRelu) { v0 = fmaxf(v0, 0.f); v1 = fmaxf(v1, 0.f); }
                if (HOUT == 1) {
                    *(__half2*)((__half*)Cv + (long long)row * N + col) =
                        __floats2half2_rn(v0, v1);
                } else {
                    float* cp = (float*)Cv + (long long)row * N + col;
                    cp[0] = v0; cp[1] = v1;
                }
            }
        }
    }
}

// ----------------------------------------------------------------------------
// rbias[n][c] = rrb_n . rk16_c  (fp32 accumulate over fp16 rk)
// ----------------------------------------------------------------------------
__global__ __launch_bounds__(256) void rbias_k(
    const float* __restrict__ rrb, const __half* __restrict__ rk16,
    float* __restrict__ rbias)
{
    const int idx = blockIdx.x * 256 + threadIdx.x;
    const int c = idx >> 4, n = idx & 15;
    const __half2* rp = (const __half2*)(rk16 + (size_t)c * DMODEL + n * DHEAD);
    const float* bp = rrb + n * DHEAD;
    float s = 0.f;
#pragma unroll
    for (int d = 0; d < 32; d++) {
        const float2 rv = __half22float2(rp[d]);
        s += rv.x * bp[2 * d] + rv.y * bp[2 * d + 1];
    }
    rbias[n * KLEN + c] = s;
}

// ----------------------------------------------------------------------------
// BD GEMM fp16, j-indexed output: BDr[bn][i][j] = q_i . rk_{j-i+1023} + rbias.
// ----------------------------------------------------------------------------
#define BDSTR 72

__global__ __launch_bounds__(256, 2) void bd16_gemm(
    const __half* __restrict__ Q16,
    const __half* __restrict__ RK16,
    const float* __restrict__ rbias, __half* __restrict__ BD)
{
    __shared__ __half As[128 * BDSTR];
    __shared__ __half Bs[128 * BDSTR];

    const int tid = threadIdx.x;
    const int warp = tid >> 5, lane = tid & 31;
    const int lr = lane >> 2, lc = lane & 3;
    const int bm = blockIdx.y * 128, bn = blockIdx.x * 128;
    if (bm + bn < 769) return;   // whole tile lands at j < 0, never read
    const int bnidx = blockIdx.z;
    const int b = bnidx >> 4, n = bnidx & 15;
    const int wm = (warp & 1) * 64;
    const int wn = (warp >> 1) * 32;
    const int aRow = lane & 15;
    const int selOff = (lane >> 4) << 3;
    const uint32_t as_b = (uint32_t)__cvta_generic_to_shared(As);
    const uint32_t bs_b = (uint32_t)__cvta_generic_to_shared(Bs);

#pragma unroll
    for (int h = 0; h < 4; h++) {
        const int ch = tid + h * 256;
        const int row = ch >> 3, seg = (ch & 7) * 8;
        const __half* ga = Q16 + ((size_t)(bm + row) * BSZ + b) * H3 + n * DHEAD + seg;
        cpa16(as_b + (uint32_t)((row * BDSTR + seg) << 1), ga);
    }
#pragma unroll
    for (int h = 0; h < 4; h++) {
        const int ch = tid + h * 256;
        const int row = ch >> 3, seg = (ch & 7) * 8;
        const __half* gb = RK16 + (size_t)(bn + row) * DMODEL + n * DHEAD + seg;
        cpa16(bs_b + (uint32_t)((row * BDSTR + seg) << 1), gb);
    }
    CP_COMMIT();

    float acc[4][4][4];
#pragma unroll
    for (int mt = 0; mt < 4; mt++)
#pragma unroll
        for (int nt = 0; nt < 4; nt++)
#pragma unroll
            for (int q = 0; q < 4; q++) acc[mt][nt][q] = 0.f;

    CP_WAIT(0);
    __syncthreads();

#pragma unroll
    for (int kk = 0; kk < 64; kk += 16) {
        uint32_t af[4][4], bfr[4][2];
#pragma unroll
        for (int mt = 0; mt < 4; mt++) {
            const uint32_t addr = as_b +
                (uint32_t)(((wm + mt * 16 + aRow) * BDSTR + kk + selOff) << 1);
            LDSM_X4(af[mt][0], af[mt][1], af[mt][2], af[mt][3], addr);
        }
#pragma unroll
        for (int p = 0; p < 2; p++) {
            uint32_t r0, r1, r2, r3;
            const uint32_t addr = bs_b +
                (uint32_t)(((wn + p * 16 + aRow) * BDSTR + kk + selOff) << 1);
            LDSM_X4(r0, r1, r2, r3, addr);
            bfr[2 * p][0] = r0; bfr[2 * p][1] = r2;
            bfr[2 * p + 1][0] = r1; bfr[2 * p + 1][1] = r3;
        }
#pragma unroll
        for (int mt = 0; mt < 4; mt++)
#pragma unroll
            for (int nt = 0; nt < 4; nt++)
                MMA_F16(acc[mt][nt], af[mt], bfr[nt]);
    }

    // epilogue: + rbias, rel-shifted fp16 store (j = c + i - 1023)
#pragma unroll
    for (int mt = 0; mt < 4; mt++) {
#pragma unroll
        for (int nt = 0; nt < 4; nt++) {
            const int col = bn + wn + nt * 8 + lc * 2;
            const float rb0 = rbias[n * KLEN + col];
            const float rb1 = rbias[n * KLEN + col + 1];
#pragma unroll
            for (int half = 0; half < 2; half++) {
                const int row = bm + wm + mt * 16 + lr + half * 8;
                const float v0 = acc[mt][nt][half * 2 + 0] + rb0;
                const float v1 = acc[mt][nt][half * 2 + 1] + rb1;
                __half* rowp = BD + ((size_t)bnidx * QLEN + row) * KLEN;
                const int j = col + row - (QLEN - 1);
                if (j >= 0)     rowp[j]     = __float2half_rn(v0);
                if (j + 1 >= 0) rowp[j + 1] = __float2half_rn(v1);
            }
        }
    }
}

// ----------------------------------------------------------------------------
// Flash attention v6: 64-row q-tiles, 256 threads / 8 warps (4 row-groups x
// 2 col-halves), 2 CTAs/SM for cross-CTA phase overlap. Register-resident P.
// ----------------------------------------------------------------------------
#define KSTR  72
#define BDF   136
#define OSTR  72
#define FLASH_SMEM (64*KSTR*2 /*Q*/ + 2*128*KSTR*2 /*K*/ + 128*KSTR*2 /*V*/ \
                    + 64*BDF*2 /*Bd*/ + 2*64*4 /*pmax*/ + 2*64*4 /*psum*/)

__global__ __launch_bounds__(256, 2) void flash_k(
    const __half* __restrict__ heads16,
    const __half* __restrict__ BD,
    const float* __restrict__ rwb, __half* __restrict__ av16)
{
    extern __shared__ char smc[];
    __half* Qs16 = (__half*)smc;                  // 64*72
    __half* Ks16 = Qs16 + 64 * KSTR;              // 2*128*72 (reused as Osum)
    __half* Vs16 = Ks16 + 2 * 128 * KSTR;         // 128*72
    __half* Bds  = Vs16 + 128 * KSTR;             // 64*136
    float*  pmax = (float*)(Bds + 64 * BDF);      // [2][64]
    float*  psum = pmax + 2 * 64;                 // [2][64]
    float*  Osum = (float*)Ks16;                  // 64*72 floats
    const uint32_t qs_b = (uint32_t)__cvta_generic_to_shared(Qs16);
    const uint32_t ks_b = (uint32_t)__cvta_generic_to_shared(Ks16);
    const uint32_t vs_b = (uint32_t)__cvta_generic_to_shared(Vs16);
    const uint32_t bd_b = (uint32_t)__cvta_generic_to_shared(Bds);

    const int tid = threadIdx.x;
    const int warp = tid >> 5, lane = tid & 31;
    const int lr = lane >> 2, lc = lane & 3;
    const int aRow = lane & 15;
    const int selOff = (lane >> 4) << 3;
    const int qt = (int)gridDim.x - 1 - (int)blockIdx.x;   // longest-first
    const int i0 = qt * 64;
    const int bn = blockIdx.y;
    const int b = bn >> 4, n = bn & 15;
    const int rg  = warp & 3;           // row group (4 x 16 rows)
    const int chh = warp >> 2;          // col half (0/1)
    const int wm  = rg * 16;
    const int njt = ((i0 + 63 + MEMLEN) >> 7) + 1;   // 128-wide j tiles

    auto loadK = [&](int jt, int buf) {
        const int j0 = jt * 128;
#pragma unroll
        for (int it = 0; it < 4; it++) {
            const int c = tid + it * 256;
            const int row = c >> 3, seg = (c & 7) << 3;
            const __half* g = heads16 + ((size_t)(j0 + row) * BSZ + b) * H3 + DMODEL + n * DHEAD + seg;
            cpa16(ks_b + (uint32_t)((((buf << 7) + row) * KSTR + seg) << 1), g);
        }
    };
    auto loadV = [&](int jt) {
        const int j0 = jt * 128;
#pragma unroll
        for (int it = 0; it < 4; it++) {
            const int c = tid + it * 256;
            const int row = c >> 3, seg = (c & 7) << 3;
            const __half* g = heads16 + ((size_t)(j0 + row) * BSZ + b) * H3 + 2 * DMODEL + n * DHEAD + seg;
            cpa16(vs_b + (uint32_t)((row * KSTR + seg) << 1), g);
        }
    };
    auto loadBd = [&](int jt) {
        const int j0 = jt * 128;
#pragma unroll
        for (int it = 0; it < 4; it++) {
            const int c = tid + it * 256;
            const int row = c >> 4, seg = (c & 15) << 3;
            const __half* g = BD + ((size_t)bn * QLEN + i0 + row) * KLEN + j0 + seg;
            cpa16(bd_b + (uint32_t)((row * BDF + seg) << 1), g);
        }
    };

    loadK(0, 0); CP_COMMIT();
    const __half* qb16 = heads16 + (size_t)MEMLEN * BSZ * H3;
#pragma unroll
    for (int it = 0; it < 4; it++) {
        const int idx = tid + it * 256;
        const int row = idx >> 4, c4 = (idx & 15) * 4;
        const __half2* qp = (const __half2*)(qb16 + ((size_t)(i0 + row) * BSZ + b) * H3 + n * DHEAD + c4);
        const float2 q0 = __half22float2(qp[0]);
        const float2 q1 = __half22float2(qp[1]);
        const float4 bb = *(const float4*)(rwb + n * DHEAD + c4);
        *(__half2*)(Qs16 + row * KSTR + c4)     = __floats2half2_rn(q0.x + bb.x, q0.y + bb.y);
        *(__half2*)(Qs16 + row * KSTR + c4 + 2) = __floats2half2_rn(q1.x + bb.z, q1.y + bb.w);
    }

    float m0 = -1e30f, m1 = -1e30f, l0 = 0.f, l1 = 0.f;

    float accO[8][4];
#pragma unroll
    for (int nt = 0; nt < 8; nt++)
#pragma unroll
        for (int q = 0; q < 4; q++) accO[nt][q] = 0.f;

    CP_WAIT(0);
    __syncthreads();

    for (int jt = 0; jt < njt; jt++) {
        const int j0 = jt * 128;
        const int cur = jt & 1;
        const bool more = (jt + 1 < njt);

        loadV(jt); loadBd(jt); CP_COMMIT();
        if (more) { loadK(jt + 1, cur ^ 1); CP_COMMIT(); }

        // ---- S = Qw . K^T : warp tile 16 rows x 64 cols ----
        float accS[8][4];
#pragma unroll
        for (int nt = 0; nt < 8; nt++)
#pragma unroll
            for (int q = 0; q < 4; q++) accS[nt][q] = 0.f;

#pragma unroll
        for (int kk = 0; kk < 64; kk += 16) {
            uint32_t af[4], bfr[8][2];
            {
                const uint32_t addr = qs_b +
                    (uint32_t)(((wm + aRow) * KSTR + kk + selOff) << 1);
                LDSM_X4(af[0], af[1], af[2], af[3], addr);
            }
#pragma unroll
            for (int p = 0; p < 4; p++) {
                uint32_t r0, r1, r2, r3;
                const uint32_t addr = ks_b +
                    (uint32_t)((((cur << 7) + chh * 64 + p * 16 + aRow) * KSTR + kk + selOff) << 1);
                LDSM_X4(r0, r1, r2, r3, addr);
                bfr[2 * p][0] = r0; bfr[2 * p][1] = r2;
                bfr[2 * p + 1][0] = r1; bfr[2 * p + 1][1] = r3;
            }
#pragma unroll
            for (int nt = 0; nt < 8; nt++)
                MMA_F16(accS[nt], af, bfr[nt]);
        }

        if (more) { CP_WAIT(1); } else { CP_WAIT(0); }
        __syncthreads();

        const int dcol = j0 + chh * 64 - (i0 + wm);
        const int lim0 = lr + MEMLEN - dcol;
        const int lim1 = lim0 + 8;
        float mx0 = -1e30f, mx1 = -1e30f;
#pragma unroll
        for (int nt = 0; nt < 8; nt++) {
            const int cl = nt * 8 + 2 * lc;
            const float2 b0 = __half22float2(*(const __half2*)&Bds[(wm + lr) * BDF + chh * 64 + nt * 8 + 2 * lc]);
            const float2 b1 = __half22float2(*(const __half2*)&Bds[(wm + lr + 8) * BDF + chh * 64 + nt * 8 + 2 * lc]);
            accS[nt][0] = (cl     <= lim0) ? (accS[nt][0] + b0.x) * 0.125f : -1e30f;
            accS[nt][1] = (cl + 1 <= lim0) ? (accS[nt][1] + b0.y) * 0.125f : -1e30f;
            accS[nt][2] = (cl     <= lim1) ? (accS[nt][2] + b1.x) * 0.125f : -1e30f;
            accS[nt][3] = (cl + 1 <= lim1) ? (accS[nt][3] + b1.y) * 0.125f : -1e30f;
            mx0 = fmaxf(mx0, fmaxf(accS[nt][0], accS[nt][1]));
            mx1 = fmaxf(mx1, fmaxf(accS[nt][2], accS[nt][3]));
        }
#pragma unroll
        for (int o = 1; o <= 2; o <<= 1) {
            mx0 = fmaxf(mx0, __shfl_xor_sync(0xffffffffu, mx0, o));
            mx1 = fmaxf(mx1, __shfl_xor_sync(0xffffffffu, mx1, o));
        }
        if (lc == 0) {
            pmax[chh * 64 + wm + lr] = mx0;
            pmax[chh * 64 + wm + lr + 8] = mx1;
        }
        __syncthreads();

        const float nm0 = fmaxf(m0, fmaxf(pmax[wm + lr], pmax[64 + wm + lr]));
        const float nm1 = fmaxf(m1, fmaxf(pmax[wm + lr + 8], pmax[64 + wm + lr + 8]));

        uint32_t pLo[8], pHi[8];
        float ls0 = 0.f, ls1 = 0.f;
#pragma unroll
        for (int nt = 0; nt < 8; nt++) {
            const __half2 h0 = __floats2half2_rn(__expf(accS[nt][0] - nm0),
                                                 __expf(accS[nt][1] - nm0));
            const __half2 h1 = __floats2half2_rn(__expf(accS[nt][2] - nm1),
                                                 __expf(accS[nt][3] - nm1));
            pLo[nt] = *(const uint32_t*)&h0;
            pHi[nt] = *(const uint32_t*)&h1;
            const float2 f0 = __half22float2(h0);
            const float2 f1 = __half22float2(h1);
            ls0 += f0.x + f0.y;
            ls1 += f1.x + f1.y;
        }
#pragma unroll
        for (int o = 1; o <= 2; o <<= 1) {
            ls0 += __shfl_xor_sync(0xffffffffu, ls0, o);
            ls1 += __shfl_xor_sync(0xffffffffu, ls1, o);
        }
        if (lc == 0) {
            psum[chh * 64 + wm + lr] = ls0;
            psum[chh * 64 + wm + lr + 8] = ls1;
        }
        __syncthreads();

        const float lt0 = psum[wm + lr] + psum[64 + wm + lr];
        const float lt1 = psum[wm + lr + 8] + psum[64 + wm + lr + 8];
        const float a0 = __expf(m0 - nm0);
        const float a1 = __expf(m1 - nm1);
        m0 = nm0; m1 = nm1;
        l0 = l0 * a0 + lt0;
        l1 = l1 * a1 + lt1;

#pragma unroll
        for (int nt = 0; nt < 8; nt++) {
            accO[nt][0] *= a0; accO[nt][1] *= a0;
            accO[nt][2] *= a1; accO[nt][3] *= a1;
        }
#pragma unroll
        for (int p = 0; p < 4; p++) {
            uint32_t af[4];
            af[0] = pLo[2 * p];     af[1] = pHi[2 * p];
            af[2] = pLo[2 * p + 1]; af[3] = pHi[2 * p + 1];
            uint32_t bf[8][2];
#pragma unroll
            for (int nb = 0; nb < 4; nb++) {
                const uint32_t addr = vs_b +
                    (uint32_t)(((chh * 64 + p * 16 + aRow) * KSTR + nb * 16 + selOff) << 1);
                LDSM_X4T(bf[2 * nb][0], bf[2 * nb][1],
                         bf[2 * nb + 1][0], bf[2 * nb + 1][1], addr);
            }
#pragma unroll
            for (int nt = 0; nt < 8; nt++)
                MMA_F16(accO[nt], af, bf[nt]);
        }

        if (more) CP_WAIT(0);
        __syncthreads();
    }

    // ---- finalize: sum col-half partials through smem, write av16 ----
    if (chh == 1) {
#pragma unroll
        for (int nt = 0; nt < 8; nt++) {
            const int col = nt * 8 + 2 * lc;
            *(float2*)&Osum[(wm + lr) * OSTR + col] =
                make_float2(accO[nt][0], accO[nt][1]);
            *(float2*)&Osum[(wm + lr + 8) * OSTR + col] =
                make_float2(accO[nt][2], accO[nt][3]);
        }
    }
    __syncthreads();
    if (chh == 0) {
        const float inv0 = 1.f / l0;
        const float inv1 = 1.f / l1;
#pragma unroll
        for (int nt = 0; nt < 8; nt++) {
            const int col = nt * 8 + 2 * lc;
            const float2 s0 = *(const float2*)&Osum[(wm + lr) * OSTR + col];
            const float2 s1 = *(const float2*)&Osum[(wm + lr + 8) * OSTR + col];
            __half2* p0 = (__half2*)(av16 + ((size_t)(i0 + wm + lr) * BSZ + b) * DMODEL + n * DHEAD + col);
            *p0 = __floats2half2_rn((accO[nt][0] + s0.x) * inv0,
                                    (accO[nt][1] + s0.y) * inv0);
            __half2* p1 = (__half2*)(av16 + ((size_t)(i0 + wm + lr + 8) * BSZ + b) * DMODEL + n * DHEAD + col);
            *p1 = __floats2half2_rn((accO[nt][2] + s1.x) * inv1,
                                    (accO[nt][3] + s1.y) * inv1);
        }
    }
}

// ----------------------------------------------------------------------------
__device__ __forceinline__ float warpSum(float v) {
#pragma unroll
    for (int o = 16; o; o >>= 1) v += __shfl_xor_sync(0xffffffffu, v, o);
    return v;
}

__global__ __launch_bounds__(256) void ln_k(
    const float* __restrict__ X, const float* __restrict__ gam,
    const float* __restrict__ bet, float* __restrict__ Y,
    __half* __restrict__ Y16)
{
    __shared__ float red[8];
    const size_t row = blockIdx.x;
    const int tid = threadIdx.x;
    const float4 v = *(const float4*)(X + row * DMODEL + tid * 4);
    float s = v.x + v.y + v.z + v.w;
    float q = v.x * v.x + v.y * v.y + v.z * v.z + v.w * v.w;

    float ws = warpSum(s);
    if ((tid & 31) == 0) red[tid >> 5] = ws;
    __syncthreads();
    if (tid < 32) {
        float t = (tid < 8) ? red[tid] : 0.f;
        t = warpSum(t);
        if (tid == 0) red[0] = t;
    }
    __syncthreads();
    const float mu = red[0] * (1.f / DMODEL);
    __syncthreads();

    float wq = warpSum(q);
    if ((tid & 31) == 0) red[tid >> 5] = wq;
    __syncthreads();
    if (tid < 32) {
        float t = (tid < 8) ? red[tid] : 0.f;
        t = warpSum(t);
        if (tid == 0) red[0] = t;
    }
    __syncthreads();
    const float var = red[0] * (1.f / DMODEL) - mu * mu;
    const float rs = rsqrtf(var + 1e-5f);

    const float4 gv = *(const float4*)(gam + tid * 4);
    const float4 bv = *(const float4*)(bet + tid * 4);
    float4 o;
    o.x = (v.x - mu) * rs * gv.x + bv.x;
    o.y = (v.y - mu) * rs * gv.y + bv.y;
    o.z = (v.z - mu) * rs * gv.z + bv.z;
    o.w = (v.w - mu) * rs * gv.w + bv.w;
    *(float4*)(Y + row * DMODEL + tid * 4) = o;
    if (Y16) {
        __half2 h[2] = { __floats2half2_rn(o.x, o.y), __floats2half2_rn(o.z, o.w) };
        *(uint2*)(Y16 + row * DMODEL + tid * 4) = *(uint2*)h;
    }
}

// ----------------------------------------------------------------------------
extern "C" void kernel_launch(void* const* d_in, const int* in_sizes, int n_in,
                              void* d_out, int out_size)
{
    (void)in_sizes; (void)n_in; (void)out_size;
    const float* w       = (const float*)d_in[0];
    const float* r       = (const float*)d_in[1];
    const float* mems    = (const float*)d_in[2];
    const float* qkv_w   = (const float*)d_in[3];
    const float* r_net_w = (const float*)d_in[4];
    const float* o_w     = (const float*)d_in[5];
    const float* rwb     = (const float*)d_in[6];
    const float* rrb     = (const float*)d_in[7];
    const float* ln1g    = (const float*)d_in[8];
    const float* ln1b    = (const float*)d_in[9];
    const float* ffw1    = (const float*)d_in[10];
    const float* ffb1    = (const float*)d_in[11];
    const float* ffw2    = (const float*)d_in[12];
    const float* ffb2    = (const float*)d_in[13];
    const float* ln2g    = (const float*)d_in[14];
    const float* ln2b    = (const float*)d_in[15];
    float* out = (float*)d_out;

    float *rbias, *tmp, *out1;
    __half *heads16, *rk16, *BD, *av16, *out116, *ffh16;
    __half *cat16, *r16, *qkvw16, *rnw16, *ow16, *ffw116, *ffw216;
    cudaGetSymbolAddress((void**)&heads16, g_heads16);
    cudaGetSymbolAddress((void**)&rk16,    g_rk16);
    cudaGetSymbolAddress((void**)&rbias,   g_rbias);
    cudaGetSymbolAddress((void**)&BD,      g_BD);
    cudaGetSymbolAddress((void**)&av16,    g_av16);
    cudaGetSymbolAddress((void**)&tmp,     g_tmp);
    cudaGetSymbolAddress((void**)&out1,    g_out1);
    cudaGetSymbolAddress((void**)&out116,  g_out116);
    cudaGetSymbolAddress((void**)&ffh16,   g_ffh16);
    cudaGetSymbolAddress((void**)&cat16,   g_cat16);
    cudaGetSymbolAddress((void**)&r16,     g_r16);
    cudaGetSymbolAddress((void**)&qkvw16,  g_qkvw16);
    cudaGetSymbolAddress((void**)&rnw16,   g_rnw16);
    cudaGetSymbolAddress((void**)&ow16,    g_ow16);
    cudaGetSymbolAddress((void**)&ffw116,  g_ffw116);
    cudaGetSymbolAddress((void**)&ffw216,  g_ffw216);

    static cudaStream_t s1 = nullptr;
    static cudaEvent_t evFork = nullptr, evJoin = nullptr;
    static int s_init_done = 0;
    if (!s_init_done) {
        cudaFuncSetAttribute(flash_k, cudaFuncAttributeMaxDynamicSharedMemorySize,
                             FLASH_SMEM);
        cudaStreamCreateWithFlags(&s1, cudaStreamNonBlocking);
        cudaEventCreateWithFlags(&evFork, cudaEventDisableTiming);
        cudaEventCreateWithFlags(&evJoin, cudaEventDisableTiming);
        s_init_done = 1;
    }

    const dim3 blk(256);
    const __half* qb16 = heads16 + (size_t)MEMLEN * BSZ * H3;  // query rows

    // ---- fork side stream off the main (capture) stream ----
    cudaEventRecord(evFork, 0);
    cudaStreamWaitEvent(s1, evFork, 0);

    // side stream: r/weight conversions -> rk GEMM -> rbias
    cvt_k<<<(KLEN * DMODEL) / 2048, blk, 0, s1>>>(r, r16);
    cvt_k<<<(DMODEL * DMODEL) / 2048, blk, 0, s1>>>(r_net_w, rnw16);
    cvt_k<<<(DMODEL * DMODEL) / 2048, blk, 0, s1>>>(o_w, ow16);
    cvt_k<<<(DMODEL * DINNER) / 2048, blk, 0, s1>>>(ffw1, ffw116);
    cvt_k<<<(DINNER * DMODEL) / 2048, blk, 0, s1>>>(ffw2, ffw216);
    gemm_h<1><<<dim3(DMODEL / 128, KLEN / 128), blk, 0, s1>>>(
        r16, DMODEL, rnw16, nullptr, nullptr, 0,
        rk16, nullptr, KLEN, DMODEL, DMODEL);
    rbias_k<<<(NHEAD * KLEN) / 256, blk, 0, s1>>>(rrb, rk16, rbias);
    cudaEventRecord(evJoin, s1);

    // main stream: input conversions -> QKV GEMM
    cvt_k<<<(MEMLEN * BSZ * DMODEL) / 2048, blk>>>(mems, cat16);
    cvt_k<<<(QLEN * BSZ * DMODEL) / 2048, blk>>>(w, cat16 + (size_t)MEMLEN * BSZ * DMODEL);
    cvt_k<<<(DMODEL * H3) / 2048, blk>>>(qkv_w, qkvw16);
    gemm_h<1><<<dim3(H3 / 128, (KLEN * BSZ) / 128), blk>>>(
        cat16, DMODEL, qkvw16, nullptr, nullptr, 0,
        heads16, nullptr, KLEN * BSZ, H3, DMODEL);

    // ---- join: bd16 needs rk16 + rbias from side stream ----
    cudaStreamWaitEvent(0, evJoin, 0);

    // BDr (fp16 MMAs, j-indexed shifted fp16 out, diag skip)
    bd16_gemm<<<dim3(KLEN / 128, QLEN / 128, BSZ * NHEAD), blk>>>(
        qb16, rk16, rbias, BD);

    // flash (64-row tiles, 2 CTAs/SM) -> av16
    flash_k<<<dim3(QLEN / 64, BSZ * NHEAD), dim3(256), FLASH_SMEM>>>(
        heads16, BD, rwb, av16);

    // attn_out = av16 @ ow16 + w
    gemm_h<0><<<dim3(DMODEL / 128, (QLEN * BSZ) / 128), blk>>>(
        av16, DMODEL, ow16, nullptr, w, 0,
        tmp, nullptr, QLEN * BSZ, DMODEL, DMODEL);

    // LN1 (dual fp32 + fp16)
    ln_k<<<QLEN * BSZ, blk>>>(tmp, ln1g, ln1b, out1, out116);

    // ffh16 = relu(out116 @ ffw116 + b1) (fp16 out)
    gemm_h<1><<<dim3(DINNER / 128, (QLEN * BSZ) / 128), blk>>>(
        out116, DMODEL, ffw116, ffb1, nullptr, 1,
        ffh16, nullptr, QLEN * BSZ, DINNER, DMODEL);

    // tmp = ffh16 @ ffw216 + b2 + out1
    gemm_h<0><<<dim3(DMODEL / 128, (QLEN * BSZ) / 128), blk>>>(
        ffh16, DINNER, ffw216, ffb2, out1, 0,
        tmp, nullptr, QLEN * BSZ, DMODEL, DINNER);

    // LN2 -> output
    ln_k<<<QLEN * BSZ, blk>>>(tmp, ln2g, ln2b, out, nullptr);
}

// round 15
// speedup vs baseline: 2.6159x; 1.0118x over previous
#include <cuda_runtime.h>
#include <cuda_fp16.h>
#include <math.h>
#include <stdint.h>

#define QLEN   1024
#define BSZ    4
#define DMODEL 1024
#define NHEAD  16
#define DHEAD  64
#define DINNER 4096
#define MEMLEN 1024
#define KLEN   2048
#define H3     (3 * DMODEL)   // 3072

// ---- static device scratch (no cudaMalloc allowed) ----
__device__ __half g_heads16[(size_t)KLEN * BSZ * H3];        // fp16 QKV heads
__device__ __half g_rk16[(size_t)KLEN * DMODEL];             // fp16 rk
__device__ float  g_rbias[(size_t)NHEAD * KLEN];
__device__ __half g_BD[(size_t)BSZ * NHEAD * QLEN * KLEN];   // j-indexed BDr
__device__ __half g_av16[(size_t)QLEN * BSZ * DMODEL];
__device__ float  g_tmp[(size_t)QLEN * BSZ * DMODEL];
__device__ float  g_out1[(size_t)QLEN * BSZ * DMODEL];
__device__ __half g_out116[(size_t)QLEN * BSZ * DMODEL];
__device__ __half g_ffh16[(size_t)QLEN * BSZ * DINNER];
__device__ __half g_cat16[(size_t)KLEN * BSZ * DMODEL];
__device__ __half g_r16[(size_t)KLEN * DMODEL];
__device__ __half g_qkvw16[(size_t)DMODEL * H3];
__device__ __half g_rnw16[(size_t)DMODEL * DMODEL];
__device__ __half g_ow16[(size_t)DMODEL * DMODEL];
__device__ __half g_ffw116[(size_t)DMODEL * DINNER];
__device__ __half g_ffw216[(size_t)DINNER * DMODEL];

__device__ __forceinline__ void cpa16(uint32_t s, const void* g) {
    asm volatile("cp.async.cg.shared.global [%0], [%1], 16;" :: "r"(s), "l"(g));
}
#define CP_COMMIT() asm volatile("cp.async.commit_group;")
#define CP_WAIT(N)  asm volatile("cp.async.wait_group %0;" :: "n"(N))

#define MMA_F16(acc, av, bv)                                                \
    asm volatile(                                                           \
        "mma.sync.aligned.m16n8k16.row.col.f32.f16.f16.f32 "                \
        "{%0,%1,%2,%3}, {%4,%5,%6,%7}, {%8,%9}, {%0,%1,%2,%3};"             \
        : "+f"(acc[0]), "+f"(acc[1]), "+f"(acc[2]), "+f"(acc[3])            \
        : "r"(av[0]), "r"(av[1]), "r"(av[2]), "r"(av[3]),                   \
          "r"(bv[0]), "r"(bv[1]))

#define LDSM_X4(r0, r1, r2, r3, addr)                                       \
    asm volatile("ldmatrix.sync.aligned.m8n8.x4.shared.b16 {%0,%1,%2,%3}, [%4];" \
        : "=r"(r0), "=r"(r1), "=r"(r2), "=r"(r3) : "r"(addr))
#define LDSM_X4T(r0, r1, r2, r3, addr)                                      \
    asm volatile("ldmatrix.sync.aligned.m8n8.x4.trans.shared.b16 {%0,%1,%2,%3}, [%4];" \
        : "=r"(r0), "=r"(r1), "=r"(r2), "=r"(r3) : "r"(addr))

// ----------------------------------------------------------------------------
__global__ __launch_bounds__(256) void cvt_k(
    const float* __restrict__ src, __half* __restrict__ dst)
{
    const int i = (blockIdx.x * 256 + threadIdx.x) * 8;
    const float4 a = *(const float4*)(src + i);
    const float4 b = *(const float4*)(src + i + 4);
    __half2 h[4];
    h[0] = __floats2half2_rn(a.x, a.y);
    h[1] = __floats2half2_rn(a.z, a.w);
    h[2] = __floats2half2_rn(b.x, b.y);
    h[3] = __floats2half2_rn(b.z, b.w);
    *(uint4*)(dst + i) = *(uint4*)h;
}

// ----------------------------------------------------------------------------
// Dense fp16 GEMM with separate B/C strides (ldb/ldc, in elements).
// HOUT=0: fp32 out. HOUT=1: fp16 out.
// ----------------------------------------------------------------------------
#define ASTR 40
#define BSTR 136

template <int HOUT>
__global__ __launch_bounds__(256, 2) void gemm_h(
    const __half* __restrict__ A, int lda,
    const __half* __restrict__ B, int ldb,
    const float* __restrict__ bias, const float* __restrict__ resid, int doRelu,
    void* __restrict__ Cv, __half* __restrict__ C16, int ldc,
    int M, int N, int Kd)
{
    __shared__ __half As[3][128 * ASTR];
    __shared__ __half Bs[3][32 * BSTR];

    const int tid  = threadIdx.x;
    const int warp = tid >> 5, lane = tid & 31;
    const int lr = lane >> 2, lc = lane & 3;
    const int bm = blockIdx.y * 128, bn = blockIdx.x * 128;
    const int wm = (warp & 1) * 64;
    const int wn = (warp >> 1) * 32;

    float acc[4][4][4];
#pragma unroll
    for (int mt = 0; mt < 4; mt++)
#pragma unroll
        for (int nt = 0; nt < 4; nt++)
#pragma unroll
            for (int q = 0; q < 4; q++) acc[mt][nt][q] = 0.f;

    const __half* aPtr[2];
    const __half* bPtr[2];
    uint32_t aDst[2], bDst[2];
#pragma unroll
    for (int h = 0; h < 2; h++) {
        const int ch = tid + h * 256;
        const int ar = ch >> 2, ao = (ch & 3) * 8;
        aPtr[h] = A + (long long)(bm + ar) * lda + ao;
        aDst[h] = (uint32_t)__cvta_generic_to_shared(&As[0][ar * ASTR + ao]);
        const int br = ch >> 4, bo = (ch & 15) * 8;
        bPtr[h] = B + (long long)br * ldb + bn + bo;
        bDst[h] = (uint32_t)__cvta_generic_to_shared(&Bs[0][br * BSTR + bo]);
    }
    const long long bStep = (long long)32 * ldb;

    auto load = [&](int kt, int s) {
#pragma unroll
        for (int h = 0; h < 2; h++)
            cpa16(aDst[h] + s * 128 * ASTR * 2, aPtr[h] + kt * 32);
#pragma unroll
        for (int h = 0; h < 2; h++)
            cpa16(bDst[h] + s * 32 * BSTR * 2, bPtr[h] + kt * bStep);
    };

    const int aRow = lane & 15;
    const int selOff = (lane >> 4) << 3;
    const uint32_t asBase = (uint32_t)__cvta_generic_to_shared(&As[0][0]);
    const uint32_t bsBase = (uint32_t)__cvta_generic_to_shared(&Bs[0][0]);

    const int nk = Kd >> 5;
    load(0, 0); CP_COMMIT();
    load(1, 1); CP_COMMIT();

    for (int kt = 0; kt < nk; kt++) {
        const int s = kt % 3;
        CP_WAIT(1);
        __syncthreads();
        if (kt + 2 < nk) load(kt + 2, (kt + 2) % 3);
        CP_COMMIT();

        const uint32_t aS = asBase + (uint32_t)(s * 128 * ASTR * 2);
        const uint32_t bS = bsBase + (uint32_t)(s * 32 * BSTR * 2);
#pragma unroll
        for (int kk = 0; kk < 32; kk += 16) {
            uint32_t af[4][4], bf[4][2];
#pragma unroll
            for (int mt = 0; mt < 4; mt++) {
                const uint32_t addr = aS +
                    (uint32_t)(((wm + mt * 16 + aRow) * ASTR + kk + selOff) * 2);
                LDSM_X4(af[mt][0], af[mt][1], af[mt][2], af[mt][3], addr);
            }
#pragma unroll
            for (int ntp = 0; ntp < 2; ntp++) {
                const uint32_t addr = bS +
                    (uint32_t)(((kk + aRow) * BSTR + wn + ntp * 16 + selOff) * 2);
                LDSM_X4T(bf[2 * ntp][0], bf[2 * ntp][1],
                         bf[2 * ntp + 1][0], bf[2 * ntp + 1][1], addr);
            }
#pragma unroll
            for (int mt = 0; mt < 4; mt++)
#pragma unroll
                for (int nt = 0; nt < 4; nt++)
                    MMA_F16(acc[mt][nt], af[mt], bf[nt]);
        }
    }

#pragma unroll
    for (int mt = 0; mt < 4; mt++) {
#pragma unroll
        for (int nt = 0; nt < 4; nt++) {
            const int col = bn + wn + nt * 8 + lc * 2;
#pragma unroll
            for (int half = 0; half < 2; half++) {
                const int row = bm + wm + mt * 16 + lr + half * 8;
                float v0 = acc[mt][nt][half * 2 + 0];
                float v1 = acc[mt][nt][half * 2 + 1];
                if (bias) { v0 += bias[col]; v1 += bias[col + 1]; }
                if (resid) {
                    const float* rp = resid + (long long)row * ldc + col;
                    v0 += rp[0]; v1 += rp[1];
                }
                if (doRelu) { v0 = fmaxf(v0, 0.f); v1 = fmaxf(v1, 0.f); }
                if (HOUT == 1) {
                    *(__half2*)((__half*)Cv + (long long)row * ldc + col) =
                        __floats2half2_rn(v0, v1);
                } else {
                    float* cp = (float*)Cv + (long long)row * ldc + col;
                    cp[0] = v0; cp[1] = v1;
                }
            }
        }
    }
}

// ----------------------------------------------------------------------------
// rbias[n][c] = rrb_n . rk16_c  (fp32 accumulate over fp16 rk)
// ----------------------------------------------------------------------------
__global__ __launch_bounds__(256) void rbias_k(
    const float* __restrict__ rrb, const __half* __restrict__ rk16,
    float* __restrict__ rbias)
{
    const int idx = blockIdx.x * 256 + threadIdx.x;
    const int c = idx >> 4, n = idx & 15;
    const __half2* rp = (const __half2*)(rk16 + (size_t)c * DMODEL + n * DHEAD);
    const float* bp = rrb + n * DHEAD;
    float s = 0.f;
#pragma unroll
    for (int d = 0; d < 32; d++) {
        const float2 rv = __half22float2(rp[d]);
        s += rv.x * bp[2 * d] + rv.y * bp[2 * d + 1];
    }
    rbias[n * KLEN + c] = s;
}

// ----------------------------------------------------------------------------
// BD GEMM fp16, j-indexed output: BDr[bn][i][j] = q_i . rk_{j-i+1023} + rbias.
// ----------------------------------------------------------------------------
#define BDSTR 72

__global__ __launch_bounds__(256, 2) void bd16_gemm(
    const __half* __restrict__ Q16,
    const __half* __restrict__ RK16,
    const float* __restrict__ rbias, __half* __restrict__ BD)
{
    __shared__ __half As[128 * BDSTR];
    __shared__ __half Bs[128 * BDSTR];

    const int tid = threadIdx.x;
    const int warp = tid >> 5, lane = tid & 31;
    const int lr = lane >> 2, lc = lane & 3;
    const int bm = blockIdx.y * 128, bn = blockIdx.x * 128;
    if (bm + bn < 769) return;   // whole tile lands at j < 0, never read
    const int bnidx = blockIdx.z;
    const int b = bnidx >> 4, n = bnidx & 15;
    const int wm = (warp & 1) * 64;
    const int wn = (warp >> 1) * 32;
    const int aRow = lane & 15;
    const int selOff = (lane >> 4) << 3;
    const uint32_t as_b = (uint32_t)__cvta_generic_to_shared(As);
    const uint32_t bs_b = (uint32_t)__cvta_generic_to_shared(Bs);

#pragma unroll
    for (int h = 0; h < 4; h++) {
        const int ch = tid + h * 256;
        const int row = ch >> 3, seg = (ch & 7) * 8;
        const __half* ga = Q16 + ((size_t)(bm + row) * BSZ + b) * H3 + n * DHEAD + seg;
        cpa16(as_b + (uint32_t)((row * BDSTR + seg) << 1), ga);
    }
#pragma unroll
    for (int h = 0; h < 4; h++) {
        const int ch = tid + h * 256;
        const int row = ch >> 3, seg = (ch & 7) * 8;
        const __half* gb = RK16 + (size_t)(bn + row) * DMODEL + n * DHEAD + seg;
        cpa16(bs_b + (uint32_t)((row * BDSTR + seg) << 1), gb);
    }
    CP_COMMIT();

    float acc[4][4][4];
#pragma unroll
    for (int mt = 0; mt < 4; mt++)
#pragma unroll
        for (int nt = 0; nt < 4; nt++)
#pragma unroll
            for (int q = 0; q < 4; q++) acc[mt][nt][q] = 0.f;

    CP_WAIT(0);
    __syncthreads();

#pragma unroll
    for (int kk = 0; kk < 64; kk += 16) {
        uint32_t af[4][4], bfr[4][2];
#pragma unroll
        for (int mt = 0; mt < 4; mt++) {
            const uint32_t addr = as_b +
                (uint32_t)(((wm + mt * 16 + aRow) * BDSTR + kk + selOff) << 1);
            LDSM_X4(af[mt][0], af[mt][1], af[mt][2], af[mt][3], addr);
        }
#pragma unroll
        for (int p = 0; p < 2; p++) {
            uint32_t r0, r1, r2, r3;
            const uint32_t addr = bs_b +
                (uint32_t)(((wn + p * 16 + aRow) * BDSTR + kk + selOff) << 1);
            LDSM_X4(r0, r1, r2, r3, addr);
            bfr[2 * p][0] = r0; bfr[2 * p][1] = r2;
            bfr[2 * p + 1][0] = r1; bfr[2 * p + 1][1] = r3;
        }
#pragma unroll
        for (int mt = 0; mt < 4; mt++)
#pragma unroll
            for (int nt = 0; nt < 4; nt++)
                MMA_F16(acc[mt][nt], af[mt], bfr[nt]);
    }

    // epilogue: + rbias, rel-shifted fp16 store (j = c + i - 1023)
#pragma unroll
    for (int mt = 0; mt < 4; mt++) {
#pragma unroll
        for (int nt = 0; nt < 4; nt++) {
            const int col = bn + wn + nt * 8 + lc * 2;
            const float rb0 = rbias[n * KLEN + col];
            const float rb1 = rbias[n * KLEN + col + 1];
#pragma unroll
            for (int half = 0; half < 2; half++) {
                const int row = bm + wm + mt * 16 + lr + half * 8;
                const float v0 = acc[mt][nt][half * 2 + 0] + rb0;
                const float v1 = acc[mt][nt][half * 2 + 1] + rb1;
                __half* rowp = BD + ((size_t)bnidx * QLEN + row) * KLEN;
                const int j = col + row - (QLEN - 1);
                if (j >= 0)     rowp[j]     = __float2half_rn(v0);
                if (j + 1 >= 0) rowp[j + 1] = __float2half_rn(v1);
            }
        }
    }
}

// ----------------------------------------------------------------------------
// Flash attention (proven v6): 64-row q-tiles, 256 threads, 2 CTAs/SM.
// ----------------------------------------------------------------------------
#define KSTR  72
#define BDF   136
#define OSTR  72
#define FLASH_SMEM (64*KSTR*2 /*Q*/ + 2*128*KSTR*2 /*K*/ + 128*KSTR*2 /*V*/ \
                    + 64*BDF*2 /*Bd*/ + 2*64*4 /*pmax*/ + 2*64*4 /*psum*/)

__global__ __launch_bounds__(256, 2) void flash_k(
    const __half* __restrict__ heads16,
    const __half* __restrict__ BD,
    const float* __restrict__ rwb, __half* __restrict__ av16)
{
    extern __shared__ char smc[];
    __half* Qs16 = (__half*)smc;
    __half* Ks16 = Qs16 + 64 * KSTR;
    __half* Vs16 = Ks16 + 2 * 128 * KSTR;
    __half* Bds  = Vs16 + 128 * KSTR;
    float*  pmax = (float*)(Bds + 64 * BDF);
    float*  psum = pmax + 2 * 64;
    float*  Osum = (float*)Ks16;
    const uint32_t qs_b = (uint32_t)__cvta_generic_to_shared(Qs16);
    const uint32_t ks_b = (uint32_t)__cvta_generic_to_shared(Ks16);
    const uint32_t vs_b = (uint32_t)__cvta_generic_to_shared(Vs16);
    const uint32_t bd_b = (uint32_t)__cvta_generic_to_shared(Bds);

    const int tid = threadIdx.x;
    const int warp = tid >> 5, lane = tid & 31;
    const int lr = lane >> 2, lc = lane & 3;
    const int aRow = lane & 15;
    const int selOff = (lane >> 4) << 3;
    const int qt = (int)gridDim.x - 1 - (int)blockIdx.x;   // longest-first
    const int i0 = qt * 64;
    const int bn = blockIdx.y;
    const int b = bn >> 4, n = bn & 15;
    const int rg  = warp & 3;
    const int chh = warp >> 2;
    const int wm  = rg * 16;
    const int njt = ((i0 + 63 + MEMLEN) >> 7) + 1;

    auto loadK = [&](int jt, int buf) {
        const int j0 = jt * 128;
#pragma unroll
        for (int it = 0; it < 4; it++) {
            const int c = tid + it * 256;
            const int row = c >> 3, seg = (c & 7) << 3;
            const __half* g = heads16 + ((size_t)(j0 + row) * BSZ + b) * H3 + DMODEL + n * DHEAD + seg;
            cpa16(ks_b + (uint32_t)((((buf << 7) + row) * KSTR + seg) << 1), g);
        }
    };
    auto loadV = [&](int jt) {
        const int j0 = jt * 128;
#pragma unroll
        for (int it = 0; it < 4; it++) {
            const int c = tid + it * 256;
            const int row = c >> 3, seg = (c & 7) << 3;
            const __half* g = heads16 + ((size_t)(j0 + row) * BSZ + b) * H3 + 2 * DMODEL + n * DHEAD + seg;
            cpa16(vs_b + (uint32_t)((row * KSTR + seg) << 1), g);
        }
    };
    auto loadBd = [&](int jt) {
        const int j0 = jt * 128;
#pragma unroll
        for (int it = 0; it < 4; it++) {
            const int c = tid + it * 256;
            const int row = c >> 4, seg = (c & 15) << 3;
            const __half* g = BD + ((size_t)bn * QLEN + i0 + row) * KLEN + j0 + seg;
            cpa16(bd_b + (uint32_t)((row * BDF + seg) << 1), g);
        }
    };

    loadK(0, 0); CP_COMMIT();
    const __half* qb16 = heads16 + (size_t)MEMLEN * BSZ * H3;
#pragma unroll
    for (int it = 0; it < 4; it++) {
        const int idx = tid + it * 256;
        const int row = idx >> 4, c4 = (idx & 15) * 4;
        const __half2* qp = (const __half2*)(qb16 + ((size_t)(i0 + row) * BSZ + b) * H3 + n * DHEAD + c4);
        const float2 q0 = __half22float2(qp[0]);
        const float2 q1 = __half22float2(qp[1]);
        const float4 bb = *(const float4*)(rwb + n * DHEAD + c4);
        *(__half2*)(Qs16 + row * KSTR + c4)     = __floats2half2_rn(q0.x + bb.x, q0.y + bb.y);
        *(__half2*)(Qs16 + row * KSTR + c4 + 2) = __floats2half2_rn(q1.x + bb.z, q1.y + bb.w);
    }

    float m0 = -1e30f, m1 = -1e30f, l0 = 0.f, l1 = 0.f;

    float accO[8][4];
#pragma unroll
    for (int nt = 0; nt < 8; nt++)
#pragma unroll
        for (int q = 0; q < 4; q++) accO[nt][q] = 0.f;

    CP_WAIT(0);
    __syncthreads();

    for (int jt = 0; jt < njt; jt++) {
        const int j0 = jt * 128;
        const int cur = jt & 1;
        const bool more = (jt + 1 < njt);

        loadV(jt); loadBd(jt); CP_COMMIT();
        if (more) { loadK(jt + 1, cur ^ 1); CP_COMMIT(); }

        float accS[8][4];
#pragma unroll
        for (int nt = 0; nt < 8; nt++)
#pragma unroll
            for (int q = 0; q < 4; q++) accS[nt][q] = 0.f;

#pragma unroll
        for (int kk = 0; kk < 64; kk += 16) {
            uint32_t af[4], bfr[8][2];
            {
                const uint32_t addr = qs_b +
                    (uint32_t)(((wm + aRow) * KSTR + kk + selOff) << 1);
                LDSM_X4(af[0], af[1], af[2], af[3], addr);
            }
#pragma unroll
            for (int p = 0; p < 4; p++) {
                uint32_t r0, r1, r2, r3;
                const uint32_t addr = ks_b +
                    (uint32_t)((((cur << 7) + chh * 64 + p * 16 + aRow) * KSTR + kk + selOff) << 1);
                LDSM_X4(r0, r1, r2, r3, addr);
                bfr[2 * p][0] = r0; bfr[2 * p][1] = r2;
                bfr[2 * p + 1][0] = r1; bfr[2 * p + 1][1] = r3;
            }
#pragma unroll
            for (int nt = 0; nt < 8; nt++)
                MMA_F16(accS[nt], af, bfr[nt]);
        }

        if (more) { CP_WAIT(1); } else { CP_WAIT(0); }
        __syncthreads();

        const int dcol = j0 + chh * 64 - (i0 + wm);
        const int lim0 = lr + MEMLEN - dcol;
        const int lim1 = lim0 + 8;
        float mx0 = -1e30f, mx1 = -1e30f;
#pragma unroll
        for (int nt = 0; nt < 8; nt++) {
            const int cl = nt * 8 + 2 * lc;
            const float2 b0 = __half22float2(*(const __half2*)&Bds[(wm + lr) * BDF + chh * 64 + nt * 8 + 2 * lc]);
            const float2 b1 = __half22float2(*(const __half2*)&Bds[(wm + lr + 8) * BDF + chh * 64 + nt * 8 + 2 * lc]);
            accS[nt][0] = (cl     <= lim0) ? (accS[nt][0] + b0.x) * 0.125f : -1e30f;
            accS[nt][1] = (cl + 1 <= lim0) ? (accS[nt][1] + b0.y) * 0.125f : -1e30f;
            accS[nt][2] = (cl     <= lim1) ? (accS[nt][2] + b1.x) * 0.125f : -1e30f;
            accS[nt][3] = (cl + 1 <= lim1) ? (accS[nt][3] + b1.y) * 0.125f : -1e30f;
            mx0 = fmaxf(mx0, fmaxf(accS[nt][0], accS[nt][1]));
            mx1 = fmaxf(mx1, fmaxf(accS[nt][2], accS[nt][3]));
        }
#pragma unroll
        for (int o = 1; o <= 2; o <<= 1) {
            mx0 = fmaxf(mx0, __shfl_xor_sync(0xffffffffu, mx0, o));
            mx1 = fmaxf(mx1, __shfl_xor_sync(0xffffffffu, mx1, o));
        }
        if (lc == 0) {
            pmax[chh * 64 + wm + lr] = mx0;
            pmax[chh * 64 + wm + lr + 8] = mx1;
        }
        __syncthreads();

        const float nm0 = fmaxf(m0, fmaxf(pmax[wm + lr], pmax[64 + wm + lr]));
        const float nm1 = fmaxf(m1, fmaxf(pmax[wm + lr + 8], pmax[64 + wm + lr + 8]));

        uint32_t pLo[8], pHi[8];
        float ls0 = 0.f, ls1 = 0.f;
#pragma unroll
        for (int nt = 0; nt < 8; nt++) {
            const __half2 h0 = __floats2half2_rn(__expf(accS[nt][0] - nm0),
                                                 __expf(accS[nt][1] - nm0));
            const __half2 h1 = __floats2half2_rn(__expf(accS[nt][2] - nm1),
                                                 __expf(accS[nt][3] - nm1));
            pLo[nt] = *(const uint32_t*)&h0;
            pHi[nt] = *(const uint32_t*)&h1;
            const float2 f0 = __half22float2(h0);
            const float2 f1 = __half22float2(h1);
            ls0 += f0.x + f0.y;
            ls1 += f1.x + f1.y;
        }
#pragma unroll
        for (int o = 1; o <= 2; o <<= 1) {
            ls0 += __shfl_xor_sync(0xffffffffu, ls0, o);
            ls1 += __shfl_xor_sync(0xffffffffu, ls1, o);
        }
        if (lc == 0) {
            psum[chh * 64 + wm + lr] = ls0;
            psum[chh * 64 + wm + lr + 8] = ls1;
        }
        __syncthreads();

        const float lt0 = psum[wm + lr] + psum[64 + wm + lr];
        const float lt1 = psum[wm + lr + 8] + psum[64 + wm + lr + 8];
        const float a0 = __expf(m0 - nm0);
        const float a1 = __expf(m1 - nm1);
        m0 = nm0; m1 = nm1;
        l0 = l0 * a0 + lt0;
        l1 = l1 * a1 + lt1;

#pragma unroll
        for (int nt = 0; nt < 8; nt++) {
            accO[nt][0] *= a0; accO[nt][1] *= a0;
            accO[nt][2] *= a1; accO[nt][3] *= a1;
        }
#pragma unroll
        for (int p = 0; p < 4; p++) {
            uint32_t af[4];
            af[0] = pLo[2 * p];     af[1] = pHi[2 * p];
            af[2] = pLo[2 * p + 1]; af[3] = pHi[2 * p + 1];
            uint32_t bf[8][2];
#pragma unroll
            for (int nb = 0; nb < 4; nb++) {
                const uint32_t addr = vs_b +
                    (uint32_t)(((chh * 64 + p * 16 + aRow) * KSTR + nb * 16 + selOff) << 1);
                LDSM_X4T(bf[2 * nb][0], bf[2 * nb][1],
                         bf[2 * nb + 1][0], bf[2 * nb + 1][1], addr);
            }
#pragma unroll
            for (int nt = 0; nt < 8; nt++)
                MMA_F16(accO[nt], af, bf[nt]);
        }

        if (more) CP_WAIT(0);
        __syncthreads();
    }

    if (chh == 1) {
#pragma unroll
        for (int nt = 0; nt < 8; nt++) {
            const int col = nt * 8 + 2 * lc;
            *(float2*)&Osum[(wm + lr) * OSTR + col] =
                make_float2(accO[nt][0], accO[nt][1]);
            *(float2*)&Osum[(wm + lr + 8) * OSTR + col] =
                make_float2(accO[nt][2], accO[nt][3]);
        }
    }
    __syncthreads();
    if (chh == 0) {
        const float inv0 = 1.f / l0;
        const float inv1 = 1.f / l1;
#pragma unroll
        for (int nt = 0; nt < 8; nt++) {
            const int col = nt * 8 + 2 * lc;
            const float2 s0 = *(const float2*)&Osum[(wm + lr) * OSTR + col];
            const float2 s1 = *(const float2*)&Osum[(wm + lr + 8) * OSTR + col];
            __half2* p0 = (__half2*)(av16 + ((size_t)(i0 + wm + lr) * BSZ + b) * DMODEL + n * DHEAD + col);
            *p0 = __floats2half2_rn((accO[nt][0] + s0.x) * inv0,
                                    (accO[nt][1] + s0.y) * inv0);
            __half2* p1 = (__half2*)(av16 + ((size_t)(i0 + wm + lr + 8) * BSZ + b) * DMODEL + n * DHEAD + col);
            *p1 = __floats2half2_rn((accO[nt][2] + s1.x) * inv1,
                                    (accO[nt][3] + s1.y) * inv1);
        }
    }
}

// ----------------------------------------------------------------------------
__device__ __forceinline__ float warpSum(float v) {
#pragma unroll
    for (int o = 16; o; o >>= 1) v += __shfl_xor_sync(0xffffffffu, v, o);
    return v;
}

__global__ __launch_bounds__(256) void ln_k(
    const float* __restrict__ X, const float* __restrict__ gam,
    const float* __restrict__ bet, float* __restrict__ Y,
    __half* __restrict__ Y16)
{
    __shared__ float red[8];
    const size_t row = blockIdx.x;
    const int tid = threadIdx.x;
    const float4 v = *(const float4*)(X + row * DMODEL + tid * 4);
    float s = v.x + v.y + v.z + v.w;
    float q = v.x * v.x + v.y * v.y + v.z * v.z + v.w * v.w;

    float ws = warpSum(s);
    if ((tid & 31) == 0) red[tid >> 5] = ws;
    __syncthreads();
    if (tid < 32) {
        float t = (tid < 8) ? red[tid] : 0.f;
        t = warpSum(t);
        if (tid == 0) red[0] = t;
    }
    __syncthreads();
    const float mu = red[0] * (1.f / DMODEL);
    __syncthreads();

    float wq = warpSum(q);
    if ((tid & 31) == 0) red[tid >> 5] = wq;
    __syncthreads();
    if (tid < 32) {
        float t = (tid < 8) ? red[tid] : 0.f;
        t = warpSum(t);
        if (tid == 0) red[0] = t;
    }
    __syncthreads();
    const float var = red[0] * (1.f / DMODEL) - mu * mu;
    const float rs = rsqrtf(var + 1e-5f);

    const float4 gv = *(const float4*)(gam + tid * 4);
    const float4 bv = *(const float4*)(bet + tid * 4);
    float4 o;
    o.x = (v.x - mu) * rs * gv.x + bv.x;
    o.y = (v.y - mu) * rs * gv.y + bv.y;
    o.z = (v.z - mu) * rs * gv.z + bv.z;
    o.w = (v.w - mu) * rs * gv.w + bv.w;
    *(float4*)(Y + row * DMODEL + tid * 4) = o;
    if (Y16) {
        __half2 h[2] = { __floats2half2_rn(o.x, o.y), __floats2half2_rn(o.z, o.w) };
        *(uint2*)(Y16 + row * DMODEL + tid * 4) = *(uint2*)h;
    }
}

// ----------------------------------------------------------------------------
extern "C" void kernel_launch(void* const* d_in, const int* in_sizes, int n_in,
                              void* d_out, int out_size)
{
    (void)in_sizes; (void)n_in; (void)out_size;
    const float* w       = (const float*)d_in[0];
    const float* r       = (const float*)d_in[1];
    const float* mems    = (const float*)d_in[2];
    const float* qkv_w   = (const float*)d_in[3];
    const float* r_net_w = (const float*)d_in[4];
    const float* o_w     = (const float*)d_in[5];
    const float* rwb     = (const float*)d_in[6];
    const float* rrb     = (const float*)d_in[7];
    const float* ln1g    = (const float*)d_in[8];
    const float* ln1b    = (const float*)d_in[9];
    const float* ffw1    = (const float*)d_in[10];
    const float* ffb1    = (const float*)d_in[11];
    const float* ffw2    = (const float*)d_in[12];
    const float* ffb2    = (const float*)d_in[13];
    const float* ln2g    = (const float*)d_in[14];
    const float* ln2b    = (const float*)d_in[15];
    float* out = (float*)d_out;

    float *rbias, *tmp, *out1;
    __half *heads16, *rk16, *BD, *av16, *out116, *ffh16;
    __half *cat16, *r16, *qkvw16, *rnw16, *ow16, *ffw116, *ffw216;
    cudaGetSymbolAddress((void**)&heads16, g_heads16);
    cudaGetSymbolAddress((void**)&rk16,    g_rk16);
    cudaGetSymbolAddress((void**)&rbias,   g_rbias);
    cudaGetSymbolAddress((void**)&BD,      g_BD);
    cudaGetSymbolAddress((void**)&av16,    g_av16);
    cudaGetSymbolAddress((void**)&tmp,     g_tmp);
    cudaGetSymbolAddress((void**)&out1,    g_out1);
    cudaGetSymbolAddress((void**)&out116,  g_out116);
    cudaGetSymbolAddress((void**)&ffh16,   g_ffh16);
    cudaGetSymbolAddress((void**)&cat16,   g_cat16);
    cudaGetSymbolAddress((void**)&r16,     g_r16);
    cudaGetSymbolAddress((void**)&qkvw16,  g_qkvw16);
    cudaGetSymbolAddress((void**)&rnw16,   g_rnw16);
    cudaGetSymbolAddress((void**)&ow16,    g_ow16);
    cudaGetSymbolAddress((void**)&ffw116,  g_ffw116);
    cudaGetSymbolAddress((void**)&ffw216,  g_ffw216);

    static cudaStream_t s1 = nullptr;
    static cudaEvent_t evFork = nullptr, evQ = nullptr, evJoin = nullptr;
    static int s_init_done = 0;
    if (!s_init_done) {
        cudaFuncSetAttribute(flash_k, cudaFuncAttributeMaxDynamicSharedMemorySize,
                             FLASH_SMEM);
        cudaStreamCreateWithFlags(&s1, cudaStreamNonBlocking);
        cudaEventCreateWithFlags(&evFork, cudaEventDisableTiming);
        cudaEventCreateWithFlags(&evQ, cudaEventDisableTiming);
        cudaEventCreateWithFlags(&evJoin, cudaEventDisableTiming);
        s_init_done = 1;
    }

    const dim3 blk(256);
    const __half* qb16 = heads16 + (size_t)MEMLEN * BSZ * H3;  // query rows

    // ---- fork side stream ----
    cudaEventRecord(evFork, 0);
    cudaStreamWaitEvent(s1, evFork, 0);

    // side stream: r/weight conversions -> rk GEMM -> rbias
    cvt_k<<<(KLEN * DMODEL) / 2048, blk, 0, s1>>>(r, r16);
    cvt_k<<<(DMODEL * DMODEL) / 2048, blk, 0, s1>>>(r_net_w, rnw16);
    cvt_k<<<(DMODEL * DMODEL) / 2048, blk, 0, s1>>>(o_w, ow16);
    cvt_k<<<(DMODEL * DINNER) / 2048, blk, 0, s1>>>(ffw1, ffw116);
    cvt_k<<<(DINNER * DMODEL) / 2048, blk, 0, s1>>>(ffw2, ffw216);
    gemm_h<1><<<dim3(DMODEL / 128, KLEN / 128), blk, 0, s1>>>(
        r16, DMODEL, rnw16, DMODEL, nullptr, nullptr, 0,
        rk16, nullptr, DMODEL, KLEN, DMODEL, DMODEL);
    rbias_k<<<(NHEAD * KLEN) / 256, blk, 0, s1>>>(rrb, rk16, rbias);

    // main stream: input conversions -> Q-GEMM (query rows only, N=1024)
    cvt_k<<<(MEMLEN * BSZ * DMODEL) / 2048, blk>>>(mems, cat16);
    cvt_k<<<(QLEN * BSZ * DMODEL) / 2048, blk>>>(w, cat16 + (size_t)MEMLEN * BSZ * DMODEL);
    cvt_k<<<(DMODEL * H3) / 2048, blk>>>(qkv_w, qkvw16);
    gemm_h<1><<<dim3(DMODEL / 128, (QLEN * BSZ) / 128), blk>>>(
        cat16 + (size_t)MEMLEN * BSZ * DMODEL, DMODEL, qkvw16, H3,
        nullptr, nullptr, 0,
        heads16 + (size_t)MEMLEN * BSZ * H3, nullptr, H3,
        QLEN * BSZ, DMODEL, DMODEL);
    cudaEventRecord(evQ, 0);

    // side stream: bd16 after Q-GEMM + rk/rbias (runs concurrent with KV-GEMM)
    cudaStreamWaitEvent(s1, evQ, 0);
    bd16_gemm<<<dim3(KLEN / 128, QLEN / 128, BSZ * NHEAD), blk, 0, s1>>>(
        qb16, rk16, rbias, BD);
    cudaEventRecord(evJoin, s1);

    // main stream: KV-GEMM (all rows, N=2048 -> cols 1024..3071 of heads16)
    gemm_h<1><<<dim3((2 * DMODEL) / 128, (KLEN * BSZ) / 128), blk>>>(
        cat16, DMODEL, qkvw16 + DMODEL, H3, nullptr, nullptr, 0,
        heads16 + DMODEL, nullptr, H3, KLEN * BSZ, 2 * DMODEL, DMODEL);

    // ---- join: flash needs BD from side stream ----
    cudaStreamWaitEvent(0, evJoin, 0);

    // flash (64-row tiles, 2 CTAs/SM) -> av16
    flash_k<<<dim3(QLEN / 64, BSZ * NHEAD), dim3(256), FLASH_SMEM>>>(
        heads16, BD, rwb, av16);

    // attn_out = av16 @ ow16 + w
    gemm_h<0><<<dim3(DMODEL / 128, (QLEN * BSZ) / 128), blk>>>(
        av16, DMODEL, ow16, DMODEL, nullptr, w, 0,
        tmp, nullptr, DMODEL, QLEN * BSZ, DMODEL, DMODEL);

    // LN1 (dual fp32 + fp16)
    ln_k<<<QLEN * BSZ, blk>>>(tmp, ln1g, ln1b, out1, out116);

    // ffh16 = relu(out116 @ ffw116 + b1) (fp16 out)
    gemm_h<1><<<dim3(DINNER / 128, (QLEN * BSZ) / 128), blk>>>(
        out116, DMODEL, ffw116, DINNER, ffb1, nullptr, 1,
        ffh16, nullptr, DINNER, QLEN * BSZ, DINNER, DMODEL);

    // tmp = ffh16 @ ffw216 + b2 + out1
    gemm_h<0><<<dim3(DMODEL / 128, (QLEN * BSZ) / 128), blk>>>(
        ffh16, DINNER, ffw216, DMODEL, ffb2, out1, 0,
        tmp, nullptr, DMODEL, QLEN * BSZ, DMODEL, DINNER);

    // LN2 -> output
    ln_k<<<QLEN * BSZ, blk>>>(tmp, ln2g, ln2b, out, nullptr);
}